// round 7
// baseline (speedup 1.0000x reference)
#include <cuda_runtime.h>
#include <cuda_bf16.h>
#include <stdint.h>
#include <math.h>

#define BQ 16
#define HD 512
#define LL 2048
#define NL 4
#define NN 32
#define NTOT (BQ * LL)  // 32768 total columns

// ---------------- scratch (static __device__, no allocs) ----------------
__device__ float g_H[(size_t)BQ * HD * LL];          // normalized stream Hn
__device__ float g_V[(size_t)BQ * HD * LL];          // pre-norm V scratch
__device__ __nv_bfloat16 g_Bth[(size_t)NTOT * HD];   // activations (n,k) hi
__device__ __nv_bfloat16 g_Btl[(size_t)NTOT * HD];   // activations (n,k) lo
#define W_ENC_OFF 0
#define W_OUT_OFF (HD * HD)
#define W_DEC_OFF (HD * HD + NL * 2 * HD * HD)
#define W_ELEMS (2 * HD * HD + NL * 2 * HD * HD)
__device__ __nv_bfloat16 g_Wh[W_ELEMS];
__device__ __nv_bfloat16 g_Wl[W_ELEMS];
__device__ float g_wre[NL * HD * NN];
__device__ float g_wim[NL * HD * NN];
__device__ float g_cre[NL * HD * NN];
__device__ float g_cim[NL * HD * NN];

// ---------------- helpers ----------------
__device__ __forceinline__ uint32_t smem_u32(const void* p)
{
    uint32_t a;
    asm("{ .reg .u64 t; cvta.to.shared.u64 t, %1; cvt.u32.u64 %0, t; }"
        : "=r"(a) : "l"(p));
    return a;
}

__device__ __forceinline__ void cp_async16(uint32_t dst, const void* src)
{
    asm volatile("cp.async.cg.shared.global [%0], [%1], 16;" :: "r"(dst), "l"(src));
}
#define CP_COMMIT() asm volatile("cp.async.commit_group;" ::: "memory")
#define CP_WAIT(n)  asm volatile("cp.async.wait_group %0;" :: "n"(n) : "memory")

__device__ __forceinline__ void ldmx4(uint32_t* r, uint32_t addr)
{
    asm volatile("ldmatrix.sync.aligned.m8n8.x4.shared.b16 {%0,%1,%2,%3}, [%4];"
                 : "=r"(r[0]), "=r"(r[1]), "=r"(r[2]), "=r"(r[3]) : "r"(addr));
}

__device__ __forceinline__ void mma16816(float* c, const uint32_t* a,
                                         const uint32_t* b)
{
    asm volatile(
        "mma.sync.aligned.m16n8k16.row.col.f32.bf16.bf16.f32 "
        "{%0,%1,%2,%3}, {%4,%5,%6,%7}, {%8,%9}, {%0,%1,%2,%3};"
        : "+f"(c[0]), "+f"(c[1]), "+f"(c[2]), "+f"(c[3])
        : "r"(a[0]), "r"(a[1]), "r"(a[2]), "r"(a[3]), "r"(b[0]), "r"(b[1]));
}

// ---- packed f32x2 (FFMA2) ----
__device__ __forceinline__ uint64_t pack2(float lo, float hi)
{
    uint64_t r;
    asm("mov.b64 %0, {%1, %2};" : "=l"(r) : "f"(lo), "f"(hi));
    return r;
}
__device__ __forceinline__ void unpack2(uint64_t v, float& lo, float& hi)
{
    asm("mov.b64 {%0, %1}, %2;" : "=f"(lo), "=f"(hi) : "l"(v));
}
__device__ __forceinline__ uint64_t fma2(uint64_t a, uint64_t b, uint64_t c)
{
    uint64_t d;
    asm("fma.rn.f32x2 %0, %1, %2, %3;" : "=l"(d) : "l"(a), "l"(b), "l"(c));
    return d;
}
__device__ __forceinline__ uint64_t mul2(uint64_t a, uint64_t b)
{
    uint64_t d;
    asm("mul.rn.f32x2 %0, %1, %2;" : "=l"(d) : "l"(a), "l"(b));
    return d;
}

// ---------------- parameter precompute ----------------
__global__ __launch_bounds__(256)
void precompute_kernel(const float* __restrict__ log_dt,
                       const float* __restrict__ log_A_real,
                       const float* __restrict__ A_imag,
                       const float* __restrict__ C_re,
                       const float* __restrict__ C_im)
{
    int idx = blockIdx.x * 256 + threadIdx.x;
    if (idx >= NL * HD * NN) return;
    int h = (idx >> 5) & (HD - 1);
    int l = idx >> 14;
    float dt = expf(log_dt[l * HD + h]);
    float a = -expf(log_A_real[idx]);
    float b = A_imag[idx];
    float xr = dt * a, xi = dt * b;
    float er = expf(xr);
    float c = cosf(xi), s = sinf(xi);
    g_wre[idx] = er * c;
    g_wim[idx] = er * s;
    float sh = sinf(0.5f * xi);
    float Ere = expm1f(xr) * c - 2.f * sh * sh;
    float Eim = er * s;
    float den = a * a + b * b;
    float Fre = (Ere * a + Eim * b) / den;
    float Fim = (Eim * a - Ere * b) / den;
    float cr = C_re[idx], ci = C_im[idx];
    g_cre[idx] = cr * Fre - ci * Fim;
    g_cim[idx] = cr * Fim + ci * Fre;
}

// ---------------- weight split fp32 -> bf16 hi/lo ----------------
__global__ __launch_bounds__(256)
void split_w_kernel(const float* __restrict__ src, __nv_bfloat16* __restrict__ hi,
                    __nv_bfloat16* __restrict__ lo, int n)
{
    int i = blockIdx.x * 256 + threadIdx.x;
    if (i >= n) return;
    float v = src[i];
    __nv_bfloat16 h = __float2bfloat16(v);
    hi[i] = h;
    lo[i] = __float2bfloat16(v - __bfloat162float(h));
}

// ---------------- transpose + split (+opt quant) ----------
template <bool QUANT>
__global__ __launch_bounds__(256)
void transpose_split_kernel(const float* __restrict__ src,
                            __nv_bfloat16* __restrict__ dhi,
                            __nv_bfloat16* __restrict__ dlo)
{
    __shared__ float tile[32][33];
    const int b = blockIdx.z;
    const int c0 = blockIdx.y * 32;
    const int t0 = blockIdx.x * 32;
    const int tx = threadIdx.x & 31, ty = threadIdx.x >> 5;
#pragma unroll
    for (int i = 0; i < 32; i += 8) {
        float v = src[((size_t)b * HD + c0 + ty + i) * LL + t0 + tx];
        if (QUANT) v = rintf(v * 64.f) * 0.015625f;
        tile[ty + i][tx] = v;
    }
    __syncthreads();
#pragma unroll
    for (int i = 0; i < 32; i += 8) {
        int t = t0 + ty + i;
        int c = c0 + tx;
        float v = tile[tx][ty + i];
        __nv_bfloat16 h = __float2bfloat16(v);
        size_t o = ((size_t)b * LL + t) * HD + c;
        dhi[o] = h;
        dlo[o] = __float2bfloat16(v - __bfloat162float(h));
    }
}

// ---------------- HMMA GEMM (3x bf16 split, fp32 acc) ----------------
#define KC 64
#define TILE_BYTES 16384            // 128 * 64 * 2B
#define STAGE_BYTES (4 * TILE_BYTES)
#define GEMM_SMEM (2 * STAGE_BYTES) // 131072

template <int EPI>
__global__ __launch_bounds__(256, 1)
void gemm_mma(const __nv_bfloat16* __restrict__ Wh, const __nv_bfloat16* __restrict__ Wl,
              const __nv_bfloat16* __restrict__ Xh, const __nv_bfloat16* __restrict__ Xl,
              float* __restrict__ out, const float* __restrict__ bias, int M,
              const float* __restrict__ Hprev)
{
    extern __shared__ char smem[];
    const uint32_t sb = smem_u32(smem);
    const int tid = threadIdx.x;
    const int wid = tid >> 5, lane = tid & 31;
    const int wm = wid >> 1, wn = wid & 1;
    const int n0 = blockIdx.x * 128;
    const int m0 = blockIdx.y * ((EPI == 2) ? 64 : 128);
    const int lr = lane & 7, lg = lane >> 3;

    float acc[2][8][4];
#pragma unroll
    for (int i = 0; i < 2; ++i)
#pragma unroll
        for (int j = 0; j < 8; ++j)
#pragma unroll
            for (int q = 0; q < 4; ++q) acc[i][j][q] = 0.f;

    auto load_chunk = [&](int kc, int st) {
        const uint32_t base = sb + st * STAGE_BYTES;
        const size_t gk = (size_t)kc * KC;
#pragma unroll
        for (int i = 0; i < 4; ++i) {
            int lin = i * 256 + tid;
            int row = lin >> 3, seg = lin & 7;
            uint32_t soff = row * 128 + (((seg ^ (row & 7))) << 4);
            int wrow;
            if (EPI == 2)
                wrow = ((row >> 4) & 1) * HD + m0 + (row >> 5) * 16 + (row & 15);
            else
                wrow = m0 + row;
            const size_t wgo = (size_t)wrow * HD + gk + seg * 8;
            const size_t xgo = (size_t)(n0 + row) * HD + gk + seg * 8;
            cp_async16(base + soff, Wh + wgo);
            cp_async16(base + TILE_BYTES + soff, Wl + wgo);
            cp_async16(base + 2 * TILE_BYTES + soff, Xh + xgo);
            cp_async16(base + 3 * TILE_BYTES + soff, Xl + xgo);
        }
        CP_COMMIT();
    };

    load_chunk(0, 0);

    const int NCH = HD / KC;  // 8
    for (int c = 0; c < NCH; ++c) {
        if (c + 1 < NCH) {
            load_chunk(c + 1, (c + 1) & 1);
            CP_WAIT(1);
        } else {
            CP_WAIT(0);
        }
        __syncthreads();

        const uint32_t stg = sb + (c & 1) * STAGE_BYTES;
#pragma unroll
        for (int ks = 0; ks < 4; ++ks) {
            uint32_t a[2][2][4];
            uint32_t b[2][4][4];
#pragma unroll
            for (int mi = 0; mi < 2; ++mi) {
                int arow = wm * 32 + mi * 16 + lr + (lg & 1) * 8;
                int aseg = ks * 2 + (lg >> 1);
                uint32_t off = arow * 128 + ((aseg ^ (arow & 7)) << 4);
                ldmx4(a[0][mi], stg + off);
                ldmx4(a[1][mi], stg + TILE_BYTES + off);
            }
#pragma unroll
            for (int g = 0; g < 4; ++g) {
                int brow = wn * 64 + g * 16 + lr + (lg >> 1) * 8;
                int bseg = ks * 2 + (lg & 1);
                uint32_t off = brow * 128 + ((bseg ^ (brow & 7)) << 4);
                ldmx4(b[0][g], stg + 2 * TILE_BYTES + off);
                ldmx4(b[1][g], stg + 3 * TILE_BYTES + off);
            }
#pragma unroll
            for (int mi = 0; mi < 2; ++mi)
#pragma unroll
                for (int j = 0; j < 8; ++j) {
                    const int g = j >> 1, p = (j & 1) * 2;
                    uint32_t bh[2] = {b[0][g][p], b[0][g][p + 1]};
                    uint32_t bl[2] = {b[1][g][p], b[1][g][p + 1]};
                    mma16816(acc[mi][j], a[0][mi], bh);
                    mma16816(acc[mi][j], a[0][mi], bl);
                    mma16816(acc[mi][j], a[1][mi], bh);
                }
        }
        __syncthreads();
    }

    // ---------------- epilogue ----------------
    if (EPI == 2) {
        const int m = m0 + wm * 16 + (lane >> 2);
        const float b10 = bias[m],      b18 = bias[m + 8];
        const float b20 = bias[HD + m], b28 = bias[HD + m + 8];
#pragma unroll
        for (int j = 0; j < 8; ++j) {
            const int n = n0 + wn * 64 + j * 8 + (lane & 3) * 2;
            const int bb = n >> 11;
            const int t = n & (LL - 1);
            float z10 = acc[0][j][0] + b10, z11 = acc[0][j][1] + b10;
            float z12 = acc[0][j][2] + b18, z13 = acc[0][j][3] + b18;
            float z20 = acc[1][j][0] + b20, z21 = acc[1][j][1] + b20;
            float z22 = acc[1][j][2] + b28, z23 = acc[1][j][3] + b28;
            const float2 p0 = *reinterpret_cast<const float2*>(
                Hprev + ((size_t)bb * HD + m) * LL + t);
            const float2 p1 = *reinterpret_cast<const float2*>(
                Hprev + ((size_t)bb * HD + m + 8) * LL + t);
            float2 v0, v1;
            v0.x = z10 / (1.f + expf(-z20)) + p0.x;
            v0.y = z11 / (1.f + expf(-z21)) + p0.y;
            v1.x = z12 / (1.f + expf(-z22)) + p1.x;
            v1.y = z13 / (1.f + expf(-z23)) + p1.y;
            *reinterpret_cast<float2*>(out + ((size_t)bb * HD + m) * LL + t) = v0;
            *reinterpret_cast<float2*>(out + ((size_t)bb * HD + m + 8) * LL + t) = v1;
        }
    } else {
#pragma unroll
        for (int mi = 0; mi < 2; ++mi) {
            const int mrow0 = m0 + wm * 32 + mi * 16 + (lane >> 2);
#pragma unroll
            for (int j = 0; j < 8; ++j) {
                const int n = n0 + wn * 64 + j * 8 + (lane & 3) * 2;
                const int bb = n >> 11;
                const int t = n & (LL - 1);
                float2 v0, v1;
                v0.x = fmaxf(acc[mi][j][0], 0.f);
                v0.y = fmaxf(acc[mi][j][1], 0.f);
                v1.x = fmaxf(acc[mi][j][2], 0.f);
                v1.y = fmaxf(acc[mi][j][3], 0.f);
                *reinterpret_cast<float2*>(out + ((size_t)bb * M + mrow0) * LL + t) = v0;
                *reinterpret_cast<float2*>(out + ((size_t)bb * M + mrow0 + 8) * LL + t) = v1;
            }
        }
    }
}

// ---------------- single-pass LayerNorm ----------------
// WRT==0: Hn = LN(V) fp32 (for next layer's scan)
// WRT==1: writes LN(V) directly as transposed bf16 hi/lo (decoder operands)
template <int WRT>
__global__ __launch_bounds__(256)
void ln_kernel(const float* __restrict__ V, float* __restrict__ Hn,
               __nv_bfloat16* __restrict__ dhi, __nv_bfloat16* __restrict__ dlo,
               const float* __restrict__ gamma, const float* __restrict__ beta)
{
    __shared__ float ssum[8][32];
    __shared__ float ssq[8][32];
    __shared__ __nv_bfloat16 hs[32][72];
    __shared__ __nv_bfloat16 ls[32][72];
    const int b = blockIdx.y;
    const int tx = threadIdx.x & 31;
    const int ty = threadIdx.x >> 5;          // 0..7
    const size_t t = (size_t)blockIdx.x * 32 + tx;
    const float* Vb = V + (size_t)b * HD * LL + t;
    float* Hb = Hn + (size_t)b * HD * LL + t;

    float vals[64];
    float s = 0.f, s2 = 0.f;
#pragma unroll
    for (int k = 0; k < 64; ++k) {
        const int c = k * 8 + ty;
        float v = Vb[(size_t)c * LL];
        vals[k] = v;
        s += v;
        s2 = fmaf(v, v, s2);
    }
    ssum[ty][tx] = s;
    ssq[ty][tx] = s2;
    __syncthreads();
    float st = 0.f, st2 = 0.f;
#pragma unroll
    for (int i = 0; i < 8; ++i) {
        st += ssum[i][tx];
        st2 += ssq[i][tx];
    }
    const float mu = st * (1.f / HD);
    const float var = st2 * (1.f / HD) - mu * mu;
    const float rstd = rsqrtf(var + 1e-5f);

    if (WRT == 0) {
#pragma unroll
        for (int k = 0; k < 64; ++k) {
            const int c = k * 8 + ty;
            Hb[(size_t)c * LL] = (vals[k] - mu) * rstd * gamma[c] + beta[c];
        }
    } else {
        const int tt = (int)(threadIdx.x >> 3), seg = (int)(threadIdx.x & 7);
        const size_t trow = ((size_t)b * LL + (size_t)blockIdx.x * 32 + tt) * HD;
#pragma unroll
        for (int kc = 0; kc < 8; ++kc) {
#pragma unroll
            for (int i = 0; i < 8; ++i) {
                const int k = kc * 8 + i;
                const int c = k * 8 + ty;
                float v = (vals[k] - mu) * rstd * gamma[c] + beta[c];
                __nv_bfloat16 h = __float2bfloat16(v);
                hs[tx][i * 8 + ty] = h;
                ls[tx][i * 8 + ty] = __float2bfloat16(v - __bfloat162float(h));
            }
            __syncthreads();
            *reinterpret_cast<uint4*>(dhi + trow + kc * 64 + seg * 8) =
                *reinterpret_cast<const uint4*>(&hs[tt][seg * 8]);
            *reinterpret_cast<uint4*>(dlo + trow + kc * 64 + seg * 8) =
                *reinterpret_cast<const uint4*>(&ls[tt][seg * 8]);
            __syncthreads();
        }
    }
}

// ---------------- SSM scan, packed f32x2 -> bf16 hi/lo T ------
__global__ __launch_bounds__(256)
void ssm_scan_fused(const float* __restrict__ hbuf,
                    __nv_bfloat16* __restrict__ dhi,
                    __nv_bfloat16* __restrict__ dlo,
                    const float* __restrict__ wre, const float* __restrict__ wim,
                    const float* __restrict__ ccre, const float* __restrict__ ccim,
                    const float* __restrict__ Dv)
{
    __shared__ float tile[32][33];
    const int tid = threadIdx.x;
    const int q = tid & 7;
    const int g = tid >> 3;                 // 0..31
    const int grp0 = blockIdx.x * 32;
    const int grp = grp0 + g;
    const int b = grp >> 9;
    const int hh = grp & (HD - 1);
    const int h0 = grp0 & (HD - 1);
    const float* hrow = hbuf + (size_t)grp * LL;

    const int pbase = hh * NN + q * 4;
    float4 w_r = *reinterpret_cast<const float4*>(&wre[pbase]);
    float4 w_i = *reinterpret_cast<const float4*>(&wim[pbase]);
    float4 c_r = *reinterpret_cast<const float4*>(&ccre[pbase]);
    float4 c_i = *reinterpret_cast<const float4*>(&ccim[pbase]);

    const uint64_t wr01 = pack2(w_r.x, w_r.y), wr23 = pack2(w_r.z, w_r.w);
    const uint64_t wi01 = pack2(w_i.x, w_i.y), wi23 = pack2(w_i.z, w_i.w);
    const uint64_t wiN01 = pack2(-w_i.x, -w_i.y), wiN23 = pack2(-w_i.z, -w_i.w);
    const uint64_t cr01 = pack2(c_r.x, c_r.y), cr23 = pack2(c_r.z, c_r.w);
    const uint64_t ciN01 = pack2(-c_i.x, -c_i.y), ciN23 = pack2(-c_i.z, -c_i.w);
    const float Dh = Dv[hh];

    uint64_t sr01 = pack2(0.f, 0.f), sr23 = sr01, si01 = sr01, si23 = sr01;

    const int tt = tid >> 3, seg = tid & 7;

    for (int t0 = 0; t0 < LL; t0 += 32) {
#pragma unroll
        for (int sub = 0; sub < 4; ++sub) {
            const int tb = t0 + sub * 8;
            const float4 ua = *reinterpret_cast<const float4*>(hrow + tb);
            const float4 ub = *reinterpret_cast<const float4*>(hrow + tb + 4);
            const float uu[8] = {ua.x, ua.y, ua.z, ua.w, ub.x, ub.y, ub.z, ub.w};
            float umine = 0.f, ykeep = 0.f;
#pragma unroll
            for (int j = 0; j < 8; ++j) {
                const float u = uu[j];
                const uint64_t up = pack2(u, u);
                uint64_t nr01 = fma2(wr01, sr01, up);
                nr01 = fma2(wiN01, si01, nr01);
                uint64_t ni01 = mul2(wi01, sr01);
                ni01 = fma2(wr01, si01, ni01);
                uint64_t nr23 = fma2(wr23, sr23, up);
                nr23 = fma2(wiN23, si23, nr23);
                uint64_t ni23 = mul2(wi23, sr23);
                ni23 = fma2(wr23, si23, ni23);
                sr01 = nr01; si01 = ni01; sr23 = nr23; si23 = ni23;
                uint64_t ap = mul2(cr01, sr01);
                ap = fma2(ciN01, si01, ap);
                ap = fma2(cr23, sr23, ap);
                ap = fma2(ciN23, si23, ap);
                float alo, ahi;
                unpack2(ap, alo, ahi);
                float acc = alo + ahi;
                acc += __shfl_xor_sync(0xffffffffu, acc, 1);
                acc += __shfl_xor_sync(0xffffffffu, acc, 2);
                acc += __shfl_xor_sync(0xffffffffu, acc, 4);
                if (j == q) { umine = u; ykeep = acc; }
            }
            float yv = fmaf(Dh, umine, 2.f * ykeep);
            float gv = 0.5f * yv * (1.f + erff(yv * 0.70710678118654752f));
            tile[sub * 8 + q][g] = gv;
        }
        __syncthreads();
        {
            const int t = t0 + tt;
            float v0 = tile[tt][seg * 4 + 0];
            float v1 = tile[tt][seg * 4 + 1];
            float v2 = tile[tt][seg * 4 + 2];
            float v3 = tile[tt][seg * 4 + 3];
            __nv_bfloat16 hi4[4], lo4[4];
            hi4[0] = __float2bfloat16(v0);
            hi4[1] = __float2bfloat16(v1);
            hi4[2] = __float2bfloat16(v2);
            hi4[3] = __float2bfloat16(v3);
            lo4[0] = __float2bfloat16(v0 - __bfloat162float(hi4[0]));
            lo4[1] = __float2bfloat16(v1 - __bfloat162float(hi4[1]));
            lo4[2] = __float2bfloat16(v2 - __bfloat162float(hi4[2]));
            lo4[3] = __float2bfloat16(v3 - __bfloat162float(hi4[3]));
            const size_t o = ((size_t)b * LL + t) * HD + h0 + seg * 4;
            *reinterpret_cast<uint2*>(dhi + o) = *reinterpret_cast<uint2*>(hi4);
            *reinterpret_cast<uint2*>(dlo + o) = *reinterpret_cast<uint2*>(lo4);
        }
        __syncthreads();
    }
}

// ---------------- launch ----------------
extern "C" void kernel_launch(void* const* d_in, const int* in_sizes, int n_in,
                              void* d_out, int out_size)
{
    const float* x = (const float*)d_in[0];
    const float* W_enc = (const float*)d_in[1];
    const float* W_dec = (const float*)d_in[2];
    const float* log_dt = (const float*)d_in[3];
    const float* log_A_real = (const float*)d_in[4];
    const float* A_imag = (const float*)d_in[5];
    const float* C_re = (const float*)d_in[6];
    const float* C_im = (const float*)d_in[7];
    const float* Dv = (const float*)d_in[8];
    const float* W_out = (const float*)d_in[9];
    const float* b_out = (const float*)d_in[10];
    const float* ln_g = (const float*)d_in[11];
    const float* ln_b = (const float*)d_in[12];
    float* out = (float*)d_out;

    float *pH, *pV, *pwre, *pwim, *pcre, *pcim;
    __nv_bfloat16 *pBth, *pBtl, *pWh, *pWl;
    cudaGetSymbolAddress((void**)&pH, g_H);
    cudaGetSymbolAddress((void**)&pV, g_V);
    cudaGetSymbolAddress((void**)&pwre, g_wre);
    cudaGetSymbolAddress((void**)&pwim, g_wim);
    cudaGetSymbolAddress((void**)&pcre, g_cre);
    cudaGetSymbolAddress((void**)&pcim, g_cim);
    cudaGetSymbolAddress((void**)&pBth, g_Bth);
    cudaGetSymbolAddress((void**)&pBtl, g_Btl);
    cudaGetSymbolAddress((void**)&pWh, g_Wh);
    cudaGetSymbolAddress((void**)&pWl, g_Wl);

    cudaFuncSetAttribute(gemm_mma<0>, cudaFuncAttributeMaxDynamicSharedMemorySize, GEMM_SMEM);
    cudaFuncSetAttribute(gemm_mma<2>, cudaFuncAttributeMaxDynamicSharedMemorySize, GEMM_SMEM);

    precompute_kernel<<<(NL * HD * NN + 255) / 256, 256>>>(log_dt, log_A_real,
                                                           A_imag, C_re, C_im);
    split_w_kernel<<<(HD * HD + 255) / 256, 256>>>(W_enc, pWh + W_ENC_OFF,
                                                   pWl + W_ENC_OFF, HD * HD);
    split_w_kernel<<<(NL * 2 * HD * HD + 255) / 256, 256>>>(
        W_out, pWh + W_OUT_OFF, pWl + W_OUT_OFF, NL * 2 * HD * HD);
    split_w_kernel<<<(HD * HD + 255) / 256, 256>>>(W_dec, pWh + W_DEC_OFF,
                                                   pWl + W_DEC_OFF, HD * HD);

    const dim3 tgrid(LL / 32, HD / 32, BQ);

    // encoder: H = relu(W_enc @ quant(x))
    transpose_split_kernel<true><<<tgrid, 256>>>(x, pBth, pBtl);
    gemm_mma<0><<<dim3(NTOT / 128, HD / 128), 256, GEMM_SMEM>>>(
        pWh + W_ENC_OFF, pWl + W_ENC_OFF, pBth, pBtl, pH, nullptr, HD, nullptr);

    for (int l = 0; l < NL; ++l) {
        const int po = l * HD * NN;
        // scan(H) + gelu -> transposed bf16 hi/lo
        ssm_scan_fused<<<(BQ * HD) / 32, 256>>>(
            pH, pBth, pBtl, pwre + po, pwim + po, pcre + po, pcim + po,
            Dv + l * HD);
        // fused GLU + residual: V = glu(z) + H
        gemm_mma<2><<<dim3(NTOT / 128, HD / 64), 256, GEMM_SMEM>>>(
            pWh + W_OUT_OFF + (size_t)l * 2 * HD * HD,
            pWl + W_OUT_OFF + (size_t)l * 2 * HD * HD,
            pBth, pBtl, pV, b_out + l * 2 * HD, HD, pH);
        // H = LN(V); last layer writes decoder operands directly
        if (l < NL - 1)
            ln_kernel<0><<<dim3(LL / 32, BQ), 256>>>(pV, pH, nullptr, nullptr,
                                                     ln_g + l * HD, ln_b + l * HD);
        else
            ln_kernel<1><<<dim3(LL / 32, BQ), 256>>>(pV, nullptr, pBth, pBtl,
                                                     ln_g + l * HD, ln_b + l * HD);
    }

    // decoder: out = relu(W_dec @ LN(V3))
    gemm_mma<0><<<dim3(NTOT / 128, HD / 128), 256, GEMM_SMEM>>>(
        pWh + W_DEC_OFF, pWl + W_DEC_OFF, pBth, pBtl, out, nullptr, HD, nullptr);
}

// round 8
// speedup vs baseline: 1.0251x; 1.0251x over previous
#include <cuda_runtime.h>
#include <cuda_bf16.h>
#include <stdint.h>
#include <math.h>

#define BQ 16
#define HD 512
#define LL 2048
#define NL 4
#define NN 32
#define NTOT (BQ * LL)  // 32768 total columns

// ---------------- scratch (static __device__, no allocs) ----------------
__device__ float g_H[(size_t)BQ * HD * LL];          // normalized stream Hn
__device__ float g_V[(size_t)BQ * HD * LL];          // pre-norm V scratch
__device__ __nv_bfloat16 g_Bth[(size_t)NTOT * HD];   // activations (n,k) hi
__device__ __nv_bfloat16 g_Btl[(size_t)NTOT * HD];   // activations (n,k) lo
#define W_ENC_OFF 0
#define W_OUT_OFF (HD * HD)
#define W_DEC_OFF (HD * HD + NL * 2 * HD * HD)
#define W_ELEMS (2 * HD * HD + NL * 2 * HD * HD)
__device__ __nv_bfloat16 g_Wh[W_ELEMS];
__device__ __nv_bfloat16 g_Wl[W_ELEMS];
__device__ float g_wre[NL * HD * NN];
__device__ float g_wim[NL * HD * NN];
__device__ float g_cre[NL * HD * NN];
__device__ float g_cim[NL * HD * NN];

// ---------------- helpers ----------------
__device__ __forceinline__ uint32_t smem_u32(const void* p)
{
    uint32_t a;
    asm("{ .reg .u64 t; cvta.to.shared.u64 t, %1; cvt.u32.u64 %0, t; }"
        : "=r"(a) : "l"(p));
    return a;
}

__device__ __forceinline__ void cp_async16(uint32_t dst, const void* src)
{
    asm volatile("cp.async.cg.shared.global [%0], [%1], 16;" :: "r"(dst), "l"(src));
}
#define CP_COMMIT() asm volatile("cp.async.commit_group;" ::: "memory")
#define CP_WAIT(n)  asm volatile("cp.async.wait_group %0;" :: "n"(n) : "memory")

__device__ __forceinline__ void ldmx4(uint32_t* r, uint32_t addr)
{
    asm volatile("ldmatrix.sync.aligned.m8n8.x4.shared.b16 {%0,%1,%2,%3}, [%4];"
                 : "=r"(r[0]), "=r"(r[1]), "=r"(r[2]), "=r"(r[3]) : "r"(addr));
}

__device__ __forceinline__ void mma16816(float* c, const uint32_t* a,
                                         const uint32_t* b)
{
    asm volatile(
        "mma.sync.aligned.m16n8k16.row.col.f32.bf16.bf16.f32 "
        "{%0,%1,%2,%3}, {%4,%5,%6,%7}, {%8,%9}, {%0,%1,%2,%3};"
        : "+f"(c[0]), "+f"(c[1]), "+f"(c[2]), "+f"(c[3])
        : "r"(a[0]), "r"(a[1]), "r"(a[2]), "r"(a[3]), "r"(b[0]), "r"(b[1]));
}

// ---------------- parameter precompute ----------------
__global__ __launch_bounds__(256)
void precompute_kernel(const float* __restrict__ log_dt,
                       const float* __restrict__ log_A_real,
                       const float* __restrict__ A_imag,
                       const float* __restrict__ C_re,
                       const float* __restrict__ C_im)
{
    int idx = blockIdx.x * 256 + threadIdx.x;
    if (idx >= NL * HD * NN) return;
    int h = (idx >> 5) & (HD - 1);
    int l = idx >> 14;
    float dt = expf(log_dt[l * HD + h]);
    float a = -expf(log_A_real[idx]);
    float b = A_imag[idx];
    float xr = dt * a, xi = dt * b;
    float er = expf(xr);
    float c = cosf(xi), s = sinf(xi);
    g_wre[idx] = er * c;
    g_wim[idx] = er * s;
    float sh = sinf(0.5f * xi);
    float Ere = expm1f(xr) * c - 2.f * sh * sh;
    float Eim = er * s;
    float den = a * a + b * b;
    float Fre = (Ere * a + Eim * b) / den;
    float Fim = (Eim * a - Ere * b) / den;
    float cr = C_re[idx], ci = C_im[idx];
    g_cre[idx] = cr * Fre - ci * Fim;
    g_cim[idx] = cr * Fim + ci * Fre;
}

// ---------------- weight split fp32 -> bf16 hi/lo (all weights, one launch) ----
__global__ __launch_bounds__(256)
void split_w_all(const float* __restrict__ W_enc, const float* __restrict__ W_out,
                 const float* __restrict__ W_dec,
                 __nv_bfloat16* __restrict__ hi, __nv_bfloat16* __restrict__ lo)
{
    int i = blockIdx.x * 256 + threadIdx.x;
    if (i >= W_ELEMS) return;
    float v;
    if (i < W_OUT_OFF) v = W_enc[i];
    else if (i < W_DEC_OFF) v = W_out[i - W_OUT_OFF];
    else v = W_dec[i - W_DEC_OFF];
    __nv_bfloat16 h = __float2bfloat16(v);
    hi[i] = h;
    lo[i] = __float2bfloat16(v - __bfloat162float(h));
}

// ---------------- transpose + split (+opt quant) ----------
template <bool QUANT>
__global__ __launch_bounds__(256)
void transpose_split_kernel(const float* __restrict__ src,
                            __nv_bfloat16* __restrict__ dhi,
                            __nv_bfloat16* __restrict__ dlo)
{
    __shared__ float tile[32][33];
    const int b = blockIdx.z;
    const int c0 = blockIdx.y * 32;
    const int t0 = blockIdx.x * 32;
    const int tx = threadIdx.x & 31, ty = threadIdx.x >> 5;
#pragma unroll
    for (int i = 0; i < 32; i += 8) {
        float v = src[((size_t)b * HD + c0 + ty + i) * LL + t0 + tx];
        if (QUANT) v = rintf(v * 64.f) * 0.015625f;
        tile[ty + i][tx] = v;
    }
    __syncthreads();
#pragma unroll
    for (int i = 0; i < 32; i += 8) {
        int t = t0 + ty + i;
        int c = c0 + tx;
        float v = tile[tx][ty + i];
        __nv_bfloat16 h = __float2bfloat16(v);
        size_t o = ((size_t)b * LL + t) * HD + c;
        dhi[o] = h;
        dlo[o] = __float2bfloat16(v - __bfloat162float(h));
    }
}

// ---------------- HMMA GEMM (3x bf16 split, fp32 acc) ----------------
#define KC 64
#define TILE_BYTES 16384            // 128 * 64 * 2B
#define STAGE_BYTES (4 * TILE_BYTES)
#define GEMM_SMEM (2 * STAGE_BYTES) // 131072

template <int EPI>
__global__ __launch_bounds__(256, 1)
void gemm_mma(const __nv_bfloat16* __restrict__ Wh, const __nv_bfloat16* __restrict__ Wl,
              const __nv_bfloat16* __restrict__ Xh, const __nv_bfloat16* __restrict__ Xl,
              float* __restrict__ out, const float* __restrict__ bias, int M,
              const float* __restrict__ Hprev)
{
    extern __shared__ char smem[];
    const uint32_t sb = smem_u32(smem);
    const int tid = threadIdx.x;
    const int wid = tid >> 5, lane = tid & 31;
    const int wm = wid >> 1, wn = wid & 1;
    const int n0 = blockIdx.x * 128;
    const int m0 = blockIdx.y * ((EPI == 2) ? 64 : 128);
    const int lr = lane & 7, lg = lane >> 3;

    float acc[2][8][4];
#pragma unroll
    for (int i = 0; i < 2; ++i)
#pragma unroll
        for (int j = 0; j < 8; ++j)
#pragma unroll
            for (int q = 0; q < 4; ++q) acc[i][j][q] = 0.f;

    auto load_chunk = [&](int kc, int st) {
        const uint32_t base = sb + st * STAGE_BYTES;
        const size_t gk = (size_t)kc * KC;
#pragma unroll
        for (int i = 0; i < 4; ++i) {
            int lin = i * 256 + tid;
            int row = lin >> 3, seg = lin & 7;
            uint32_t soff = row * 128 + (((seg ^ (row & 7))) << 4);
            int wrow;
            if (EPI == 2)
                wrow = ((row >> 4) & 1) * HD + m0 + (row >> 5) * 16 + (row & 15);
            else
                wrow = m0 + row;
            const size_t wgo = (size_t)wrow * HD + gk + seg * 8;
            const size_t xgo = (size_t)(n0 + row) * HD + gk + seg * 8;
            cp_async16(base + soff, Wh + wgo);
            cp_async16(base + TILE_BYTES + soff, Wl + wgo);
            cp_async16(base + 2 * TILE_BYTES + soff, Xh + xgo);
            cp_async16(base + 3 * TILE_BYTES + soff, Xl + xgo);
        }
        CP_COMMIT();
    };

    load_chunk(0, 0);

    const int NCH = HD / KC;  // 8
    for (int c = 0; c < NCH; ++c) {
        if (c + 1 < NCH) {
            load_chunk(c + 1, (c + 1) & 1);
            CP_WAIT(1);
        } else {
            CP_WAIT(0);
        }
        __syncthreads();

        const uint32_t stg = sb + (c & 1) * STAGE_BYTES;
#pragma unroll
        for (int ks = 0; ks < 4; ++ks) {
            uint32_t a[2][2][4];
            uint32_t b[2][4][4];
#pragma unroll
            for (int mi = 0; mi < 2; ++mi) {
                int arow = wm * 32 + mi * 16 + lr + (lg & 1) * 8;
                int aseg = ks * 2 + (lg >> 1);
                uint32_t off = arow * 128 + ((aseg ^ (arow & 7)) << 4);
                ldmx4(a[0][mi], stg + off);
                ldmx4(a[1][mi], stg + TILE_BYTES + off);
            }
#pragma unroll
            for (int g = 0; g < 4; ++g) {
                int brow = wn * 64 + g * 16 + lr + (lg >> 1) * 8;
                int bseg = ks * 2 + (lg & 1);
                uint32_t off = brow * 128 + ((bseg ^ (brow & 7)) << 4);
                ldmx4(b[0][g], stg + 2 * TILE_BYTES + off);
                ldmx4(b[1][g], stg + 3 * TILE_BYTES + off);
            }
#pragma unroll
            for (int mi = 0; mi < 2; ++mi)
#pragma unroll
                for (int j = 0; j < 8; ++j) {
                    const int g = j >> 1, p = (j & 1) * 2;
                    uint32_t bh[2] = {b[0][g][p], b[0][g][p + 1]};
                    uint32_t bl[2] = {b[1][g][p], b[1][g][p + 1]};
                    mma16816(acc[mi][j], a[0][mi], bh);
                    mma16816(acc[mi][j], a[0][mi], bl);
                    mma16816(acc[mi][j], a[1][mi], bh);
                }
        }
        __syncthreads();
    }

    // ---------------- epilogue ----------------
    if (EPI == 2) {
        const int m = m0 + wm * 16 + (lane >> 2);
        const float b10 = bias[m],      b18 = bias[m + 8];
        const float b20 = bias[HD + m], b28 = bias[HD + m + 8];
#pragma unroll
        for (int j = 0; j < 8; ++j) {
            const int n = n0 + wn * 64 + j * 8 + (lane & 3) * 2;
            const int bb = n >> 11;
            const int t = n & (LL - 1);
            float z10 = acc[0][j][0] + b10, z11 = acc[0][j][1] + b10;
            float z12 = acc[0][j][2] + b18, z13 = acc[0][j][3] + b18;
            float z20 = acc[1][j][0] + b20, z21 = acc[1][j][1] + b20;
            float z22 = acc[1][j][2] + b28, z23 = acc[1][j][3] + b28;
            const float2 p0 = *reinterpret_cast<const float2*>(
                Hprev + ((size_t)bb * HD + m) * LL + t);
            const float2 p1 = *reinterpret_cast<const float2*>(
                Hprev + ((size_t)bb * HD + m + 8) * LL + t);
            float2 v0, v1;
            v0.x = z10 / (1.f + expf(-z20)) + p0.x;
            v0.y = z11 / (1.f + expf(-z21)) + p0.y;
            v1.x = z12 / (1.f + expf(-z22)) + p1.x;
            v1.y = z13 / (1.f + expf(-z23)) + p1.y;
            *reinterpret_cast<float2*>(out + ((size_t)bb * HD + m) * LL + t) = v0;
            *reinterpret_cast<float2*>(out + ((size_t)bb * HD + m + 8) * LL + t) = v1;
        }
    } else {
#pragma unroll
        for (int mi = 0; mi < 2; ++mi) {
            const int mrow0 = m0 + wm * 32 + mi * 16 + (lane >> 2);
#pragma unroll
            for (int j = 0; j < 8; ++j) {
                const int n = n0 + wn * 64 + j * 8 + (lane & 3) * 2;
                const int bb = n >> 11;
                const int t = n & (LL - 1);
                float2 v0, v1;
                v0.x = fmaxf(acc[mi][j][0], 0.f);
                v0.y = fmaxf(acc[mi][j][1], 0.f);
                v1.x = fmaxf(acc[mi][j][2], 0.f);
                v1.y = fmaxf(acc[mi][j][3], 0.f);
                *reinterpret_cast<float2*>(out + ((size_t)bb * M + mrow0) * LL + t) = v0;
                *reinterpret_cast<float2*>(out + ((size_t)bb * M + mrow0 + 8) * LL + t) = v1;
            }
        }
    }
}

// ---------------- single-pass LayerNorm ----------------
// WRT==0: Hn = LN(V) fp32 (for next layer's scan)
// WRT==1: writes LN(V) directly as transposed bf16 hi/lo (decoder operands)
template <int WRT>
__global__ __launch_bounds__(256)
void ln_kernel(const float* __restrict__ V, float* __restrict__ Hn,
               __nv_bfloat16* __restrict__ dhi, __nv_bfloat16* __restrict__ dlo,
               const float* __restrict__ gamma, const float* __restrict__ beta)
{
    __shared__ float ssum[8][32];
    __shared__ float ssq[8][32];
    __shared__ __nv_bfloat16 hs[32][72];
    __shared__ __nv_bfloat16 ls[32][72];
    const int b = blockIdx.y;
    const int tx = threadIdx.x & 31;
    const int ty = threadIdx.x >> 5;          // 0..7
    const size_t t = (size_t)blockIdx.x * 32 + tx;
    const float* Vb = V + (size_t)b * HD * LL + t;
    float* Hb = Hn + (size_t)b * HD * LL + t;

    float vals[64];
    float s = 0.f, s2 = 0.f;
#pragma unroll
    for (int k = 0; k < 64; ++k) {
        const int c = k * 8 + ty;
        float v = Vb[(size_t)c * LL];
        vals[k] = v;
        s += v;
        s2 = fmaf(v, v, s2);
    }
    ssum[ty][tx] = s;
    ssq[ty][tx] = s2;
    __syncthreads();
    float st = 0.f, st2 = 0.f;
#pragma unroll
    for (int i = 0; i < 8; ++i) {
        st += ssum[i][tx];
        st2 += ssq[i][tx];
    }
    const float mu = st * (1.f / HD);
    const float var = st2 * (1.f / HD) - mu * mu;
    const float rstd = rsqrtf(var + 1e-5f);

    if (WRT == 0) {
#pragma unroll
        for (int k = 0; k < 64; ++k) {
            const int c = k * 8 + ty;
            Hb[(size_t)c * LL] = (vals[k] - mu) * rstd * gamma[c] + beta[c];
        }
    } else {
        const int tt = (int)(threadIdx.x >> 3), seg = (int)(threadIdx.x & 7);
        const size_t trow = ((size_t)b * LL + (size_t)blockIdx.x * 32 + tt) * HD;
#pragma unroll
        for (int kc = 0; kc < 8; ++kc) {
#pragma unroll
            for (int i = 0; i < 8; ++i) {
                const int k = kc * 8 + i;
                const int c = k * 8 + ty;
                float v = (vals[k] - mu) * rstd * gamma[c] + beta[c];
                __nv_bfloat16 h = __float2bfloat16(v);
                hs[tx][i * 8 + ty] = h;
                ls[tx][i * 8 + ty] = __float2bfloat16(v - __bfloat162float(h));
            }
            __syncthreads();
            *reinterpret_cast<uint4*>(dhi + trow + kc * 64 + seg * 8) =
                *reinterpret_cast<const uint4*>(&hs[tt][seg * 8]);
            *reinterpret_cast<uint4*>(dlo + trow + kc * 64 + seg * 8) =
                *reinterpret_cast<const uint4*>(&ls[tt][seg * 8]);
            __syncthreads();
        }
    }
}

// ---------------- SSM scan (scalar, R6 form) -> bf16 hi/lo T ------
__global__ __launch_bounds__(256)
void ssm_scan_fused(const float* __restrict__ hbuf,
                    __nv_bfloat16* __restrict__ dhi,
                    __nv_bfloat16* __restrict__ dlo,
                    const float* __restrict__ wre, const float* __restrict__ wim,
                    const float* __restrict__ ccre, const float* __restrict__ ccim,
                    const float* __restrict__ Dv)
{
    __shared__ float tile[32][33];
    const int tid = threadIdx.x;
    const int q = tid & 7;
    const int g = tid >> 3;                 // 0..31
    const int grp0 = blockIdx.x * 32;
    const int grp = grp0 + g;
    const int b = grp >> 9;
    const int hh = grp & (HD - 1);
    const int h0 = grp0 & (HD - 1);
    const float* hrow = hbuf + (size_t)grp * LL;

    const int pbase = hh * NN + q * 4;
    float4 w_r = *reinterpret_cast<const float4*>(&wre[pbase]);
    float4 w_i = *reinterpret_cast<const float4*>(&wim[pbase]);
    float4 c_r = *reinterpret_cast<const float4*>(&ccre[pbase]);
    float4 c_i = *reinterpret_cast<const float4*>(&ccim[pbase]);
    float wr[4] = {w_r.x, w_r.y, w_r.z, w_r.w};
    float wi[4] = {w_i.x, w_i.y, w_i.z, w_i.w};
    float cr[4] = {c_r.x, c_r.y, c_r.z, c_r.w};
    float ci[4] = {c_i.x, c_i.y, c_i.z, c_i.w};
    const float Dh = Dv[hh];

    float sr[4] = {0.f, 0.f, 0.f, 0.f};
    float si[4] = {0.f, 0.f, 0.f, 0.f};

    const int tt = tid >> 3, seg = tid & 7;

    for (int t0 = 0; t0 < LL; t0 += 32) {
#pragma unroll
        for (int sub = 0; sub < 4; ++sub) {
            const int tb = t0 + sub * 8;
            const float4 ua = *reinterpret_cast<const float4*>(hrow + tb);
            const float4 ub = *reinterpret_cast<const float4*>(hrow + tb + 4);
            const float uu[8] = {ua.x, ua.y, ua.z, ua.w, ub.x, ub.y, ub.z, ub.w};
            float umine = 0.f, ykeep = 0.f;
#pragma unroll
            for (int j = 0; j < 8; ++j) {
                const float u = uu[j];
#pragma unroll
                for (int k = 0; k < 4; ++k) {
                    float nr = fmaf(wr[k], sr[k], u);
                    nr = fmaf(-wi[k], si[k], nr);
                    float ni = wr[k] * si[k];
                    ni = fmaf(wi[k], sr[k], ni);
                    sr[k] = nr;
                    si[k] = ni;
                }
                float acc = 0.f;
#pragma unroll
                for (int k = 0; k < 4; ++k) {
                    acc = fmaf(cr[k], sr[k], acc);
                    acc = fmaf(-ci[k], si[k], acc);
                }
                acc += __shfl_xor_sync(0xffffffffu, acc, 1);
                acc += __shfl_xor_sync(0xffffffffu, acc, 2);
                acc += __shfl_xor_sync(0xffffffffu, acc, 4);
                if (j == q) { umine = u; ykeep = acc; }
            }
            float yv = fmaf(Dh, umine, 2.f * ykeep);
            float gv = 0.5f * yv * (1.f + erff(yv * 0.70710678118654752f));
            tile[sub * 8 + q][g] = gv;
        }
        __syncthreads();
        {
            const int t = t0 + tt;
            float v0 = tile[tt][seg * 4 + 0];
            float v1 = tile[tt][seg * 4 + 1];
            float v2 = tile[tt][seg * 4 + 2];
            float v3 = tile[tt][seg * 4 + 3];
            __nv_bfloat16 hi4[4], lo4[4];
            hi4[0] = __float2bfloat16(v0);
            hi4[1] = __float2bfloat16(v1);
            hi4[2] = __float2bfloat16(v2);
            hi4[3] = __float2bfloat16(v3);
            lo4[0] = __float2bfloat16(v0 - __bfloat162float(hi4[0]));
            lo4[1] = __float2bfloat16(v1 - __bfloat162float(hi4[1]));
            lo4[2] = __float2bfloat16(v2 - __bfloat162float(hi4[2]));
            lo4[3] = __float2bfloat16(v3 - __bfloat162float(hi4[3]));
            const size_t o = ((size_t)b * LL + t) * HD + h0 + seg * 4;
            *reinterpret_cast<uint2*>(dhi + o) = *reinterpret_cast<uint2*>(hi4);
            *reinterpret_cast<uint2*>(dlo + o) = *reinterpret_cast<uint2*>(lo4);
        }
        __syncthreads();
    }
}

// ---------------- launch ----------------
extern "C" void kernel_launch(void* const* d_in, const int* in_sizes, int n_in,
                              void* d_out, int out_size)
{
    const float* x = (const float*)d_in[0];
    const float* W_enc = (const float*)d_in[1];
    const float* W_dec = (const float*)d_in[2];
    const float* log_dt = (const float*)d_in[3];
    const float* log_A_real = (const float*)d_in[4];
    const float* A_imag = (const float*)d_in[5];
    const float* C_re = (const float*)d_in[6];
    const float* C_im = (const float*)d_in[7];
    const float* Dv = (const float*)d_in[8];
    const float* W_out = (const float*)d_in[9];
    const float* b_out = (const float*)d_in[10];
    const float* ln_g = (const float*)d_in[11];
    const float* ln_b = (const float*)d_in[12];
    float* out = (float*)d_out;

    float *pH, *pV, *pwre, *pwim, *pcre, *pcim;
    __nv_bfloat16 *pBth, *pBtl, *pWh, *pWl;
    cudaGetSymbolAddress((void**)&pH, g_H);
    cudaGetSymbolAddress((void**)&pV, g_V);
    cudaGetSymbolAddress((void**)&pwre, g_wre);
    cudaGetSymbolAddress((void**)&pwim, g_wim);
    cudaGetSymbolAddress((void**)&pcre, g_cre);
    cudaGetSymbolAddress((void**)&pcim, g_cim);
    cudaGetSymbolAddress((void**)&pBth, g_Bth);
    cudaGetSymbolAddress((void**)&pBtl, g_Btl);
    cudaGetSymbolAddress((void**)&pWh, g_Wh);
    cudaGetSymbolAddress((void**)&pWl, g_Wl);

    cudaFuncSetAttribute(gemm_mma<0>, cudaFuncAttributeMaxDynamicSharedMemorySize, GEMM_SMEM);
    cudaFuncSetAttribute(gemm_mma<2>, cudaFuncAttributeMaxDynamicSharedMemorySize, GEMM_SMEM);

    precompute_kernel<<<(NL * HD * NN + 255) / 256, 256>>>(log_dt, log_A_real,
                                                           A_imag, C_re, C_im);
    split_w_all<<<(W_ELEMS + 255) / 256, 256>>>(W_enc, W_out, W_dec, pWh, pWl);

    const dim3 tgrid(LL / 32, HD / 32, BQ);

    // encoder: H = relu(W_enc @ quant(x))
    transpose_split_kernel<true><<<tgrid, 256>>>(x, pBth, pBtl);
    gemm_mma<0><<<dim3(NTOT / 128, HD / 128), 256, GEMM_SMEM>>>(
        pWh + W_ENC_OFF, pWl + W_ENC_OFF, pBth, pBtl, pH, nullptr, HD, nullptr);

    for (int l = 0; l < NL; ++l) {
        const int po = l * HD * NN;
        // scan(H) + gelu -> transposed bf16 hi/lo
        ssm_scan_fused<<<(BQ * HD) / 32, 256>>>(
            pH, pBth, pBtl, pwre + po, pwim + po, pcre + po, pcim + po,
            Dv + l * HD);
        // fused GLU + residual: V = glu(z) + H
        gemm_mma<2><<<dim3(NTOT / 128, HD / 64), 256, GEMM_SMEM>>>(
            pWh + W_OUT_OFF + (size_t)l * 2 * HD * HD,
            pWl + W_OUT_OFF + (size_t)l * 2 * HD * HD,
            pBth, pBtl, pV, b_out + l * 2 * HD, HD, pH);
        // H = LN(V); last layer writes decoder operands directly
        if (l < NL - 1)
            ln_kernel<0><<<dim3(LL / 32, BQ), 256>>>(pV, pH, nullptr, nullptr,
                                                     ln_g + l * HD, ln_b + l * HD);
        else
            ln_kernel<1><<<dim3(LL / 32, BQ), 256>>>(pV, nullptr, pBth, pBtl,
                                                     ln_g + l * HD, ln_b + l * HD);
    }

    // decoder: out = relu(W_dec @ LN(V3))
    gemm_mma<0><<<dim3(NTOT / 128, HD / 128), 256, GEMM_SMEM>>>(
        pWh + W_DEC_OFF, pWl + W_DEC_OFF, pBth, pBtl, out, nullptr, HD, nullptr);
}

// round 10
// speedup vs baseline: 1.0316x; 1.0063x over previous
#include <cuda_runtime.h>
#include <cuda_bf16.h>
#include <stdint.h>
#include <math.h>

#define BQ 16
#define HD 512
#define LL 2048
#define NL 4
#define NN 32
#define NTOT (BQ * LL)  // 32768 total columns

// ---------------- scratch (static __device__, no allocs) ----------------
__device__ float g_H[(size_t)BQ * HD * LL];          // normalized stream Hn
__device__ float g_V[(size_t)BQ * HD * LL];          // pre-norm V scratch
__device__ __nv_bfloat16 g_Bth[(size_t)NTOT * HD];   // activations (n,k) hi
__device__ __nv_bfloat16 g_Btl[(size_t)NTOT * HD];   // activations (n,k) lo
#define W_ENC_OFF 0
#define W_OUT_OFF (HD * HD)
#define W_DEC_OFF (HD * HD + NL * 2 * HD * HD)
#define W_ELEMS (2 * HD * HD + NL * 2 * HD * HD)
__device__ __nv_bfloat16 g_Wh[W_ELEMS];
__device__ __nv_bfloat16 g_Wl[W_ELEMS];
__device__ float g_wre[NL * HD * NN];
__device__ float g_wim[NL * HD * NN];
__device__ float g_cre[NL * HD * NN];
__device__ float g_cim[NL * HD * NN];

// ---------------- helpers ----------------
__device__ __forceinline__ uint32_t smem_u32(const void* p)
{
    uint32_t a;
    asm("{ .reg .u64 t; cvta.to.shared.u64 t, %1; cvt.u32.u64 %0, t; }"
        : "=r"(a) : "l"(p));
    return a;
}

__device__ __forceinline__ void cp_async16(uint32_t dst, const void* src)
{
    asm volatile("cp.async.cg.shared.global [%0], [%1], 16;" :: "r"(dst), "l"(src));
}
#define CP_COMMIT() asm volatile("cp.async.commit_group;" ::: "memory")
#define CP_WAIT(n)  asm volatile("cp.async.wait_group %0;" :: "n"(n) : "memory")

__device__ __forceinline__ void ldmx4(uint32_t* r, uint32_t addr)
{
    asm volatile("ldmatrix.sync.aligned.m8n8.x4.shared.b16 {%0,%1,%2,%3}, [%4];"
                 : "=r"(r[0]), "=r"(r[1]), "=r"(r[2]), "=r"(r[3]) : "r"(addr));
}

__device__ __forceinline__ void mma16816(float* c, const uint32_t* a,
                                         const uint32_t* b)
{
    asm volatile(
        "mma.sync.aligned.m16n8k16.row.col.f32.bf16.bf16.f32 "
        "{%0,%1,%2,%3}, {%4,%5,%6,%7}, {%8,%9}, {%0,%1,%2,%3};"
        : "+f"(c[0]), "+f"(c[1]), "+f"(c[2]), "+f"(c[3])
        : "r"(a[0]), "r"(a[1]), "r"(a[2]), "r"(a[3]), "r"(b[0]), "r"(b[1]));
}

// ---------------- parameter precompute ----------------
__global__ __launch_bounds__(256)
void precompute_kernel(const float* __restrict__ log_dt,
                       const float* __restrict__ log_A_real,
                       const float* __restrict__ A_imag,
                       const float* __restrict__ C_re,
                       const float* __restrict__ C_im)
{
    int idx = blockIdx.x * 256 + threadIdx.x;
    if (idx >= NL * HD * NN) return;
    int h = (idx >> 5) & (HD - 1);
    int l = idx >> 14;
    float dt = expf(log_dt[l * HD + h]);
    float a = -expf(log_A_real[idx]);
    float b = A_imag[idx];
    float xr = dt * a, xi = dt * b;
    float er = expf(xr);
    float c = cosf(xi), s = sinf(xi);
    g_wre[idx] = er * c;
    g_wim[idx] = er * s;
    float sh = sinf(0.5f * xi);
    float Ere = expm1f(xr) * c - 2.f * sh * sh;
    float Eim = er * s;
    float den = a * a + b * b;
    float Fre = (Ere * a + Eim * b) / den;
    float Fim = (Eim * a - Ere * b) / den;
    float cr = C_re[idx], ci = C_im[idx];
    g_cre[idx] = cr * Fre - ci * Fim;
    g_cim[idx] = cr * Fim + ci * Fre;
}

// ---------------- weight split fp32 -> bf16 hi/lo (all weights, one launch) ----
__global__ __launch_bounds__(256)
void split_w_all(const float* __restrict__ W_enc, const float* __restrict__ W_out,
                 const float* __restrict__ W_dec,
                 __nv_bfloat16* __restrict__ hi, __nv_bfloat16* __restrict__ lo)
{
    int i = blockIdx.x * 256 + threadIdx.x;
    if (i >= W_ELEMS) return;
    float v;
    if (i < W_OUT_OFF) v = W_enc[i];
    else if (i < W_DEC_OFF) v = W_out[i - W_OUT_OFF];
    else v = W_dec[i - W_DEC_OFF];
    __nv_bfloat16 h = __float2bfloat16(v);
    hi[i] = h;
    lo[i] = __float2bfloat16(v - __bfloat162float(h));
}

// ---------------- transpose + split (+opt quant) ----------
template <bool QUANT>
__global__ __launch_bounds__(256)
void transpose_split_kernel(const float* __restrict__ src,
                            __nv_bfloat16* __restrict__ dhi,
                            __nv_bfloat16* __restrict__ dlo)
{
    __shared__ float tile[32][33];
    const int b = blockIdx.z;
    const int c0 = blockIdx.y * 32;
    const int t0 = blockIdx.x * 32;
    const int tx = threadIdx.x & 31, ty = threadIdx.x >> 5;
#pragma unroll
    for (int i = 0; i < 32; i += 8) {
        float v = src[((size_t)b * HD + c0 + ty + i) * LL + t0 + tx];
        if (QUANT) v = rintf(v * 64.f) * 0.015625f;
        tile[ty + i][tx] = v;
    }
    __syncthreads();
#pragma unroll
    for (int i = 0; i < 32; i += 8) {
        int t = t0 + ty + i;
        int c = c0 + tx;
        float v = tile[tx][ty + i];
        __nv_bfloat16 h = __float2bfloat16(v);
        size_t o = ((size_t)b * LL + t) * HD + c;
        dhi[o] = h;
        dlo[o] = __float2bfloat16(v - __bfloat162float(h));
    }
}

// ---------------- HMMA GEMM (3x bf16 split, fp32 acc, 3-stage pipe) --------
#define KC 64
#define TILE_BYTES 16384            // 128 * 64 * 2B
#define STAGE_BYTES (4 * TILE_BYTES)
#define GEMM_SMEM (3 * STAGE_BYTES) // 196608

template <int EPI>
__global__ __launch_bounds__(256, 1)
void gemm_mma(const __nv_bfloat16* __restrict__ Wh, const __nv_bfloat16* __restrict__ Wl,
              const __nv_bfloat16* __restrict__ Xh, const __nv_bfloat16* __restrict__ Xl,
              float* __restrict__ out, const float* __restrict__ bias, int M,
              const float* __restrict__ Hprev)
{
    extern __shared__ char smem[];
    const uint32_t sb = smem_u32(smem);
    const int tid = threadIdx.x;
    const int wid = tid >> 5, lane = tid & 31;
    const int wm = wid >> 1, wn = wid & 1;
    const int n0 = blockIdx.x * 128;
    const int m0 = blockIdx.y * ((EPI == 2) ? 64 : 128);
    const int lr = lane & 7, lg = lane >> 3;

    float acc[2][8][4];
#pragma unroll
    for (int i = 0; i < 2; ++i)
#pragma unroll
        for (int j = 0; j < 8; ++j)
#pragma unroll
            for (int q = 0; q < 4; ++q) acc[i][j][q] = 0.f;

    auto load_chunk = [&](int kc, int st) {
        const uint32_t base = sb + st * STAGE_BYTES;
        const size_t gk = (size_t)kc * KC;
#pragma unroll
        for (int i = 0; i < 4; ++i) {
            int lin = i * 256 + tid;
            int row = lin >> 3, seg = lin & 7;
            uint32_t soff = row * 128 + (((seg ^ (row & 7))) << 4);
            int wrow;
            if (EPI == 2)
                wrow = ((row >> 4) & 1) * HD + m0 + (row >> 5) * 16 + (row & 15);
            else
                wrow = m0 + row;
            const size_t wgo = (size_t)wrow * HD + gk + seg * 8;
            const size_t xgo = (size_t)(n0 + row) * HD + gk + seg * 8;
            cp_async16(base + soff, Wh + wgo);
            cp_async16(base + TILE_BYTES + soff, Wl + wgo);
            cp_async16(base + 2 * TILE_BYTES + soff, Xh + xgo);
            cp_async16(base + 3 * TILE_BYTES + soff, Xl + xgo);
        }
        CP_COMMIT();
    };

    load_chunk(0, 0);
    load_chunk(1, 1);

    const int NCH = HD / KC;  // 8
    for (int c = 0; c < NCH; ++c) {
        if (c < NCH - 1) { CP_WAIT(1); } else { CP_WAIT(0); }
        __syncthreads();
        if (c + 2 < NCH) load_chunk(c + 2, (c + 2) % 3);

        const uint32_t stg = sb + (c % 3) * STAGE_BYTES;
#pragma unroll
        for (int ks = 0; ks < 4; ++ks) {
            uint32_t a[2][2][4];
            uint32_t b[2][4][4];
#pragma unroll
            for (int mi = 0; mi < 2; ++mi) {
                int arow = wm * 32 + mi * 16 + lr + (lg & 1) * 8;
                int aseg = ks * 2 + (lg >> 1);
                uint32_t off = arow * 128 + ((aseg ^ (arow & 7)) << 4);
                ldmx4(a[0][mi], stg + off);
                ldmx4(a[1][mi], stg + TILE_BYTES + off);
            }
#pragma unroll
            for (int g = 0; g < 4; ++g) {
                int brow = wn * 64 + g * 16 + lr + (lg >> 1) * 8;
                int bseg = ks * 2 + (lg & 1);
                uint32_t off = brow * 128 + ((bseg ^ (brow & 7)) << 4);
                ldmx4(b[0][g], stg + 2 * TILE_BYTES + off);
                ldmx4(b[1][g], stg + 3 * TILE_BYTES + off);
            }
#pragma unroll
            for (int mi = 0; mi < 2; ++mi)
#pragma unroll
                for (int j = 0; j < 8; ++j) {
                    const int g = j >> 1, p = (j & 1) * 2;
                    uint32_t bh[2] = {b[0][g][p], b[0][g][p + 1]};
                    uint32_t bl[2] = {b[1][g][p], b[1][g][p + 1]};
                    mma16816(acc[mi][j], a[0][mi], bh);
                    mma16816(acc[mi][j], a[0][mi], bl);
                    mma16816(acc[mi][j], a[1][mi], bh);
                }
        }
    }

    // ---------------- epilogue ----------------
    if (EPI == 2) {
        const int m = m0 + wm * 16 + (lane >> 2);
        const float b10 = bias[m],      b18 = bias[m + 8];
        const float b20 = bias[HD + m], b28 = bias[HD + m + 8];
#pragma unroll
        for (int j = 0; j < 8; ++j) {
            const int n = n0 + wn * 64 + j * 8 + (lane & 3) * 2;
            const int bb = n >> 11;
            const int t = n & (LL - 1);
            float z10 = acc[0][j][0] + b10, z11 = acc[0][j][1] + b10;
            float z12 = acc[0][j][2] + b18, z13 = acc[0][j][3] + b18;
            float z20 = acc[1][j][0] + b20, z21 = acc[1][j][1] + b20;
            float z22 = acc[1][j][2] + b28, z23 = acc[1][j][3] + b28;
            const float2 p0 = *reinterpret_cast<const float2*>(
                Hprev + ((size_t)bb * HD + m) * LL + t);
            const float2 p1 = *reinterpret_cast<const float2*>(
                Hprev + ((size_t)bb * HD + m + 8) * LL + t);
            float2 v0, v1;
            v0.x = z10 / (1.f + expf(-z20)) + p0.x;
            v0.y = z11 / (1.f + expf(-z21)) + p0.y;
            v1.x = z12 / (1.f + expf(-z22)) + p1.x;
            v1.y = z13 / (1.f + expf(-z23)) + p1.y;
            *reinterpret_cast<float2*>(out + ((size_t)bb * HD + m) * LL + t) = v0;
            *reinterpret_cast<float2*>(out + ((size_t)bb * HD + m + 8) * LL + t) = v1;
        }
    } else {
#pragma unroll
        for (int mi = 0; mi < 2; ++mi) {
            const int mrow0 = m0 + wm * 32 + mi * 16 + (lane >> 2);
#pragma unroll
            for (int j = 0; j < 8; ++j) {
                const int n = n0 + wn * 64 + j * 8 + (lane & 3) * 2;
                const int bb = n >> 11;
                const int t = n & (LL - 1);
                float2 v0, v1;
                v0.x = fmaxf(acc[mi][j][0], 0.f);
                v0.y = fmaxf(acc[mi][j][1], 0.f);
                v1.x = fmaxf(acc[mi][j][2], 0.f);
                v1.y = fmaxf(acc[mi][j][3], 0.f);
                *reinterpret_cast<float2*>(out + ((size_t)bb * M + mrow0) * LL + t) = v0;
                *reinterpret_cast<float2*>(out + ((size_t)bb * M + mrow0 + 8) * LL + t) = v1;
            }
        }
    }
}

// ---------------- single-pass LayerNorm ----------------
// WRT==0: Hn = LN(V) fp32 (for next layer's scan)
// WRT==1: writes LN(V) directly as transposed bf16 hi/lo (decoder operands)
template <int WRT>
__global__ __launch_bounds__(256)
void ln_kernel(const float* __restrict__ V, float* __restrict__ Hn,
               __nv_bfloat16* __restrict__ dhi, __nv_bfloat16* __restrict__ dlo,
               const float* __restrict__ gamma, const float* __restrict__ beta)
{
    __shared__ float ssum[8][32];
    __shared__ float ssq[8][32];
    __shared__ __nv_bfloat16 hs[32][72];
    __shared__ __nv_bfloat16 ls[32][72];
    const int b = blockIdx.y;
    const int tx = threadIdx.x & 31;
    const int ty = threadIdx.x >> 5;          // 0..7
    const size_t t = (size_t)blockIdx.x * 32 + tx;
    const float* Vb = V + (size_t)b * HD * LL + t;
    float* Hb = Hn + (size_t)b * HD * LL + t;

    float vals[64];
    float s = 0.f, s2 = 0.f;
#pragma unroll
    for (int k = 0; k < 64; ++k) {
        const int c = k * 8 + ty;
        float v = Vb[(size_t)c * LL];
        vals[k] = v;
        s += v;
        s2 = fmaf(v, v, s2);
    }
    ssum[ty][tx] = s;
    ssq[ty][tx] = s2;
    __syncthreads();
    float st = 0.f, st2 = 0.f;
#pragma unroll
    for (int i = 0; i < 8; ++i) {
        st += ssum[i][tx];
        st2 += ssq[i][tx];
    }
    const float mu = st * (1.f / HD);
    const float var = st2 * (1.f / HD) - mu * mu;
    const float rstd = rsqrtf(var + 1e-5f);

    if (WRT == 0) {
#pragma unroll
        for (int k = 0; k < 64; ++k) {
            const int c = k * 8 + ty;
            Hb[(size_t)c * LL] = (vals[k] - mu) * rstd * gamma[c] + beta[c];
        }
    } else {
        const int tt = (int)(threadIdx.x >> 3), seg = (int)(threadIdx.x & 7);
        const size_t trow = ((size_t)b * LL + (size_t)blockIdx.x * 32 + tt) * HD;
#pragma unroll
        for (int kc = 0; kc < 8; ++kc) {
#pragma unroll
            for (int i = 0; i < 8; ++i) {
                const int k = kc * 8 + i;
                const int c = k * 8 + ty;
                float v = (vals[k] - mu) * rstd * gamma[c] + beta[c];
                __nv_bfloat16 h = __float2bfloat16(v);
                hs[tx][i * 8 + ty] = h;
                ls[tx][i * 8 + ty] = __float2bfloat16(v - __bfloat162float(h));
            }
            __syncthreads();
            *reinterpret_cast<uint4*>(dhi + trow + kc * 64 + seg * 8) =
                *reinterpret_cast<const uint4*>(&hs[tt][seg * 8]);
            *reinterpret_cast<uint4*>(dlo + trow + kc * 64 + seg * 8) =
                *reinterpret_cast<const uint4*>(&ls[tt][seg * 8]);
            __syncthreads();
        }
    }
}

// ---------------- SSM scan (scalar) -> bf16 hi/lo T ------
__global__ __launch_bounds__(256)
void ssm_scan_fused(const float* __restrict__ hbuf,
                    __nv_bfloat16* __restrict__ dhi,
                    __nv_bfloat16* __restrict__ dlo,
                    const float* __restrict__ wre, const float* __restrict__ wim,
                    const float* __restrict__ ccre, const float* __restrict__ ccim,
                    const float* __restrict__ Dv)
{
    __shared__ float tile[32][33];
    const int tid = threadIdx.x;
    const int q = tid & 7;
    const int g = tid >> 3;                 // 0..31
    const int grp0 = blockIdx.x * 32;
    const int grp = grp0 + g;
    const int b = grp >> 9;
    const int hh = grp & (HD - 1);
    const int h0 = grp0 & (HD - 1);
    const float* hrow = hbuf + (size_t)grp * LL;

    const int pbase = hh * NN + q * 4;
    float4 w_r = *reinterpret_cast<const float4*>(&wre[pbase]);
    float4 w_i = *reinterpret_cast<const float4*>(&wim[pbase]);
    float4 c_r = *reinterpret_cast<const float4*>(&ccre[pbase]);
    float4 c_i = *reinterpret_cast<const float4*>(&ccim[pbase]);
    float wr[4] = {w_r.x, w_r.y, w_r.z, w_r.w};
    float wi[4] = {w_i.x, w_i.y, w_i.z, w_i.w};
    float cr[4] = {c_r.x, c_r.y, c_r.z, c_r.w};
    float ci[4] = {c_i.x, c_i.y, c_i.z, c_i.w};
    const float Dh = Dv[hh];

    float sr[4] = {0.f, 0.f, 0.f, 0.f};
    float si[4] = {0.f, 0.f, 0.f, 0.f};

    const int tt = tid >> 3, seg = tid & 7;

    for (int t0 = 0; t0 < LL; t0 += 32) {
#pragma unroll
        for (int sub = 0; sub < 4; ++sub) {
            const int tb = t0 + sub * 8;
            const float4 ua = *reinterpret_cast<const float4*>(hrow + tb);
            const float4 ub = *reinterpret_cast<const float4*>(hrow + tb + 4);
            const float uu[8] = {ua.x, ua.y, ua.z, ua.w, ub.x, ub.y, ub.z, ub.w};
            float umine = 0.f, ykeep = 0.f;
#pragma unroll
            for (int j = 0; j < 8; ++j) {
                const float u = uu[j];
#pragma unroll
                for (int k = 0; k < 4; ++k) {
                    float nr = fmaf(wr[k], sr[k], u);
                    nr = fmaf(-wi[k], si[k], nr);
                    float ni = wr[k] * si[k];
                    ni = fmaf(wi[k], sr[k], ni);
                    sr[k] = nr;
                    si[k] = ni;
                }
                float acc = 0.f;
#pragma unroll
                for (int k = 0; k < 4; ++k) {
                    acc = fmaf(cr[k], sr[k], acc);
                    acc = fmaf(-ci[k], si[k], acc);
                }
                acc += __shfl_xor_sync(0xffffffffu, acc, 1);
                acc += __shfl_xor_sync(0xffffffffu, acc, 2);
                acc += __shfl_xor_sync(0xffffffffu, acc, 4);
                if (j == q) { umine = u; ykeep = acc; }
            }
            float yv = fmaf(Dh, umine, 2.f * ykeep);
            float gv = 0.5f * yv * (1.f + erff(yv * 0.70710678118654752f));
            tile[sub * 8 + q][g] = gv;
        }
        __syncthreads();
        {
            const int t = t0 + tt;
            float v0 = tile[tt][seg * 4 + 0];
            float v1 = tile[tt][seg * 4 + 1];
            float v2 = tile[tt][seg * 4 + 2];
            float v3 = tile[tt][seg * 4 + 3];
            __nv_bfloat16 hi4[4], lo4[4];
            hi4[0] = __float2bfloat16(v0);
            hi4[1] = __float2bfloat16(v1);
            hi4[2] = __float2bfloat16(v2);
            hi4[3] = __float2bfloat16(v3);
            lo4[0] = __float2bfloat16(v0 - __bfloat162float(hi4[0]));
            lo4[1] = __float2bfloat16(v1 - __bfloat162float(hi4[1]));
            lo4[2] = __float2bfloat16(v2 - __bfloat162float(hi4[2]));
            lo4[3] = __float2bfloat16(v3 - __bfloat162float(hi4[3]));
            const size_t o = ((size_t)b * LL + t) * HD + h0 + seg * 4;
            *reinterpret_cast<uint2*>(dhi + o) = *reinterpret_cast<uint2*>(hi4);
            *reinterpret_cast<uint2*>(dlo + o) = *reinterpret_cast<uint2*>(lo4);
        }
        __syncthreads();
    }
}

// ---------------- launch ----------------
extern "C" void kernel_launch(void* const* d_in, const int* in_sizes, int n_in,
                              void* d_out, int out_size)
{
    const float* x = (const float*)d_in[0];
    const float* W_enc = (const float*)d_in[1];
    const float* W_dec = (const float*)d_in[2];
    const float* log_dt = (const float*)d_in[3];
    const float* log_A_real = (const float*)d_in[4];
    const float* A_imag = (const float*)d_in[5];
    const float* C_re = (const float*)d_in[6];
    const float* C_im = (const float*)d_in[7];
    const float* Dv = (const float*)d_in[8];
    const float* W_out = (const float*)d_in[9];
    const float* b_out = (const float*)d_in[10];
    const float* ln_g = (const float*)d_in[11];
    const float* ln_b = (const float*)d_in[12];
    float* out = (float*)d_out;

    float *pH, *pV, *pwre, *pwim, *pcre, *pcim;
    __nv_bfloat16 *pBth, *pBtl, *pWh, *pWl;
    cudaGetSymbolAddress((void**)&pH, g_H);
    cudaGetSymbolAddress((void**)&pV, g_V);
    cudaGetSymbolAddress((void**)&pwre, g_wre);
    cudaGetSymbolAddress((void**)&pwim, g_wim);
    cudaGetSymbolAddress((void**)&pcre, g_cre);
    cudaGetSymbolAddress((void**)&pcim, g_cim);
    cudaGetSymbolAddress((void**)&pBth, g_Bth);
    cudaGetSymbolAddress((void**)&pBtl, g_Btl);
    cudaGetSymbolAddress((void**)&pWh, g_Wh);
    cudaGetSymbolAddress((void**)&pWl, g_Wl);

    cudaFuncSetAttribute(gemm_mma<0>, cudaFuncAttributeMaxDynamicSharedMemorySize, GEMM_SMEM);
    cudaFuncSetAttribute(gemm_mma<2>, cudaFuncAttributeMaxDynamicSharedMemorySize, GEMM_SMEM);

    precompute_kernel<<<(NL * HD * NN + 255) / 256, 256>>>(log_dt, log_A_real,
                                                           A_imag, C_re, C_im);
    split_w_all<<<(W_ELEMS + 255) / 256, 256>>>(W_enc, W_out, W_dec, pWh, pWl);

    const dim3 tgrid(LL / 32, HD / 32, BQ);

    // encoder: H = relu(W_enc @ quant(x))
    transpose_split_kernel<true><<<tgrid, 256>>>(x, pBth, pBtl);
    gemm_mma<0><<<dim3(NTOT / 128, HD / 128), 256, GEMM_SMEM>>>(
        pWh + W_ENC_OFF, pWl + W_ENC_OFF, pBth, pBtl, pH, nullptr, HD, nullptr);

    for (int l = 0; l < NL; ++l) {
        const int po = l * HD * NN;
        // scan(H) + gelu -> transposed bf16 hi/lo
        ssm_scan_fused<<<(BQ * HD) / 32, 256>>>(
            pH, pBth, pBtl, pwre + po, pwim + po, pcre + po, pcim + po,
            Dv + l * HD);
        // fused GLU + residual: V = glu(z) + H
        gemm_mma<2><<<dim3(NTOT / 128, HD / 64), 256, GEMM_SMEM>>>(
            pWh + W_OUT_OFF + (size_t)l * 2 * HD * HD,
            pWl + W_OUT_OFF + (size_t)l * 2 * HD * HD,
            pBth, pBtl, pV, b_out + l * 2 * HD, HD, pH);
        // H = LN(V); last layer writes decoder operands directly
        if (l < NL - 1)
            ln_kernel<0><<<dim3(LL / 32, BQ), 256>>>(pV, pH, nullptr, nullptr,
                                                     ln_g + l * HD, ln_b + l * HD);
        else
            ln_kernel<1><<<dim3(LL / 32, BQ), 256>>>(pV, nullptr, pBth, pBtl,
                                                     ln_g + l * HD, ln_b + l * HD);
    }

    // decoder: out = relu(W_dec @ LN(V3))
    gemm_mma<0><<<dim3(NTOT / 128, HD / 128), 256, GEMM_SMEM>>>(
        pWh + W_DEC_OFF, pWl + W_DEC_OFF, pBth, pBtl, out, nullptr, HD, nullptr);
}

// round 12
// speedup vs baseline: 1.0330x; 1.0014x over previous
#include <cuda_runtime.h>
#include <cuda_bf16.h>
#include <stdint.h>
#include <math.h>

#define BQ 16
#define HD 512
#define LL 2048
#define NL 4
#define NN 32
#define NTOT (BQ * LL)  // 32768 total columns

// ---------------- scratch (static __device__, no allocs) ----------------
__device__ float g_H[(size_t)BQ * HD * LL];          // normalized stream Hn
__device__ float g_V[(size_t)BQ * HD * LL];          // pre-norm V scratch
__device__ __nv_bfloat16 g_Bth[(size_t)NTOT * HD];   // activations (n,k) hi
__device__ __nv_bfloat16 g_Btl[(size_t)NTOT * HD];   // activations (n,k) lo
#define W_ENC_OFF 0
#define W_OUT_OFF (HD * HD)
#define W_DEC_OFF (HD * HD + NL * 2 * HD * HD)
#define W_ELEMS (2 * HD * HD + NL * 2 * HD * HD)
__device__ __nv_bfloat16 g_Wh[W_ELEMS];
__device__ __nv_bfloat16 g_Wl[W_ELEMS];
__device__ float g_wre[NL * HD * NN];
__device__ float g_wim[NL * HD * NN];
__device__ float g_cre[NL * HD * NN];
__device__ float g_cim[NL * HD * NN];

// ---------------- helpers ----------------
__device__ __forceinline__ uint32_t smem_u32(const void* p)
{
    uint32_t a;
    asm("{ .reg .u64 t; cvta.to.shared.u64 t, %1; cvt.u32.u64 %0, t; }"
        : "=r"(a) : "l"(p));
    return a;
}

__device__ __forceinline__ void cp_async16(uint32_t dst, const void* src)
{
    asm volatile("cp.async.cg.shared.global [%0], [%1], 16;" :: "r"(dst), "l"(src));
}
#define CP_COMMIT() asm volatile("cp.async.commit_group;" ::: "memory")
#define CP_WAIT(n)  asm volatile("cp.async.wait_group %0;" :: "n"(n) : "memory")

__device__ __forceinline__ void ldmx4(uint32_t* r, uint32_t addr)
{
    asm volatile("ldmatrix.sync.aligned.m8n8.x4.shared.b16 {%0,%1,%2,%3}, [%4];"
                 : "=r"(r[0]), "=r"(r[1]), "=r"(r[2]), "=r"(r[3]) : "r"(addr));
}

__device__ __forceinline__ void mma16816(float* c, const uint32_t* a,
                                         const uint32_t* b)
{
    asm volatile(
        "mma.sync.aligned.m16n8k16.row.col.f32.bf16.bf16.f32 "
        "{%0,%1,%2,%3}, {%4,%5,%6,%7}, {%8,%9}, {%0,%1,%2,%3};"
        : "+f"(c[0]), "+f"(c[1]), "+f"(c[2]), "+f"(c[3])
        : "r"(a[0]), "r"(a[1]), "r"(a[2]), "r"(a[3]), "r"(b[0]), "r"(b[1]));
}

// ---------------- parameter precompute ----------------
__global__ __launch_bounds__(256)
void precompute_kernel(const float* __restrict__ log_dt,
                       const float* __restrict__ log_A_real,
                       const float* __restrict__ A_imag,
                       const float* __restrict__ C_re,
                       const float* __restrict__ C_im)
{
    int idx = blockIdx.x * 256 + threadIdx.x;
    if (idx >= NL * HD * NN) return;
    int h = (idx >> 5) & (HD - 1);
    int l = idx >> 14;
    float dt = expf(log_dt[l * HD + h]);
    float a = -expf(log_A_real[idx]);
    float b = A_imag[idx];
    float xr = dt * a, xi = dt * b;
    float er = expf(xr);
    float c = cosf(xi), s = sinf(xi);
    g_wre[idx] = er * c;
    g_wim[idx] = er * s;
    float sh = sinf(0.5f * xi);
    float Ere = expm1f(xr) * c - 2.f * sh * sh;
    float Eim = er * s;
    float den = a * a + b * b;
    float Fre = (Ere * a + Eim * b) / den;
    float Fim = (Eim * a - Ere * b) / den;
    float cr = C_re[idx], ci = C_im[idx];
    g_cre[idx] = cr * Fre - ci * Fim;
    g_cim[idx] = cr * Fim + ci * Fre;
}

// ---------------- weight split fp32 -> bf16 hi/lo (all weights, one launch) ----
__global__ __launch_bounds__(256)
void split_w_all(const float* __restrict__ W_enc, const float* __restrict__ W_out,
                 const float* __restrict__ W_dec,
                 __nv_bfloat16* __restrict__ hi, __nv_bfloat16* __restrict__ lo)
{
    int i = blockIdx.x * 256 + threadIdx.x;
    if (i >= W_ELEMS) return;
    float v;
    if (i < W_OUT_OFF) v = W_enc[i];
    else if (i < W_DEC_OFF) v = W_out[i - W_OUT_OFF];
    else v = W_dec[i - W_DEC_OFF];
    __nv_bfloat16 h = __float2bfloat16(v);
    hi[i] = h;
    lo[i] = __float2bfloat16(v - __bfloat162float(h));
}

// ---------------- transpose + split (+opt quant) ----------
template <bool QUANT>
__global__ __launch_bounds__(256)
void transpose_split_kernel(const float* __restrict__ src,
                            __nv_bfloat16* __restrict__ dhi,
                            __nv_bfloat16* __restrict__ dlo)
{
    __shared__ float tile[32][33];
    const int b = blockIdx.z;
    const int c0 = blockIdx.y * 32;
    const int t0 = blockIdx.x * 32;
    const int tx = threadIdx.x & 31, ty = threadIdx.x >> 5;
#pragma unroll
    for (int i = 0; i < 32; i += 8) {
        float v = src[((size_t)b * HD + c0 + ty + i) * LL + t0 + tx];
        if (QUANT) v = rintf(v * 64.f) * 0.015625f;
        tile[ty + i][tx] = v;
    }
    __syncthreads();
#pragma unroll
    for (int i = 0; i < 32; i += 8) {
        int t = t0 + ty + i;
        int c = c0 + tx;
        float v = tile[tx][ty + i];
        __nv_bfloat16 h = __float2bfloat16(v);
        size_t o = ((size_t)b * LL + t) * HD + c;
        dhi[o] = h;
        dlo[o] = __float2bfloat16(v - __bfloat162float(h));
    }
}

// ---------------- HMMA GEMM (3x bf16 split, fp32 acc, 3-stage pipe,
//                  register-double-buffered fragments) --------
#define KC 64
#define TILE_BYTES 16384            // 128 * 64 * 2B
#define STAGE_BYTES (4 * TILE_BYTES)
#define GEMM_SMEM (3 * STAGE_BYTES) // 196608

template <int EPI>
__global__ __launch_bounds__(256, 1)
void gemm_mma(const __nv_bfloat16* __restrict__ Wh, const __nv_bfloat16* __restrict__ Wl,
              const __nv_bfloat16* __restrict__ Xh, const __nv_bfloat16* __restrict__ Xl,
              float* __restrict__ out, const float* __restrict__ bias, int M,
              const float* __restrict__ Hprev)
{
    extern __shared__ char smem[];
    const uint32_t sb = smem_u32(smem);
    const int tid = threadIdx.x;
    const int wid = tid >> 5, lane = tid & 31;
    const int wm = wid >> 1, wn = wid & 1;
    const int n0 = blockIdx.x * 128;
    const int m0 = blockIdx.y * ((EPI == 2) ? 64 : 128);
    const int lr = lane & 7, lg = lane >> 3;

    float acc[2][8][4];
#pragma unroll
    for (int i = 0; i < 2; ++i)
#pragma unroll
        for (int j = 0; j < 8; ++j)
#pragma unroll
            for (int q = 0; q < 4; ++q) acc[i][j][q] = 0.f;

    auto load_chunk = [&](int kc, int st) {
        const uint32_t base = sb + st * STAGE_BYTES;
        const size_t gk = (size_t)kc * KC;
#pragma unroll
        for (int i = 0; i < 4; ++i) {
            int lin = i * 256 + tid;
            int row = lin >> 3, seg = lin & 7;
            uint32_t soff = row * 128 + (((seg ^ (row & 7))) << 4);
            int wrow;
            if (EPI == 2)
                wrow = ((row >> 4) & 1) * HD + m0 + (row >> 5) * 16 + (row & 15);
            else
                wrow = m0 + row;
            const size_t wgo = (size_t)wrow * HD + gk + seg * 8;
            const size_t xgo = (size_t)(n0 + row) * HD + gk + seg * 8;
            cp_async16(base + soff, Wh + wgo);
            cp_async16(base + TILE_BYTES + soff, Wl + wgo);
            cp_async16(base + 2 * TILE_BYTES + soff, Xh + xgo);
            cp_async16(base + 3 * TILE_BYTES + soff, Xl + xgo);
        }
        CP_COMMIT();
    };

    // fragment loader for one ks slice from stage base stg
    auto load_frags = [&](uint32_t stg, int ks,
                          uint32_t a[2][2][4], uint32_t b[2][4][4]) {
#pragma unroll
        for (int mi = 0; mi < 2; ++mi) {
            int arow = wm * 32 + mi * 16 + lr + (lg & 1) * 8;
            int aseg = ks * 2 + (lg >> 1);
            uint32_t off = arow * 128 + ((aseg ^ (arow & 7)) << 4);
            ldmx4(a[0][mi], stg + off);
            ldmx4(a[1][mi], stg + TILE_BYTES + off);
        }
#pragma unroll
        for (int g = 0; g < 4; ++g) {
            int brow = wn * 64 + g * 16 + lr + (lg >> 1) * 8;
            int bseg = ks * 2 + (lg & 1);
            uint32_t off = brow * 128 + ((bseg ^ (brow & 7)) << 4);
            ldmx4(b[0][g], stg + 2 * TILE_BYTES + off);
            ldmx4(b[1][g], stg + 3 * TILE_BYTES + off);
        }
    };

    load_chunk(0, 0);
    load_chunk(1, 1);

    uint32_t af[2][2][2][4];   // [buf][half][mi][reg]
    uint32_t bf[2][2][4][4];   // [buf][half][g][reg]

    const int NCH = HD / KC;  // 8
    for (int c = 0; c < NCH; ++c) {
        if (c < NCH - 1) { CP_WAIT(1); } else { CP_WAIT(0); }
        __syncthreads();
        if (c + 2 < NCH) load_chunk(c + 2, (c + 2) % 3);

        const uint32_t stg = sb + (c % 3) * STAGE_BYTES;
        load_frags(stg, 0, af[0], bf[0]);
#pragma unroll
        for (int ks = 0; ks < 4; ++ks) {
            const int cur = ks & 1;
            if (ks < 3)
                load_frags(stg, ks + 1, af[cur ^ 1], bf[cur ^ 1]);
#pragma unroll
            for (int mi = 0; mi < 2; ++mi)
#pragma unroll
                for (int j = 0; j < 8; ++j) {
                    const int g = j >> 1, p = (j & 1) * 2;
                    uint32_t bh[2] = {bf[cur][0][g][p], bf[cur][0][g][p + 1]};
                    uint32_t bl[2] = {bf[cur][1][g][p], bf[cur][1][g][p + 1]};
                    mma16816(acc[mi][j], af[cur][0][mi], bh);  // ah*bh
                    mma16816(acc[mi][j], af[cur][0][mi], bl);  // ah*bl (FIXED)
                    mma16816(acc[mi][j], af[cur][1][mi], bh);  // al*bh
                }
        }
    }

    // ---------------- epilogue ----------------
    if (EPI == 2) {
        const int m = m0 + wm * 16 + (lane >> 2);
        const float b10 = bias[m],      b18 = bias[m + 8];
        const float b20 = bias[HD + m], b28 = bias[HD + m + 8];
#pragma unroll
        for (int j = 0; j < 8; ++j) {
            const int n = n0 + wn * 64 + j * 8 + (lane & 3) * 2;
            const int bb = n >> 11;
            const int t = n & (LL - 1);
            float z10 = acc[0][j][0] + b10, z11 = acc[0][j][1] + b10;
            float z12 = acc[0][j][2] + b18, z13 = acc[0][j][3] + b18;
            float z20 = acc[1][j][0] + b20, z21 = acc[1][j][1] + b20;
            float z22 = acc[1][j][2] + b28, z23 = acc[1][j][3] + b28;
            const float2 p0 = *reinterpret_cast<const float2*>(
                Hprev + ((size_t)bb * HD + m) * LL + t);
            const float2 p1 = *reinterpret_cast<const float2*>(
                Hprev + ((size_t)bb * HD + m + 8) * LL + t);
            float2 v0, v1;
            v0.x = z10 / (1.f + expf(-z20)) + p0.x;
            v0.y = z11 / (1.f + expf(-z21)) + p0.y;
            v1.x = z12 / (1.f + expf(-z22)) + p1.x;
            v1.y = z13 / (1.f + expf(-z23)) + p1.y;
            *reinterpret_cast<float2*>(out + ((size_t)bb * HD + m) * LL + t) = v0;
            *reinterpret_cast<float2*>(out + ((size_t)bb * HD + m + 8) * LL + t) = v1;
        }
    } else {
#pragma unroll
        for (int mi = 0; mi < 2; ++mi) {
            const int mrow0 = m0 + wm * 32 + mi * 16 + (lane >> 2);
#pragma unroll
            for (int j = 0; j < 8; ++j) {
                const int n = n0 + wn * 64 + j * 8 + (lane & 3) * 2;
                const int bb = n >> 11;
                const int t = n & (LL - 1);
                float2 v0, v1;
                v0.x = fmaxf(acc[mi][j][0], 0.f);
                v0.y = fmaxf(acc[mi][j][1], 0.f);
                v1.x = fmaxf(acc[mi][j][2], 0.f);
                v1.y = fmaxf(acc[mi][j][3], 0.f);
                *reinterpret_cast<float2*>(out + ((size_t)bb * M + mrow0) * LL + t) = v0;
                *reinterpret_cast<float2*>(out + ((size_t)bb * M + mrow0 + 8) * LL + t) = v1;
            }
        }
    }
}

// ---------------- single-pass LayerNorm ----------------
// WRT==0: Hn = LN(V) fp32 (for next layer's scan)
// WRT==1: writes LN(V) directly as transposed bf16 hi/lo (decoder operands)
template <int WRT>
__global__ __launch_bounds__(256)
void ln_kernel(const float* __restrict__ V, float* __restrict__ Hn,
               __nv_bfloat16* __restrict__ dhi, __nv_bfloat16* __restrict__ dlo,
               const float* __restrict__ gamma, const float* __restrict__ beta)
{
    __shared__ float ssum[8][32];
    __shared__ float ssq[8][32];
    __shared__ __nv_bfloat16 hs[32][72];
    __shared__ __nv_bfloat16 ls[32][72];
    const int b = blockIdx.y;
    const int tx = threadIdx.x & 31;
    const int ty = threadIdx.x >> 5;          // 0..7
    const size_t t = (size_t)blockIdx.x * 32 + tx;
    const float* Vb = V + (size_t)b * HD * LL + t;
    float* Hb = Hn + (size_t)b * HD * LL + t;

    float vals[64];
    float s = 0.f, s2 = 0.f;
#pragma unroll
    for (int k = 0; k < 64; ++k) {
        const int c = k * 8 + ty;
        float v = Vb[(size_t)c * LL];
        vals[k] = v;
        s += v;
        s2 = fmaf(v, v, s2);
    }
    ssum[ty][tx] = s;
    ssq[ty][tx] = s2;
    __syncthreads();
    float st = 0.f, st2 = 0.f;
#pragma unroll
    for (int i = 0; i < 8; ++i) {
        st += ssum[i][tx];
        st2 += ssq[i][tx];
    }
    const float mu = st * (1.f / HD);
    const float var = st2 * (1.f / HD) - mu * mu;
    const float rstd = rsqrtf(var + 1e-5f);

    if (WRT == 0) {
#pragma unroll
        for (int k = 0; k < 64; ++k) {
            const int c = k * 8 + ty;
            Hb[(size_t)c * LL] = (vals[k] - mu) * rstd * gamma[c] + beta[c];
        }
    } else {
        const int tt = (int)(threadIdx.x >> 3), seg = (int)(threadIdx.x & 7);
        const size_t trow = ((size_t)b * LL + (size_t)blockIdx.x * 32 + tt) * HD;
#pragma unroll
        for (int kc = 0; kc < 8; ++kc) {
#pragma unroll
            for (int i = 0; i < 8; ++i) {
                const int k = kc * 8 + i;
                const int c = k * 8 + ty;
                float v = (vals[k] - mu) * rstd * gamma[c] + beta[c];
                __nv_bfloat16 h = __float2bfloat16(v);
                hs[tx][i * 8 + ty] = h;
                ls[tx][i * 8 + ty] = __float2bfloat16(v - __bfloat162float(h));
            }
            __syncthreads();
            *reinterpret_cast<uint4*>(dhi + trow + kc * 64 + seg * 8) =
                *reinterpret_cast<const uint4*>(&hs[tt][seg * 8]);
            *reinterpret_cast<uint4*>(dlo + trow + kc * 64 + seg * 8) =
                *reinterpret_cast<const uint4*>(&ls[tt][seg * 8]);
            __syncthreads();
        }
    }
}

// ---------------- SSM scan (scalar) -> bf16 hi/lo T ------
__global__ __launch_bounds__(256)
void ssm_scan_fused(const float* __restrict__ hbuf,
                    __nv_bfloat16* __restrict__ dhi,
                    __nv_bfloat16* __restrict__ dlo,
                    const float* __restrict__ wre, const float* __restrict__ wim,
                    const float* __restrict__ ccre, const float* __restrict__ ccim,
                    const float* __restrict__ Dv)
{
    __shared__ float tile[32][33];
    const int tid = threadIdx.x;
    const int q = tid & 7;
    const int g = tid >> 3;                 // 0..31
    const int grp0 = blockIdx.x * 32;
    const int grp = grp0 + g;
    const int b = grp >> 9;
    const int hh = grp & (HD - 1);
    const int h0 = grp0 & (HD - 1);
    const float* hrow = hbuf + (size_t)grp * LL;

    const int pbase = hh * NN + q * 4;
    float4 w_r = *reinterpret_cast<const float4*>(&wre[pbase]);
    float4 w_i = *reinterpret_cast<const float4*>(&wim[pbase]);
    float4 c_r = *reinterpret_cast<const float4*>(&ccre[pbase]);
    float4 c_i = *reinterpret_cast<const float4*>(&ccim[pbase]);
    float wr[4] = {w_r.x, w_r.y, w_r.z, w_r.w};
    float wi[4] = {w_i.x, w_i.y, w_i.z, w_i.w};
    float cr[4] = {c_r.x, c_r.y, c_r.z, c_r.w};
    float ci[4] = {c_i.x, c_i.y, c_i.z, c_i.w};
    const float Dh = Dv[hh];

    float sr[4] = {0.f, 0.f, 0.f, 0.f};
    float si[4] = {0.f, 0.f, 0.f, 0.f};

    const int tt = tid >> 3, seg = tid & 7;

    for (int t0 = 0; t0 < LL; t0 += 32) {
#pragma unroll
        for (int sub = 0; sub < 4; ++sub) {
            const int tb = t0 + sub * 8;
            const float4 ua = *reinterpret_cast<const float4*>(hrow + tb);
            const float4 ub = *reinterpret_cast<const float4*>(hrow + tb + 4);
            const float uu[8] = {ua.x, ua.y, ua.z, ua.w, ub.x, ub.y, ub.z, ub.w};
            float umine = 0.f, ykeep = 0.f;
#pragma unroll
            for (int j = 0; j < 8; ++j) {
                const float u = uu[j];
#pragma unroll
                for (int k = 0; k < 4; ++k) {
                    float nr = fmaf(wr[k], sr[k], u);
                    nr = fmaf(-wi[k], si[k], nr);
                    float ni = wr[k] * si[k];
                    ni = fmaf(wi[k], sr[k], ni);
                    sr[k] = nr;
                    si[k] = ni;
                }
                float acc = 0.f;
#pragma unroll
                for (int k = 0; k < 4; ++k) {
                    acc = fmaf(cr[k], sr[k], acc);
                    acc = fmaf(-ci[k], si[k], acc);
                }
                acc += __shfl_xor_sync(0xffffffffu, acc, 1);
                acc += __shfl_xor_sync(0xffffffffu, acc, 2);
                acc += __shfl_xor_sync(0xffffffffu, acc, 4);
                if (j == q) { umine = u; ykeep = acc; }
            }
            float yv = fmaf(Dh, umine, 2.f * ykeep);
            float gv = 0.5f * yv * (1.f + erff(yv * 0.70710678118654752f));
            tile[sub * 8 + q][g] = gv;
        }
        __syncthreads();
        {
            const int t = t0 + tt;
            float v0 = tile[tt][seg * 4 + 0];
            float v1 = tile[tt][seg * 4 + 1];
            float v2 = tile[tt][seg * 4 + 2];
            float v3 = tile[tt][seg * 4 + 3];
            __nv_bfloat16 hi4[4], lo4[4];
            hi4[0] = __float2bfloat16(v0);
            hi4[1] = __float2bfloat16(v1);
            hi4[2] = __float2bfloat16(v2);
            hi4[3] = __float2bfloat16(v3);
            lo4[0] = __float2bfloat16(v0 - __bfloat162float(hi4[0]));
            lo4[1] = __float2bfloat16(v1 - __bfloat162float(hi4[1]));
            lo4[2] = __float2bfloat16(v2 - __bfloat162float(hi4[2]));
            lo4[3] = __float2bfloat16(v3 - __bfloat162float(hi4[3]));
            const size_t o = ((size_t)b * LL + t) * HD + h0 + seg * 4;
            *reinterpret_cast<uint2*>(dhi + o) = *reinterpret_cast<uint2*>(hi4);
            *reinterpret_cast<uint2*>(dlo + o) = *reinterpret_cast<uint2*>(lo4);
        }
        __syncthreads();
    }
}

// ---------------- launch ----------------
extern "C" void kernel_launch(void* const* d_in, const int* in_sizes, int n_in,
                              void* d_out, int out_size)
{
    const float* x = (const float*)d_in[0];
    const float* W_enc = (const float*)d_in[1];
    const float* W_dec = (const float*)d_in[2];
    const float* log_dt = (const float*)d_in[3];
    const float* log_A_real = (const float*)d_in[4];
    const float* A_imag = (const float*)d_in[5];
    const float* C_re = (const float*)d_in[6];
    const float* C_im = (const float*)d_in[7];
    const float* Dv = (const float*)d_in[8];
    const float* W_out = (const float*)d_in[9];
    const float* b_out = (const float*)d_in[10];
    const float* ln_g = (const float*)d_in[11];
    const float* ln_b = (const float*)d_in[12];
    float* out = (float*)d_out;

    float *pH, *pV, *pwre, *pwim, *pcre, *pcim;
    __nv_bfloat16 *pBth, *pBtl, *pWh, *pWl;
    cudaGetSymbolAddress((void**)&pH, g_H);
    cudaGetSymbolAddress((void**)&pV, g_V);
    cudaGetSymbolAddress((void**)&pwre, g_wre);
    cudaGetSymbolAddress((void**)&pwim, g_wim);
    cudaGetSymbolAddress((void**)&pcre, g_cre);
    cudaGetSymbolAddress((void**)&pcim, g_cim);
    cudaGetSymbolAddress((void**)&pBth, g_Bth);
    cudaGetSymbolAddress((void**)&pBtl, g_Btl);
    cudaGetSymbolAddress((void**)&pWh, g_Wh);
    cudaGetSymbolAddress((void**)&pWl, g_Wl);

    cudaFuncSetAttribute(gemm_mma<0>, cudaFuncAttributeMaxDynamicSharedMemorySize, GEMM_SMEM);
    cudaFuncSetAttribute(gemm_mma<2>, cudaFuncAttributeMaxDynamicSharedMemorySize, GEMM_SMEM);

    precompute_kernel<<<(NL * HD * NN + 255) / 256, 256>>>(log_dt, log_A_real,
                                                           A_imag, C_re, C_im);
    split_w_all<<<(W_ELEMS + 255) / 256, 256>>>(W_enc, W_out, W_dec, pWh, pWl);

    const dim3 tgrid(LL / 32, HD / 32, BQ);

    // encoder: H = relu(W_enc @ quant(x))
    transpose_split_kernel<true><<<tgrid, 256>>>(x, pBth, pBtl);
    gemm_mma<0><<<dim3(NTOT / 128, HD / 128), 256, GEMM_SMEM>>>(
        pWh + W_ENC_OFF, pWl + W_ENC_OFF, pBth, pBtl, pH, nullptr, HD, nullptr);

    for (int l = 0; l < NL; ++l) {
        const int po = l * HD * NN;
        // scan(H) + gelu -> transposed bf16 hi/lo
        ssm_scan_fused<<<(BQ * HD) / 32, 256>>>(
            pH, pBth, pBtl, pwre + po, pwim + po, pcre + po, pcim + po,
            Dv + l * HD);
        // fused GLU + residual: V = glu(z) + H
        gemm_mma<2><<<dim3(NTOT / 128, HD / 64), 256, GEMM_SMEM>>>(
            pWh + W_OUT_OFF + (size_t)l * 2 * HD * HD,
            pWl + W_OUT_OFF + (size_t)l * 2 * HD * HD,
            pBth, pBtl, pV, b_out + l * 2 * HD, HD, pH);
        // H = LN(V); last layer writes decoder operands directly
        if (l < NL - 1)
            ln_kernel<0><<<dim3(LL / 32, BQ), 256>>>(pV, pH, nullptr, nullptr,
                                                     ln_g + l * HD, ln_b + l * HD);
        else
            ln_kernel<1><<<dim3(LL / 32, BQ), 256>>>(pV, nullptr, pBth, pBtl,
                                                     ln_g + l * HD, ln_b + l * HD);
    }

    // decoder: out = relu(W_dec @ LN(V3))
    gemm_mma<0><<<dim3(NTOT / 128, HD / 128), 256, GEMM_SMEM>>>(
        pWh + W_DEC_OFF, pWl + W_DEC_OFF, pBth, pBtl, out, nullptr, HD, nullptr);
}

// round 13
// speedup vs baseline: 1.0450x; 1.0116x over previous
#include <cuda_runtime.h>
#include <cuda_bf16.h>
#include <stdint.h>
#include <math.h>

#define BQ 16
#define HD 512
#define LL 2048
#define NL 4
#define NN 32
#define NTOT (BQ * LL)  // 32768 total columns

// ---------------- scratch (static __device__, no allocs) ----------------
__device__ float g_H[(size_t)BQ * HD * LL];          // normalized stream Hn
__device__ float g_V[(size_t)BQ * HD * LL];          // pre-norm V scratch
__device__ __nv_bfloat16 g_Bth[(size_t)NTOT * HD];   // activations (n,k) hi
__device__ __nv_bfloat16 g_Btl[(size_t)NTOT * HD];   // activations (n,k) lo
#define W_ENC_OFF 0
#define W_OUT_OFF (HD * HD)
#define W_DEC_OFF (HD * HD + NL * 2 * HD * HD)
#define W_ELEMS (2 * HD * HD + NL * 2 * HD * HD)
__device__ __nv_bfloat16 g_Wh[W_ELEMS];
__device__ __nv_bfloat16 g_Wl[W_ELEMS];
__device__ float g_wre[NL * HD * NN];
__device__ float g_wim[NL * HD * NN];
__device__ float g_cre[NL * HD * NN];
__device__ float g_cim[NL * HD * NN];

// ---------------- helpers ----------------
__device__ __forceinline__ uint32_t smem_u32(const void* p)
{
    uint32_t a;
    asm("{ .reg .u64 t; cvta.to.shared.u64 t, %1; cvt.u32.u64 %0, t; }"
        : "=r"(a) : "l"(p));
    return a;
}

__device__ __forceinline__ void cp_async16(uint32_t dst, const void* src)
{
    asm volatile("cp.async.cg.shared.global [%0], [%1], 16;" :: "r"(dst), "l"(src));
}
#define CP_COMMIT() asm volatile("cp.async.commit_group;" ::: "memory")
#define CP_WAIT(n)  asm volatile("cp.async.wait_group %0;" :: "n"(n) : "memory")

__device__ __forceinline__ void ldmx4(uint32_t* r, uint32_t addr)
{
    asm volatile("ldmatrix.sync.aligned.m8n8.x4.shared.b16 {%0,%1,%2,%3}, [%4];"
                 : "=r"(r[0]), "=r"(r[1]), "=r"(r[2]), "=r"(r[3]) : "r"(addr));
}

__device__ __forceinline__ void mma16816(float* c, const uint32_t* a,
                                         const uint32_t* b)
{
    asm volatile(
        "mma.sync.aligned.m16n8k16.row.col.f32.bf16.bf16.f32 "
        "{%0,%1,%2,%3}, {%4,%5,%6,%7}, {%8,%9}, {%0,%1,%2,%3};"
        : "+f"(c[0]), "+f"(c[1]), "+f"(c[2]), "+f"(c[3])
        : "r"(a[0]), "r"(a[1]), "r"(a[2]), "r"(a[3]), "r"(b[0]), "r"(b[1]));
}

// ---------------- parameter precompute ----------------
__global__ __launch_bounds__(256)
void precompute_kernel(const float* __restrict__ log_dt,
                       const float* __restrict__ log_A_real,
                       const float* __restrict__ A_imag,
                       const float* __restrict__ C_re,
                       const float* __restrict__ C_im)
{
    int idx = blockIdx.x * 256 + threadIdx.x;
    if (idx >= NL * HD * NN) return;
    int h = (idx >> 5) & (HD - 1);
    int l = idx >> 14;
    float dt = expf(log_dt[l * HD + h]);
    float a = -expf(log_A_real[idx]);
    float b = A_imag[idx];
    float xr = dt * a, xi = dt * b;
    float er = expf(xr);
    float c = cosf(xi), s = sinf(xi);
    g_wre[idx] = er * c;
    g_wim[idx] = er * s;
    float sh = sinf(0.5f * xi);
    float Ere = expm1f(xr) * c - 2.f * sh * sh;
    float Eim = er * s;
    float den = a * a + b * b;
    float Fre = (Ere * a + Eim * b) / den;
    float Fim = (Eim * a - Ere * b) / den;
    float cr = C_re[idx], ci = C_im[idx];
    g_cre[idx] = cr * Fre - ci * Fim;
    g_cim[idx] = cr * Fim + ci * Fre;
}

// ---------------- weight split fp32 -> bf16 hi/lo (all weights, one launch) ----
__global__ __launch_bounds__(256)
void split_w_all(const float* __restrict__ W_enc, const float* __restrict__ W_out,
                 const float* __restrict__ W_dec,
                 __nv_bfloat16* __restrict__ hi, __nv_bfloat16* __restrict__ lo)
{
    int i = blockIdx.x * 256 + threadIdx.x;
    if (i >= W_ELEMS) return;
    float v;
    if (i < W_OUT_OFF) v = W_enc[i];
    else if (i < W_DEC_OFF) v = W_out[i - W_OUT_OFF];
    else v = W_dec[i - W_DEC_OFF];
    __nv_bfloat16 h = __float2bfloat16(v);
    hi[i] = h;
    lo[i] = __float2bfloat16(v - __bfloat162float(h));
}

// ---------------- transpose + split (+opt quant) ----------
template <bool QUANT>
__global__ __launch_bounds__(256)
void transpose_split_kernel(const float* __restrict__ src,
                            __nv_bfloat16* __restrict__ dhi,
                            __nv_bfloat16* __restrict__ dlo)
{
    __shared__ float tile[32][33];
    const int b = blockIdx.z;
    const int c0 = blockIdx.y * 32;
    const int t0 = blockIdx.x * 32;
    const int tx = threadIdx.x & 31, ty = threadIdx.x >> 5;
#pragma unroll
    for (int i = 0; i < 32; i += 8) {
        float v = src[((size_t)b * HD + c0 + ty + i) * LL + t0 + tx];
        if (QUANT) v = rintf(v * 64.f) * 0.015625f;
        tile[ty + i][tx] = v;
    }
    __syncthreads();
#pragma unroll
    for (int i = 0; i < 32; i += 8) {
        int t = t0 + ty + i;
        int c = c0 + tx;
        float v = tile[tx][ty + i];
        __nv_bfloat16 h = __float2bfloat16(v);
        size_t o = ((size_t)b * LL + t) * HD + c;
        dhi[o] = h;
        dlo[o] = __float2bfloat16(v - __bfloat162float(h));
    }
}

// ---------------- HMMA GEMM (3x bf16 split, fp32 acc, 3-stage pipe,
//                  512 threads: 4x4 warps, each 32x32) --------
#define KC 64
#define TILE_BYTES 16384            // 128 * 64 * 2B
#define STAGE_BYTES (4 * TILE_BYTES)
#define GEMM_SMEM (3 * STAGE_BYTES) // 196608
#define GTHREADS 512

template <int EPI>
__global__ __launch_bounds__(GTHREADS, 1)
void gemm_mma(const __nv_bfloat16* __restrict__ Wh, const __nv_bfloat16* __restrict__ Wl,
              const __nv_bfloat16* __restrict__ Xh, const __nv_bfloat16* __restrict__ Xl,
              float* __restrict__ out, const float* __restrict__ bias, int M,
              const float* __restrict__ Hprev)
{
    extern __shared__ char smem[];
    const uint32_t sb = smem_u32(smem);
    const int tid = threadIdx.x;
    const int wid = tid >> 5, lane = tid & 31;
    const int wm = wid >> 2, wn = wid & 3;        // 4x4 warp grid
    const int n0 = blockIdx.x * 128;
    const int m0 = blockIdx.y * ((EPI == 2) ? 64 : 128);
    const int lr = lane & 7, lg = lane >> 3;

    float acc[2][4][4];
#pragma unroll
    for (int i = 0; i < 2; ++i)
#pragma unroll
        for (int j = 0; j < 4; ++j)
#pragma unroll
            for (int q = 0; q < 4; ++q) acc[i][j][q] = 0.f;

    auto load_chunk = [&](int kc, int st) {
        const uint32_t base = sb + st * STAGE_BYTES;
        const size_t gk = (size_t)kc * KC;
#pragma unroll
        for (int i = 0; i < 2; ++i) {
            int lin = i * GTHREADS + tid;
            int row = lin >> 3, seg = lin & 7;
            uint32_t soff = row * 128 + (((seg ^ (row & 7))) << 4);
            int wrow;
            if (EPI == 2)
                wrow = ((row >> 4) & 1) * HD + m0 + (row >> 5) * 16 + (row & 15);
            else
                wrow = m0 + row;
            const size_t wgo = (size_t)wrow * HD + gk + seg * 8;
            const size_t xgo = (size_t)(n0 + row) * HD + gk + seg * 8;
            cp_async16(base + soff, Wh + wgo);
            cp_async16(base + TILE_BYTES + soff, Wl + wgo);
            cp_async16(base + 2 * TILE_BYTES + soff, Xh + xgo);
            cp_async16(base + 3 * TILE_BYTES + soff, Xl + xgo);
        }
        CP_COMMIT();
    };

    load_chunk(0, 0);
    load_chunk(1, 1);

    const int NCH = HD / KC;  // 8
    for (int c = 0; c < NCH; ++c) {
        if (c < NCH - 1) { CP_WAIT(1); } else { CP_WAIT(0); }
        __syncthreads();
        if (c + 2 < NCH) load_chunk(c + 2, (c + 2) % 3);

        const uint32_t stg = sb + (c % 3) * STAGE_BYTES;
#pragma unroll
        for (int ks = 0; ks < 4; ++ks) {
            uint32_t a[2][2][4];   // [half][mi][reg]
            uint32_t b[2][2][4];   // [half][g][reg]
#pragma unroll
            for (int mi = 0; mi < 2; ++mi) {
                int arow = wm * 32 + mi * 16 + lr + (lg & 1) * 8;
                int aseg = ks * 2 + (lg >> 1);
                uint32_t off = arow * 128 + ((aseg ^ (arow & 7)) << 4);
                ldmx4(a[0][mi], stg + off);
                ldmx4(a[1][mi], stg + TILE_BYTES + off);
            }
#pragma unroll
            for (int g = 0; g < 2; ++g) {
                int brow = wn * 32 + g * 16 + lr + (lg >> 1) * 8;
                int bseg = ks * 2 + (lg & 1);
                uint32_t off = brow * 128 + ((bseg ^ (brow & 7)) << 4);
                ldmx4(b[0][g], stg + 2 * TILE_BYTES + off);
                ldmx4(b[1][g], stg + 3 * TILE_BYTES + off);
            }
#pragma unroll
            for (int mi = 0; mi < 2; ++mi)
#pragma unroll
                for (int j = 0; j < 4; ++j) {
                    const int g = j >> 1, p = (j & 1) * 2;
                    uint32_t bh[2] = {b[0][g][p], b[0][g][p + 1]};
                    uint32_t bl[2] = {b[1][g][p], b[1][g][p + 1]};
                    mma16816(acc[mi][j], a[0][mi], bh);  // ah*bh
                    mma16816(acc[mi][j], a[0][mi], bl);  // ah*bl
                    mma16816(acc[mi][j], a[1][mi], bh);  // al*bh
                }
        }
    }

    // ---------------- epilogue ----------------
    if (EPI == 2) {
        const int m = m0 + wm * 16 + (lane >> 2);
        const float b1 = bias[m];
        const float b2 = bias[HD + m];
#pragma unroll
        for (int j = 0; j < 4; ++j) {
            const int n = n0 + wn * 32 + j * 8 + (lane & 3) * 2;
            const int bb = n >> 11;
            const int t = n & (LL - 1);
            float z10 = acc[0][j][0] + b1, z11 = acc[0][j][1] + b1;
            float z20 = acc[1][j][0] + b2, z21 = acc[1][j][1] + b2;
            const int m8 = m + 8;
            const float b18 = bias[m8];
            const float b28 = bias[HD + m8];
            float z12 = acc[0][j][2] + b18, z13 = acc[0][j][3] + b18;
            float z22 = acc[1][j][2] + b28, z23 = acc[1][j][3] + b28;
            const float2 p0 = *reinterpret_cast<const float2*>(
                Hprev + ((size_t)bb * HD + m) * LL + t);
            const float2 p1 = *reinterpret_cast<const float2*>(
                Hprev + ((size_t)bb * HD + m8) * LL + t);
            float2 v0, v1;
            v0.x = z10 / (1.f + expf(-z20)) + p0.x;
            v0.y = z11 / (1.f + expf(-z21)) + p0.y;
            v1.x = z12 / (1.f + expf(-z22)) + p1.x;
            v1.y = z13 / (1.f + expf(-z23)) + p1.y;
            *reinterpret_cast<float2*>(out + ((size_t)bb * HD + m) * LL + t) = v0;
            *reinterpret_cast<float2*>(out + ((size_t)bb * HD + m8) * LL + t) = v1;
        }
    } else {
#pragma unroll
        for (int mi = 0; mi < 2; ++mi) {
            const int mrow0 = m0 + wm * 32 + mi * 16 + (lane >> 2);
#pragma unroll
            for (int j = 0; j < 4; ++j) {
                const int n = n0 + wn * 32 + j * 8 + (lane & 3) * 2;
                const int bb = n >> 11;
                const int t = n & (LL - 1);
                float2 v0, v1;
                v0.x = fmaxf(acc[mi][j][0], 0.f);
                v0.y = fmaxf(acc[mi][j][1], 0.f);
                v1.x = fmaxf(acc[mi][j][2], 0.f);
                v1.y = fmaxf(acc[mi][j][3], 0.f);
                *reinterpret_cast<float2*>(out + ((size_t)bb * M + mrow0) * LL + t) = v0;
                *reinterpret_cast<float2*>(out + ((size_t)bb * M + mrow0 + 8) * LL + t) = v1;
            }
        }
    }
}

// ---------------- single-pass LayerNorm ----------------
// WRT==0: Hn = LN(V) fp32 (for next layer's scan)
// WRT==1: writes LN(V) directly as transposed bf16 hi/lo (decoder operands)
template <int WRT>
__global__ __launch_bounds__(256)
void ln_kernel(const float* __restrict__ V, float* __restrict__ Hn,
               __nv_bfloat16* __restrict__ dhi, __nv_bfloat16* __restrict__ dlo,
               const float* __restrict__ gamma, const float* __restrict__ beta)
{
    __shared__ float ssum[8][32];
    __shared__ float ssq[8][32];
    __shared__ __nv_bfloat16 hs[32][72];
    __shared__ __nv_bfloat16 ls[32][72];
    const int b = blockIdx.y;
    const int tx = threadIdx.x & 31;
    const int ty = threadIdx.x >> 5;          // 0..7
    const size_t t = (size_t)blockIdx.x * 32 + tx;
    const float* Vb = V + (size_t)b * HD * LL + t;
    float* Hb = Hn + (size_t)b * HD * LL + t;

    float vals[64];
    float s = 0.f, s2 = 0.f;
#pragma unroll
    for (int k = 0; k < 64; ++k) {
        const int c = k * 8 + ty;
        float v = Vb[(size_t)c * LL];
        vals[k] = v;
        s += v;
        s2 = fmaf(v, v, s2);
    }
    ssum[ty][tx] = s;
    ssq[ty][tx] = s2;
    __syncthreads();
    float st = 0.f, st2 = 0.f;
#pragma unroll
    for (int i = 0; i < 8; ++i) {
        st += ssum[i][tx];
        st2 += ssq[i][tx];
    }
    const float mu = st * (1.f / HD);
    const float var = st2 * (1.f / HD) - mu * mu;
    const float rstd = rsqrtf(var + 1e-5f);

    if (WRT == 0) {
#pragma unroll
        for (int k = 0; k < 64; ++k) {
            const int c = k * 8 + ty;
            Hb[(size_t)c * LL] = (vals[k] - mu) * rstd * gamma[c] + beta[c];
        }
    } else {
        const int tt = (int)(threadIdx.x >> 3), seg = (int)(threadIdx.x & 7);
        const size_t trow = ((size_t)b * LL + (size_t)blockIdx.x * 32 + tt) * HD;
#pragma unroll
        for (int kc = 0; kc < 8; ++kc) {
#pragma unroll
            for (int i = 0; i < 8; ++i) {
                const int k = kc * 8 + i;
                const int c = k * 8 + ty;
                float v = (vals[k] - mu) * rstd * gamma[c] + beta[c];
                __nv_bfloat16 h = __float2bfloat16(v);
                hs[tx][i * 8 + ty] = h;
                ls[tx][i * 8 + ty] = __float2bfloat16(v - __bfloat162float(h));
            }
            __syncthreads();
            *reinterpret_cast<uint4*>(dhi + trow + kc * 64 + seg * 8) =
                *reinterpret_cast<const uint4*>(&hs[tt][seg * 8]);
            *reinterpret_cast<uint4*>(dlo + trow + kc * 64 + seg * 8) =
                *reinterpret_cast<const uint4*>(&ls[tt][seg * 8]);
            __syncthreads();
        }
    }
}

// ---------------- SSM scan (scalar) -> bf16 hi/lo T ------
__global__ __launch_bounds__(256)
void ssm_scan_fused(const float* __restrict__ hbuf,
                    __nv_bfloat16* __restrict__ dhi,
                    __nv_bfloat16* __restrict__ dlo,
                    const float* __restrict__ wre, const float* __restrict__ wim,
                    const float* __restrict__ ccre, const float* __restrict__ ccim,
                    const float* __restrict__ Dv)
{
    __shared__ float tile[32][33];
    const int tid = threadIdx.x;
    const int q = tid & 7;
    const int g = tid >> 3;                 // 0..31
    const int grp0 = blockIdx.x * 32;
    const int grp = grp0 + g;
    const int b = grp >> 9;
    const int hh = grp & (HD - 1);
    const int h0 = grp0 & (HD - 1);
    const float* hrow = hbuf + (size_t)grp * LL;

    const int pbase = hh * NN + q * 4;
    float4 w_r = *reinterpret_cast<const float4*>(&wre[pbase]);
    float4 w_i = *reinterpret_cast<const float4*>(&wim[pbase]);
    float4 c_r = *reinterpret_cast<const float4*>(&ccre[pbase]);
    float4 c_i = *reinterpret_cast<const float4*>(&ccim[pbase]);
    float wr[4] = {w_r.x, w_r.y, w_r.z, w_r.w};
    float wi[4] = {w_i.x, w_i.y, w_i.z, w_i.w};
    float cr[4] = {c_r.x, c_r.y, c_r.z, c_r.w};
    float ci[4] = {c_i.x, c_i.y, c_i.z, c_i.w};
    const float Dh = Dv[hh];

    float sr[4] = {0.f, 0.f, 0.f, 0.f};
    float si[4] = {0.f, 0.f, 0.f, 0.f};

    const int tt = tid >> 3, seg = tid & 7;

    for (int t0 = 0; t0 < LL; t0 += 32) {
#pragma unroll
        for (int sub = 0; sub < 4; ++sub) {
            const int tb = t0 + sub * 8;
            const float4 ua = *reinterpret_cast<const float4*>(hrow + tb);
            const float4 ub = *reinterpret_cast<const float4*>(hrow + tb + 4);
            const float uu[8] = {ua.x, ua.y, ua.z, ua.w, ub.x, ub.y, ub.z, ub.w};
            float umine = 0.f, ykeep = 0.f;
#pragma unroll
            for (int j = 0; j < 8; ++j) {
                const float u = uu[j];
#pragma unroll
                for (int k = 0; k < 4; ++k) {
                    float nr = fmaf(wr[k], sr[k], u);
                    nr = fmaf(-wi[k], si[k], nr);
                    float ni = wr[k] * si[k];
                    ni = fmaf(wi[k], sr[k], ni);
                    sr[k] = nr;
                    si[k] = ni;
                }
                float acc = 0.f;
#pragma unroll
                for (int k = 0; k < 4; ++k) {
                    acc = fmaf(cr[k], sr[k], acc);
                    acc = fmaf(-ci[k], si[k], acc);
                }
                acc += __shfl_xor_sync(0xffffffffu, acc, 1);
                acc += __shfl_xor_sync(0xffffffffu, acc, 2);
                acc += __shfl_xor_sync(0xffffffffu, acc, 4);
                if (j == q) { umine = u; ykeep = acc; }
            }
            float yv = fmaf(Dh, umine, 2.f * ykeep);
            float gv = 0.5f * yv * (1.f + erff(yv * 0.70710678118654752f));
            tile[sub * 8 + q][g] = gv;
        }
        __syncthreads();
        {
            const int t = t0 + tt;
            float v0 = tile[tt][seg * 4 + 0];
            float v1 = tile[tt][seg * 4 + 1];
            float v2 = tile[tt][seg * 4 + 2];
            float v3 = tile[tt][seg * 4 + 3];
            __nv_bfloat16 hi4[4], lo4[4];
            hi4[0] = __float2bfloat16(v0);
            hi4[1] = __float2bfloat16(v1);
            hi4[2] = __float2bfloat16(v2);
            hi4[3] = __float2bfloat16(v3);
            lo4[0] = __float2bfloat16(v0 - __bfloat162float(hi4[0]));
            lo4[1] = __float2bfloat16(v1 - __bfloat162float(hi4[1]));
            lo4[2] = __float2bfloat16(v2 - __bfloat162float(hi4[2]));
            lo4[3] = __float2bfloat16(v3 - __bfloat162float(hi4[3]));
            const size_t o = ((size_t)b * LL + t) * HD + h0 + seg * 4;
            *reinterpret_cast<uint2*>(dhi + o) = *reinterpret_cast<uint2*>(hi4);
            *reinterpret_cast<uint2*>(dlo + o) = *reinterpret_cast<uint2*>(lo4);
        }
        __syncthreads();
    }
}

// ---------------- launch ----------------
extern "C" void kernel_launch(void* const* d_in, const int* in_sizes, int n_in,
                              void* d_out, int out_size)
{
    const float* x = (const float*)d_in[0];
    const float* W_enc = (const float*)d_in[1];
    const float* W_dec = (const float*)d_in[2];
    const float* log_dt = (const float*)d_in[3];
    const float* log_A_real = (const float*)d_in[4];
    const float* A_imag = (const float*)d_in[5];
    const float* C_re = (const float*)d_in[6];
    const float* C_im = (const float*)d_in[7];
    const float* Dv = (const float*)d_in[8];
    const float* W_out = (const float*)d_in[9];
    const float* b_out = (const float*)d_in[10];
    const float* ln_g = (const float*)d_in[11];
    const float* ln_b = (const float*)d_in[12];
    float* out = (float*)d_out;

    float *pH, *pV, *pwre, *pwim, *pcre, *pcim;
    __nv_bfloat16 *pBth, *pBtl, *pWh, *pWl;
    cudaGetSymbolAddress((void**)&pH, g_H);
    cudaGetSymbolAddress((void**)&pV, g_V);
    cudaGetSymbolAddress((void**)&pwre, g_wre);
    cudaGetSymbolAddress((void**)&pwim, g_wim);
    cudaGetSymbolAddress((void**)&pcre, g_cre);
    cudaGetSymbolAddress((void**)&pcim, g_cim);
    cudaGetSymbolAddress((void**)&pBth, g_Bth);
    cudaGetSymbolAddress((void**)&pBtl, g_Btl);
    cudaGetSymbolAddress((void**)&pWh, g_Wh);
    cudaGetSymbolAddress((void**)&pWl, g_Wl);

    cudaFuncSetAttribute(gemm_mma<0>, cudaFuncAttributeMaxDynamicSharedMemorySize, GEMM_SMEM);
    cudaFuncSetAttribute(gemm_mma<2>, cudaFuncAttributeMaxDynamicSharedMemorySize, GEMM_SMEM);

    precompute_kernel<<<(NL * HD * NN + 255) / 256, 256>>>(log_dt, log_A_real,
                                                           A_imag, C_re, C_im);
    split_w_all<<<(W_ELEMS + 255) / 256, 256>>>(W_enc, W_out, W_dec, pWh, pWl);

    const dim3 tgrid(LL / 32, HD / 32, BQ);

    // encoder: H = relu(W_enc @ quant(x))
    transpose_split_kernel<true><<<tgrid, 256>>>(x, pBth, pBtl);
    gemm_mma<0><<<dim3(NTOT / 128, HD / 128), GTHREADS, GEMM_SMEM>>>(
        pWh + W_ENC_OFF, pWl + W_ENC_OFF, pBth, pBtl, pH, nullptr, HD, nullptr);

    for (int l = 0; l < NL; ++l) {
        const int po = l * HD * NN;
        // scan(H) + gelu -> transposed bf16 hi/lo
        ssm_scan_fused<<<(BQ * HD) / 32, 256>>>(
            pH, pBth, pBtl, pwre + po, pwim + po, pcre + po, pcim + po,
            Dv + l * HD);
        // fused GLU + residual: V = glu(z) + H
        gemm_mma<2><<<dim3(NTOT / 128, HD / 64), GTHREADS, GEMM_SMEM>>>(
            pWh + W_OUT_OFF + (size_t)l * 2 * HD * HD,
            pWl + W_OUT_OFF + (size_t)l * 2 * HD * HD,
            pBth, pBtl, pV, b_out + l * 2 * HD, HD, pH);
        // H = LN(V); last layer writes decoder operands directly
        if (l < NL - 1)
            ln_kernel<0><<<dim3(LL / 32, BQ), 256>>>(pV, pH, nullptr, nullptr,
                                                     ln_g + l * HD, ln_b + l * HD);
        else
            ln_kernel<1><<<dim3(LL / 32, BQ), 256>>>(pV, nullptr, pBth, pBtl,
                                                     ln_g + l * HD, ln_b + l * HD);
    }

    // decoder: out = relu(W_dec @ LN(V3))
    gemm_mma<0><<<dim3(NTOT / 128, HD / 128), GTHREADS, GEMM_SMEM>>>(
        pWh + W_DEC_OFF, pWl + W_DEC_OFF, pBth, pBtl, out, nullptr, HD, nullptr);
}

// round 15
// speedup vs baseline: 1.1020x; 1.0545x over previous
#include <cuda_runtime.h>
#include <cuda_bf16.h>
#include <stdint.h>
#include <math.h>

#define BQ 16
#define HD 512
#define LL 2048
#define NL 4
#define NN 32
#define NTOT (BQ * LL)  // 32768 total columns

// ---------------- scratch (static __device__, no allocs) ----------------
__device__ float g_H[(size_t)BQ * HD * LL];          // normalized stream Hn
__device__ float g_V[(size_t)BQ * HD * LL];          // pre-norm V scratch
__device__ __nv_bfloat16 g_Bth[(size_t)NTOT * HD];   // activations (n,k) hi
__device__ __nv_bfloat16 g_Btl[(size_t)NTOT * HD];   // activations (n,k) lo
#define W_ENC_OFF 0
#define W_OUT_OFF (HD * HD)
#define W_DEC_OFF (HD * HD + NL * 2 * HD * HD)
#define W_ELEMS (2 * HD * HD + NL * 2 * HD * HD)
__device__ __nv_bfloat16 g_Wh[W_ELEMS];
__device__ __nv_bfloat16 g_Wl[W_ELEMS];
__device__ float g_wre[NL * HD * NN];
__device__ float g_wim[NL * HD * NN];
__device__ float g_cre[NL * HD * NN];
__device__ float g_cim[NL * HD * NN];

// ---------------- helpers ----------------
__device__ __forceinline__ uint32_t smem_u32(const void* p)
{
    uint32_t a;
    asm("{ .reg .u64 t; cvta.to.shared.u64 t, %1; cvt.u32.u64 %0, t; }"
        : "=r"(a) : "l"(p));
    return a;
}

__device__ __forceinline__ void cp_async16(uint32_t dst, const void* src)
{
    asm volatile("cp.async.cg.shared.global [%0], [%1], 16;" :: "r"(dst), "l"(src));
}
#define CP_COMMIT() asm volatile("cp.async.commit_group;" ::: "memory")
#define CP_WAIT(n)  asm volatile("cp.async.wait_group %0;" :: "n"(n) : "memory")

__device__ __forceinline__ void ldmx4(uint32_t* r, uint32_t addr)
{
    asm volatile("ldmatrix.sync.aligned.m8n8.x4.shared.b16 {%0,%1,%2,%3}, [%4];"
                 : "=r"(r[0]), "=r"(r[1]), "=r"(r[2]), "=r"(r[3]) : "r"(addr));
}

__device__ __forceinline__ void mma16816(float* c, const uint32_t* a,
                                         const uint32_t* b)
{
    asm volatile(
        "mma.sync.aligned.m16n8k16.row.col.f32.bf16.bf16.f32 "
        "{%0,%1,%2,%3}, {%4,%5,%6,%7}, {%8,%9}, {%0,%1,%2,%3};"
        : "+f"(c[0]), "+f"(c[1]), "+f"(c[2]), "+f"(c[3])
        : "r"(a[0]), "r"(a[1]), "r"(a[2]), "r"(a[3]), "r"(b[0]), "r"(b[1]));
}

// ---------------- parameter precompute ----------------
__global__ __launch_bounds__(256)
void precompute_kernel(const float* __restrict__ log_dt,
                       const float* __restrict__ log_A_real,
                       const float* __restrict__ A_imag,
                       const float* __restrict__ C_re,
                       const float* __restrict__ C_im)
{
    int idx = blockIdx.x * 256 + threadIdx.x;
    if (idx >= NL * HD * NN) return;
    int h = (idx >> 5) & (HD - 1);
    int l = idx >> 14;
    float dt = expf(log_dt[l * HD + h]);
    float a = -expf(log_A_real[idx]);
    float b = A_imag[idx];
    float xr = dt * a, xi = dt * b;
    float er = expf(xr);
    float c = cosf(xi), s = sinf(xi);
    g_wre[idx] = er * c;
    g_wim[idx] = er * s;
    float sh = sinf(0.5f * xi);
    float Ere = expm1f(xr) * c - 2.f * sh * sh;
    float Eim = er * s;
    float den = a * a + b * b;
    float Fre = (Ere * a + Eim * b) / den;
    float Fim = (Eim * a - Ere * b) / den;
    float cr = C_re[idx], ci = C_im[idx];
    g_cre[idx] = cr * Fre - ci * Fim;
    g_cim[idx] = cr * Fim + ci * Fre;
}

// ---------------- weight split fp32 -> bf16 hi/lo (all weights, one launch) ----
__global__ __launch_bounds__(256)
void split_w_all(const float* __restrict__ W_enc, const float* __restrict__ W_out,
                 const float* __restrict__ W_dec,
                 __nv_bfloat16* __restrict__ hi, __nv_bfloat16* __restrict__ lo)
{
    int i = blockIdx.x * 256 + threadIdx.x;
    if (i >= W_ELEMS) return;
    float v;
    if (i < W_OUT_OFF) v = W_enc[i];
    else if (i < W_DEC_OFF) v = W_out[i - W_OUT_OFF];
    else v = W_dec[i - W_DEC_OFF];
    __nv_bfloat16 h = __float2bfloat16(v);
    hi[i] = h;
    lo[i] = __float2bfloat16(v - __bfloat162float(h));
}

// ---------------- transpose + split (+opt quant) ----------
template <bool QUANT>
__global__ __launch_bounds__(256)
void transpose_split_kernel(const float* __restrict__ src,
                            __nv_bfloat16* __restrict__ dhi,
                            __nv_bfloat16* __restrict__ dlo)
{
    __shared__ float tile[32][33];
    const int b = blockIdx.z;
    const int c0 = blockIdx.y * 32;
    const int t0 = blockIdx.x * 32;
    const int tx = threadIdx.x & 31, ty = threadIdx.x >> 5;
#pragma unroll
    for (int i = 0; i < 32; i += 8) {
        float v = src[((size_t)b * HD + c0 + ty + i) * LL + t0 + tx];
        if (QUANT) v = rintf(v * 64.f) * 0.015625f;
        tile[ty + i][tx] = v;
    }
    __syncthreads();
#pragma unroll
    for (int i = 0; i < 32; i += 8) {
        int t = t0 + ty + i;
        int c = c0 + tx;
        float v = tile[tx][ty + i];
        __nv_bfloat16 h = __float2bfloat16(v);
        size_t o = ((size_t)b * LL + t) * HD + c;
        dhi[o] = h;
        dlo[o] = __float2bfloat16(v - __bfloat162float(h));
    }
}

// ---------------- HMMA GEMM (3x bf16 split, fp32 acc, 3-stage pipe,
//                  512 threads: 4x4 warps, each 32x32) --------
#define KC 64
#define TILE_BYTES 16384            // 128 * 64 * 2B
#define STAGE_BYTES (4 * TILE_BYTES)
#define GEMM_SMEM (3 * STAGE_BYTES) // 196608
#define GTHREADS 512

template <int EPI>
__global__ __launch_bounds__(GTHREADS, 1)
void gemm_mma(const __nv_bfloat16* __restrict__ Wh, const __nv_bfloat16* __restrict__ Wl,
              const __nv_bfloat16* __restrict__ Xh, const __nv_bfloat16* __restrict__ Xl,
              float* __restrict__ out, const float* __restrict__ bias, int M,
              const float* __restrict__ Hprev)
{
    extern __shared__ char smem[];
    const uint32_t sb = smem_u32(smem);
    const int tid = threadIdx.x;
    const int wid = tid >> 5, lane = tid & 31;
    const int wm = wid >> 2, wn = wid & 3;        // 4x4 warp grid
    const int n0 = blockIdx.x * 128;
    const int m0 = blockIdx.y * ((EPI == 2) ? 64 : 128);
    const int lr = lane & 7, lg = lane >> 3;

    float acc[2][4][4];
#pragma unroll
    for (int i = 0; i < 2; ++i)
#pragma unroll
        for (int j = 0; j < 4; ++j)
#pragma unroll
            for (int q = 0; q < 4; ++q) acc[i][j][q] = 0.f;

    auto load_chunk = [&](int kc, int st) {
        const uint32_t base = sb + st * STAGE_BYTES;
        const size_t gk = (size_t)kc * KC;
#pragma unroll
        for (int i = 0; i < 2; ++i) {
            int lin = i * GTHREADS + tid;
            int row = lin >> 3, seg = lin & 7;
            uint32_t soff = row * 128 + (((seg ^ (row & 7))) << 4);
            int wrow;
            if (EPI == 2)
                wrow = ((row >> 4) & 1) * HD + m0 + (row >> 5) * 16 + (row & 15);
            else
                wrow = m0 + row;
            const size_t wgo = (size_t)wrow * HD + gk + seg * 8;
            const size_t xgo = (size_t)(n0 + row) * HD + gk + seg * 8;
            cp_async16(base + soff, Wh + wgo);
            cp_async16(base + TILE_BYTES + soff, Wl + wgo);
            cp_async16(base + 2 * TILE_BYTES + soff, Xh + xgo);
            cp_async16(base + 3 * TILE_BYTES + soff, Xl + xgo);
        }
        CP_COMMIT();
    };

    load_chunk(0, 0);
    load_chunk(1, 1);

    const int NCH = HD / KC;  // 8
    for (int c = 0; c < NCH; ++c) {
        if (c < NCH - 1) { CP_WAIT(1); } else { CP_WAIT(0); }
        __syncthreads();
        if (c + 2 < NCH) load_chunk(c + 2, (c + 2) % 3);

        const uint32_t stg = sb + (c % 3) * STAGE_BYTES;
#pragma unroll
        for (int ks = 0; ks < 4; ++ks) {
            uint32_t a[2][2][4];   // [half][mi][reg]
            uint32_t b[2][2][4];   // [half][g][reg]
#pragma unroll
            for (int mi = 0; mi < 2; ++mi) {
                int arow = wm * 32 + mi * 16 + lr + (lg & 1) * 8;
                int aseg = ks * 2 + (lg >> 1);
                uint32_t off = arow * 128 + ((aseg ^ (arow & 7)) << 4);
                ldmx4(a[0][mi], stg + off);
                ldmx4(a[1][mi], stg + TILE_BYTES + off);
            }
#pragma unroll
            for (int g = 0; g < 2; ++g) {
                int brow = wn * 32 + g * 16 + lr + (lg >> 1) * 8;
                int bseg = ks * 2 + (lg & 1);
                uint32_t off = brow * 128 + ((bseg ^ (brow & 7)) << 4);
                ldmx4(b[0][g], stg + 2 * TILE_BYTES + off);
                ldmx4(b[1][g], stg + 3 * TILE_BYTES + off);
            }
#pragma unroll
            for (int mi = 0; mi < 2; ++mi)
#pragma unroll
                for (int j = 0; j < 4; ++j) {
                    const int g = j >> 1, p = (j & 1) * 2;
                    uint32_t bh[2] = {b[0][g][p], b[0][g][p + 1]};
                    uint32_t bl[2] = {b[1][g][p], b[1][g][p + 1]};
                    mma16816(acc[mi][j], a[0][mi], bh);  // ah*bh
                    mma16816(acc[mi][j], a[0][mi], bl);  // ah*bl
                    mma16816(acc[mi][j], a[1][mi], bh);  // al*bh
                }
        }
    }

    // ---------------- epilogue ----------------
    if (EPI == 2) {
        const int m = m0 + wm * 16 + (lane >> 2);
        const float b1 = bias[m];
        const float b2 = bias[HD + m];
#pragma unroll
        for (int j = 0; j < 4; ++j) {
            const int n = n0 + wn * 32 + j * 8 + (lane & 3) * 2;
            const int bb = n >> 11;
            const int t = n & (LL - 1);
            float z10 = acc[0][j][0] + b1, z11 = acc[0][j][1] + b1;
            float z20 = acc[1][j][0] + b2, z21 = acc[1][j][1] + b2;
            const int m8 = m + 8;
            const float b18 = bias[m8];
            const float b28 = bias[HD + m8];
            float z12 = acc[0][j][2] + b18, z13 = acc[0][j][3] + b18;
            float z22 = acc[1][j][2] + b28, z23 = acc[1][j][3] + b28;
            const float2 p0 = *reinterpret_cast<const float2*>(
                Hprev + ((size_t)bb * HD + m) * LL + t);
            const float2 p1 = *reinterpret_cast<const float2*>(
                Hprev + ((size_t)bb * HD + m8) * LL + t);
            float2 v0, v1;
            v0.x = z10 / (1.f + expf(-z20)) + p0.x;
            v0.y = z11 / (1.f + expf(-z21)) + p0.y;
            v1.x = z12 / (1.f + expf(-z22)) + p1.x;
            v1.y = z13 / (1.f + expf(-z23)) + p1.y;
            *reinterpret_cast<float2*>(out + ((size_t)bb * HD + m) * LL + t) = v0;
            *reinterpret_cast<float2*>(out + ((size_t)bb * HD + m8) * LL + t) = v1;
        }
    } else {
#pragma unroll
        for (int mi = 0; mi < 2; ++mi) {
            const int mrow0 = m0 + wm * 32 + mi * 16 + (lane >> 2);
#pragma unroll
            for (int j = 0; j < 4; ++j) {
                const int n = n0 + wn * 32 + j * 8 + (lane & 3) * 2;
                const int bb = n >> 11;
                const int t = n & (LL - 1);
                float2 v0, v1;
                v0.x = fmaxf(acc[mi][j][0], 0.f);
                v0.y = fmaxf(acc[mi][j][1], 0.f);
                v1.x = fmaxf(acc[mi][j][2], 0.f);
                v1.y = fmaxf(acc[mi][j][3], 0.f);
                *reinterpret_cast<float2*>(out + ((size_t)bb * M + mrow0) * LL + t) = v0;
                *reinterpret_cast<float2*>(out + ((size_t)bb * M + mrow0 + 8) * LL + t) = v1;
            }
        }
    }
}

// ---------------- single-pass LayerNorm ----------------
// WRT==0: Hn = LN(V) fp32 (for next layer's scan)
// WRT==1: writes LN(V) directly as transposed bf16 hi/lo (decoder operands)
template <int WRT>
__global__ __launch_bounds__(256)
void ln_kernel(const float* __restrict__ V, float* __restrict__ Hn,
               __nv_bfloat16* __restrict__ dhi, __nv_bfloat16* __restrict__ dlo,
               const float* __restrict__ gamma, const float* __restrict__ beta)
{
    __shared__ float ssum[8][32];
    __shared__ float ssq[8][32];
    __shared__ __nv_bfloat16 hs[32][72];
    __shared__ __nv_bfloat16 ls[32][72];
    const int b = blockIdx.y;
    const int tx = threadIdx.x & 31;
    const int ty = threadIdx.x >> 5;          // 0..7
    const size_t t = (size_t)blockIdx.x * 32 + tx;
    const float* Vb = V + (size_t)b * HD * LL + t;
    float* Hb = Hn + (size_t)b * HD * LL + t;

    float vals[64];
    float s = 0.f, s2 = 0.f;
#pragma unroll
    for (int k = 0; k < 64; ++k) {
        const int c = k * 8 + ty;
        float v = Vb[(size_t)c * LL];
        vals[k] = v;
        s += v;
        s2 = fmaf(v, v, s2);
    }
    ssum[ty][tx] = s;
    ssq[ty][tx] = s2;
    __syncthreads();
    float st = 0.f, st2 = 0.f;
#pragma unroll
    for (int i = 0; i < 8; ++i) {
        st += ssum[i][tx];
        st2 += ssq[i][tx];
    }
    const float mu = st * (1.f / HD);
    const float var = st2 * (1.f / HD) - mu * mu;
    const float rstd = rsqrtf(var + 1e-5f);

    if (WRT == 0) {
#pragma unroll
        for (int k = 0; k < 64; ++k) {
            const int c = k * 8 + ty;
            Hb[(size_t)c * LL] = (vals[k] - mu) * rstd * gamma[c] + beta[c];
        }
    } else {
        const int tt = (int)(threadIdx.x >> 3), seg = (int)(threadIdx.x & 7);
        const size_t trow = ((size_t)b * LL + (size_t)blockIdx.x * 32 + tt) * HD;
#pragma unroll
        for (int kc = 0; kc < 8; ++kc) {
#pragma unroll
            for (int i = 0; i < 8; ++i) {
                const int k = kc * 8 + i;
                const int c = k * 8 + ty;
                float v = (vals[k] - mu) * rstd * gamma[c] + beta[c];
                __nv_bfloat16 h = __float2bfloat16(v);
                hs[tx][i * 8 + ty] = h;
                ls[tx][i * 8 + ty] = __float2bfloat16(v - __bfloat162float(h));
            }
            __syncthreads();
            *reinterpret_cast<uint4*>(dhi + trow + kc * 64 + seg * 8) =
                *reinterpret_cast<const uint4*>(&hs[tt][seg * 8]);
            *reinterpret_cast<uint4*>(dlo + trow + kc * 64 + seg * 8) =
                *reinterpret_cast<const uint4*>(&ls[tt][seg * 8]);
            __syncthreads();
        }
    }
}

// ---------------- SSM scan: 4 lanes/channel, 8 states/lane -> bf16 hi/lo T --
__global__ __launch_bounds__(256)
void ssm_scan_fused(const float* __restrict__ hbuf,
                    __nv_bfloat16* __restrict__ dhi,
                    __nv_bfloat16* __restrict__ dlo,
                    const float* __restrict__ wre, const float* __restrict__ wim,
                    const float* __restrict__ ccre, const float* __restrict__ ccim,
                    const float* __restrict__ Dv)
{
    __shared__ float tile[32][72];
    const int tid = threadIdx.x;
    const int q = tid & 3;                  // lane within 4-lane group
    const int g = tid >> 2;                 // 0..63 channel within block
    const int grp0 = blockIdx.x * 64;
    const int grp = grp0 + g;
    const int b = grp >> 9;
    const int hh = grp & (HD - 1);
    const int h0 = grp0 & (HD - 1);
    const float* hrow = hbuf + (size_t)grp * LL;

    const int pbase = hh * NN + q * 8;
    float wr[8], wi[8], cr[8], ci[8];
    {
        float4 a0 = *reinterpret_cast<const float4*>(&wre[pbase]);
        float4 a1 = *reinterpret_cast<const float4*>(&wre[pbase + 4]);
        wr[0]=a0.x; wr[1]=a0.y; wr[2]=a0.z; wr[3]=a0.w;
        wr[4]=a1.x; wr[5]=a1.y; wr[6]=a1.z; wr[7]=a1.w;
        float4 b0 = *reinterpret_cast<const float4*>(&wim[pbase]);
        float4 b1 = *reinterpret_cast<const float4*>(&wim[pbase + 4]);
        wi[0]=b0.x; wi[1]=b0.y; wi[2]=b0.z; wi[3]=b0.w;
        wi[4]=b1.x; wi[5]=b1.y; wi[6]=b1.z; wi[7]=b1.w;
        float4 c0 = *reinterpret_cast<const float4*>(&ccre[pbase]);
        float4 c1 = *reinterpret_cast<const float4*>(&ccre[pbase + 4]);
        cr[0]=c0.x; cr[1]=c0.y; cr[2]=c0.z; cr[3]=c0.w;
        cr[4]=c1.x; cr[5]=c1.y; cr[6]=c1.z; cr[7]=c1.w;
        float4 d0 = *reinterpret_cast<const float4*>(&ccim[pbase]);
        float4 d1 = *reinterpret_cast<const float4*>(&ccim[pbase + 4]);
        ci[0]=d0.x; ci[1]=d0.y; ci[2]=d0.z; ci[3]=d0.w;
        ci[4]=d1.x; ci[5]=d1.y; ci[6]=d1.z; ci[7]=d1.w;
    }
    const float Dh = Dv[hh];

    float sr[8], si[8];
#pragma unroll
    for (int k = 0; k < 8; ++k) { sr[k] = 0.f; si[k] = 0.f; }

    const int tt = tid >> 3, seg = tid & 7;

    for (int t0 = 0; t0 < LL; t0 += 32) {
#pragma unroll
        for (int sub = 0; sub < 8; ++sub) {
            const int tb = t0 + sub * 4;
            const float4 ua = *reinterpret_cast<const float4*>(hrow + tb);
            const float uu[4] = {ua.x, ua.y, ua.z, ua.w};
            float umine = 0.f, ykeep = 0.f;
#pragma unroll
            for (int j = 0; j < 4; ++j) {
                const float u = uu[j];
#pragma unroll
                for (int k = 0; k < 8; ++k) {
                    float nr = fmaf(wr[k], sr[k], u);
                    nr = fmaf(-wi[k], si[k], nr);
                    float ni = wr[k] * si[k];
                    ni = fmaf(wi[k], sr[k], ni);
                    sr[k] = nr;
                    si[k] = ni;
                }
                float acc = 0.f;
#pragma unroll
                for (int k = 0; k < 8; ++k) {
                    acc = fmaf(cr[k], sr[k], acc);
                    acc = fmaf(-ci[k], si[k], acc);
                }
                acc += __shfl_xor_sync(0xffffffffu, acc, 1);
                acc += __shfl_xor_sync(0xffffffffu, acc, 2);
                if (j == q) { umine = u; ykeep = acc; }
            }
            float yv = fmaf(Dh, umine, 2.f * ykeep);
            float gv = 0.5f * yv * (1.f + erff(yv * 0.70710678118654752f));
            tile[sub * 4 + q][g] = gv;
        }
        __syncthreads();
        {
            const int t = t0 + tt;
            __nv_bfloat16 hi8[8], lo8[8];
#pragma unroll
            for (int i = 0; i < 8; ++i) {
                float v = tile[tt][seg * 8 + i];
                hi8[i] = __float2bfloat16(v);
                lo8[i] = __float2bfloat16(v - __bfloat162float(hi8[i]));
            }
            const size_t o = ((size_t)b * LL + t) * HD + h0 + seg * 8;
            *reinterpret_cast<uint4*>(dhi + o) = *reinterpret_cast<uint4*>(hi8);
            *reinterpret_cast<uint4*>(dlo + o) = *reinterpret_cast<uint4*>(lo8);
        }
        __syncthreads();
    }
}

// ---------------- launch ----------------
extern "C" void kernel_launch(void* const* d_in, const int* in_sizes, int n_in,
                              void* d_out, int out_size)
{
    const float* x = (const float*)d_in[0];
    const float* W_enc = (const float*)d_in[1];
    const float* W_dec = (const float*)d_in[2];
    const float* log_dt = (const float*)d_in[3];
    const float* log_A_real = (const float*)d_in[4];
    const float* A_imag = (const float*)d_in[5];
    const float* C_re = (const float*)d_in[6];
    const float* C_im = (const float*)d_in[7];
    const float* Dv = (const float*)d_in[8];
    const float* W_out = (const float*)d_in[9];
    const float* b_out = (const float*)d_in[10];
    const float* ln_g = (const float*)d_in[11];
    const float* ln_b = (const float*)d_in[12];
    float* out = (float*)d_out;

    float *pH, *pV, *pwre, *pwim, *pcre, *pcim;
    __nv_bfloat16 *pBth, *pBtl, *pWh, *pWl;
    cudaGetSymbolAddress((void**)&pH, g_H);
    cudaGetSymbolAddress((void**)&pV, g_V);
    cudaGetSymbolAddress((void**)&pwre, g_wre);
    cudaGetSymbolAddress((void**)&pwim, g_wim);
    cudaGetSymbolAddress((void**)&pcre, g_cre);
    cudaGetSymbolAddress((void**)&pcim, g_cim);
    cudaGetSymbolAddress((void**)&pBth, g_Bth);
    cudaGetSymbolAddress((void**)&pBtl, g_Btl);
    cudaGetSymbolAddress((void**)&pWh, g_Wh);
    cudaGetSymbolAddress((void**)&pWl, g_Wl);

    cudaFuncSetAttribute(gemm_mma<0>, cudaFuncAttributeMaxDynamicSharedMemorySize, GEMM_SMEM);
    cudaFuncSetAttribute(gemm_mma<2>, cudaFuncAttributeMaxDynamicSharedMemorySize, GEMM_SMEM);

    precompute_kernel<<<(NL * HD * NN + 255) / 256, 256>>>(log_dt, log_A_real,
                                                           A_imag, C_re, C_im);
    split_w_all<<<(W_ELEMS + 255) / 256, 256>>>(W_enc, W_out, W_dec, pWh, pWl);

    const dim3 tgrid(LL / 32, HD / 32, BQ);

    // encoder: H = relu(W_enc @ quant(x))
    transpose_split_kernel<true><<<tgrid, 256>>>(x, pBth, pBtl);
    gemm_mma<0><<<dim3(NTOT / 128, HD / 128), GTHREADS, GEMM_SMEM>>>(
        pWh + W_ENC_OFF, pWl + W_ENC_OFF, pBth, pBtl, pH, nullptr, HD, nullptr);

    for (int l = 0; l < NL; ++l) {
        const int po = l * HD * NN;
        // scan(H) + gelu -> transposed bf16 hi/lo
        ssm_scan_fused<<<(BQ * HD) / 64, 256>>>(
            pH, pBth, pBtl, pwre + po, pwim + po, pcre + po, pcim + po,
            Dv + l * HD);
        // fused GLU + residual: V = glu(z) + H
        gemm_mma<2><<<dim3(NTOT / 128, HD / 64), GTHREADS, GEMM_SMEM>>>(
            pWh + W_OUT_OFF + (size_t)l * 2 * HD * HD,
            pWl + W_OUT_OFF + (size_t)l * 2 * HD * HD,
            pBth, pBtl, pV, b_out + l * 2 * HD, HD, pH);
        // H = LN(V); last layer writes decoder operands directly
        if (l < NL - 1)
            ln_kernel<0><<<dim3(LL / 32, BQ), 256>>>(pV, pH, nullptr, nullptr,
                                                     ln_g + l * HD, ln_b + l * HD);
        else
            ln_kernel<1><<<dim3(LL / 32, BQ), 256>>>(pV, nullptr, pBth, pBtl,
                                                     ln_g + l * HD, ln_b + l * HD);
    }

    // decoder: out = relu(W_dec @ LN(V3))
    gemm_mma<0><<<dim3(NTOT / 128, HD / 128), GTHREADS, GEMM_SMEM>>>(
        pWh + W_DEC_OFF, pWl + W_DEC_OFF, pBth, pBtl, out, nullptr, HD, nullptr);
}

// round 16
// speedup vs baseline: 1.1607x; 1.0532x over previous
#include <cuda_runtime.h>
#include <cuda_bf16.h>
#include <stdint.h>
#include <math.h>

#define BQ 16
#define HD 512
#define LL 2048
#define NL 4
#define NN 32
#define NTOT (BQ * LL)  // 32768 total columns

// ---------------- scratch (static __device__, no allocs) ----------------
__device__ float g_H[(size_t)BQ * HD * LL];          // normalized stream Hn
__device__ float g_V[(size_t)BQ * HD * LL];          // pre-norm V scratch
__device__ __nv_bfloat16 g_Bth[(size_t)NTOT * HD];   // activations (n,k) hi
__device__ __nv_bfloat16 g_Btl[(size_t)NTOT * HD];   // activations (n,k) lo
#define W_ENC_OFF 0
#define W_OUT_OFF (HD * HD)
#define W_DEC_OFF (HD * HD + NL * 2 * HD * HD)
#define W_ELEMS (2 * HD * HD + NL * 2 * HD * HD)
__device__ __nv_bfloat16 g_Wh[W_ELEMS];
__device__ __nv_bfloat16 g_Wl[W_ELEMS];
__device__ float g_wre[NL * HD * NN];
__device__ float g_wim[NL * HD * NN];
__device__ float g_cre[NL * HD * NN];
__device__ float g_cim[NL * HD * NN];

// ---------------- helpers ----------------
__device__ __forceinline__ uint32_t smem_u32(const void* p)
{
    uint32_t a;
    asm("{ .reg .u64 t; cvta.to.shared.u64 t, %1; cvt.u32.u64 %0, t; }"
        : "=r"(a) : "l"(p));
    return a;
}

__device__ __forceinline__ void cp_async16(uint32_t dst, const void* src)
{
    asm volatile("cp.async.cg.shared.global [%0], [%1], 16;" :: "r"(dst), "l"(src));
}
#define CP_COMMIT() asm volatile("cp.async.commit_group;" ::: "memory")
#define CP_WAIT(n)  asm volatile("cp.async.wait_group %0;" :: "n"(n) : "memory")

__device__ __forceinline__ void ldmx4(uint32_t* r, uint32_t addr)
{
    asm volatile("ldmatrix.sync.aligned.m8n8.x4.shared.b16 {%0,%1,%2,%3}, [%4];"
                 : "=r"(r[0]), "=r"(r[1]), "=r"(r[2]), "=r"(r[3]) : "r"(addr));
}

__device__ __forceinline__ void mma16816(float* c, const uint32_t* a,
                                         const uint32_t* b)
{
    asm volatile(
        "mma.sync.aligned.m16n8k16.row.col.f32.bf16.bf16.f32 "
        "{%0,%1,%2,%3}, {%4,%5,%6,%7}, {%8,%9}, {%0,%1,%2,%3};"
        : "+f"(c[0]), "+f"(c[1]), "+f"(c[2]), "+f"(c[3])
        : "r"(a[0]), "r"(a[1]), "r"(a[2]), "r"(a[3]), "r"(b[0]), "r"(b[1]));
}

// ---------------- parameter precompute ----------------
__global__ __launch_bounds__(256)
void precompute_kernel(const float* __restrict__ log_dt,
                       const float* __restrict__ log_A_real,
                       const float* __restrict__ A_imag,
                       const float* __restrict__ C_re,
                       const float* __restrict__ C_im)
{
    int idx = blockIdx.x * 256 + threadIdx.x;
    if (idx >= NL * HD * NN) return;
    int h = (idx >> 5) & (HD - 1);
    int l = idx >> 14;
    float dt = expf(log_dt[l * HD + h]);
    float a = -expf(log_A_real[idx]);
    float b = A_imag[idx];
    float xr = dt * a, xi = dt * b;
    float er = expf(xr);
    float c = cosf(xi), s = sinf(xi);
    g_wre[idx] = er * c;
    g_wim[idx] = er * s;
    float sh = sinf(0.5f * xi);
    float Ere = expm1f(xr) * c - 2.f * sh * sh;
    float Eim = er * s;
    float den = a * a + b * b;
    float Fre = (Ere * a + Eim * b) / den;
    float Fim = (Eim * a - Ere * b) / den;
    float cr = C_re[idx], ci = C_im[idx];
    g_cre[idx] = cr * Fre - ci * Fim;
    g_cim[idx] = cr * Fim + ci * Fre;
}

// ---------------- weight split fp32 -> bf16 hi/lo ----------------
__global__ __launch_bounds__(256)
void split_w_all(const float* __restrict__ W_enc, const float* __restrict__ W_out,
                 const float* __restrict__ W_dec,
                 __nv_bfloat16* __restrict__ hi, __nv_bfloat16* __restrict__ lo)
{
    int i = blockIdx.x * 256 + threadIdx.x;
    if (i >= W_ELEMS) return;
    float v;
    if (i < W_OUT_OFF) v = W_enc[i];
    else if (i < W_DEC_OFF) v = W_out[i - W_OUT_OFF];
    else v = W_dec[i - W_DEC_OFF];
    __nv_bfloat16 h = __float2bfloat16(v);
    hi[i] = h;
    lo[i] = __float2bfloat16(v - __bfloat162float(h));
}

// ---------------- transpose + split (+opt quant) ----------
template <bool QUANT>
__global__ __launch_bounds__(256)
void transpose_split_kernel(const float* __restrict__ src,
                            __nv_bfloat16* __restrict__ dhi,
                            __nv_bfloat16* __restrict__ dlo)
{
    __shared__ float tile[32][33];
    const int b = blockIdx.z;
    const int c0 = blockIdx.y * 32;
    const int t0 = blockIdx.x * 32;
    const int tx = threadIdx.x & 31, ty = threadIdx.x >> 5;
#pragma unroll
    for (int i = 0; i < 32; i += 8) {
        float v = src[((size_t)b * HD + c0 + ty + i) * LL + t0 + tx];
        if (QUANT) v = rintf(v * 64.f) * 0.015625f;
        tile[ty + i][tx] = v;
    }
    __syncthreads();
#pragma unroll
    for (int i = 0; i < 32; i += 8) {
        int t = t0 + ty + i;
        int c = c0 + tx;
        float v = tile[tx][ty + i];
        __nv_bfloat16 h = __float2bfloat16(v);
        size_t o = ((size_t)b * LL + t) * HD + c;
        dhi[o] = h;
        dlo[o] = __float2bfloat16(v - __bfloat162float(h));
    }
}

#define KC 64
// ============ EPI0 GEMM: relu, 256 thr, tile 128x128, 3-stage (R12) =========
#define TILE_BYTES 16384            // 128 * 64 * 2B
#define STAGE0 (4 * TILE_BYTES)     // 65536
#define SMEM0 (3 * STAGE0)          // 196608

__global__ __launch_bounds__(256, 1)
void gemm_relu(const __nv_bfloat16* __restrict__ Wh, const __nv_bfloat16* __restrict__ Wl,
               const __nv_bfloat16* __restrict__ Xh, const __nv_bfloat16* __restrict__ Xl,
               float* __restrict__ out, int M)
{
    extern __shared__ char smem[];
    const uint32_t sb = smem_u32(smem);
    const int tid = threadIdx.x;
    const int wid = tid >> 5, lane = tid & 31;
    const int wm = wid >> 1, wn = wid & 1;
    const int n0 = blockIdx.x * 128;
    const int m0 = blockIdx.y * 128;
    const int lr = lane & 7, lg = lane >> 3;

    float acc[2][8][4];
#pragma unroll
    for (int i = 0; i < 2; ++i)
#pragma unroll
        for (int j = 0; j < 8; ++j)
#pragma unroll
            for (int q = 0; q < 4; ++q) acc[i][j][q] = 0.f;

    auto load_chunk = [&](int kc, int st) {
        const uint32_t base = sb + st * STAGE0;
        const size_t gk = (size_t)kc * KC;
#pragma unroll
        for (int i = 0; i < 4; ++i) {
            int lin = i * 256 + tid;
            int row = lin >> 3, seg = lin & 7;
            uint32_t soff = row * 128 + (((seg ^ (row & 7))) << 4);
            const size_t wgo = (size_t)(m0 + row) * HD + gk + seg * 8;
            const size_t xgo = (size_t)(n0 + row) * HD + gk + seg * 8;
            cp_async16(base + soff, Wh + wgo);
            cp_async16(base + TILE_BYTES + soff, Wl + wgo);
            cp_async16(base + 2 * TILE_BYTES + soff, Xh + xgo);
            cp_async16(base + 3 * TILE_BYTES + soff, Xl + xgo);
        }
        CP_COMMIT();
    };

    load_chunk(0, 0);
    load_chunk(1, 1);

    const int NCH = HD / KC;  // 8
    for (int c = 0; c < NCH; ++c) {
        if (c < NCH - 1) { CP_WAIT(1); } else { CP_WAIT(0); }
        __syncthreads();
        if (c + 2 < NCH) load_chunk(c + 2, (c + 2) % 3);

        const uint32_t stg = sb + (c % 3) * STAGE0;
#pragma unroll
        for (int ks = 0; ks < 4; ++ks) {
            uint32_t a[2][2][4];
            uint32_t b[2][4][4];
#pragma unroll
            for (int mi = 0; mi < 2; ++mi) {
                int arow = wm * 32 + mi * 16 + lr + (lg & 1) * 8;
                int aseg = ks * 2 + (lg >> 1);
                uint32_t off = arow * 128 + ((aseg ^ (arow & 7)) << 4);
                ldmx4(a[0][mi], stg + off);
                ldmx4(a[1][mi], stg + TILE_BYTES + off);
            }
#pragma unroll
            for (int g = 0; g < 4; ++g) {
                int brow = wn * 64 + g * 16 + lr + (lg >> 1) * 8;
                int bseg = ks * 2 + (lg & 1);
                uint32_t off = brow * 128 + ((bseg ^ (brow & 7)) << 4);
                ldmx4(b[0][g], stg + 2 * TILE_BYTES + off);
                ldmx4(b[1][g], stg + 3 * TILE_BYTES + off);
            }
#pragma unroll
            for (int mi = 0; mi < 2; ++mi)
#pragma unroll
                for (int j = 0; j < 8; ++j) {
                    const int g = j >> 1, p = (j & 1) * 2;
                    uint32_t bh[2] = {b[0][g][p], b[0][g][p + 1]};
                    uint32_t bl[2] = {b[1][g][p], b[1][g][p + 1]};
                    mma16816(acc[mi][j], a[0][mi], bh);
                    mma16816(acc[mi][j], a[0][mi], bl);
                    mma16816(acc[mi][j], a[1][mi], bh);
                }
        }
    }

#pragma unroll
    for (int mi = 0; mi < 2; ++mi) {
        const int mrow0 = m0 + wm * 32 + mi * 16 + (lane >> 2);
#pragma unroll
        for (int j = 0; j < 8; ++j) {
            const int n = n0 + wn * 64 + j * 8 + (lane & 3) * 2;
            const int bb = n >> 11;
            const int t = n & (LL - 1);
            float2 v0, v1;
            v0.x = fmaxf(acc[mi][j][0], 0.f);
            v0.y = fmaxf(acc[mi][j][1], 0.f);
            v1.x = fmaxf(acc[mi][j][2], 0.f);
            v1.y = fmaxf(acc[mi][j][3], 0.f);
            *reinterpret_cast<float2*>(out + ((size_t)bb * M + mrow0) * LL + t) = v0;
            *reinterpret_cast<float2*>(out + ((size_t)bb * M + mrow0 + 8) * LL + t) = v1;
        }
    }
}

// ==== EPI2 GEMM: GLU+residual, 512 thr, A 256x64 (z1/z2), B 128x64, 2-stage ==
#define TILE_A2 32768               // 256 * 64 * 2B
#define TILE_B2 16384               // 128 * 64 * 2B
#define STAGE2 (2 * TILE_A2 + 2 * TILE_B2)   // 98304
#define SMEM2 (2 * STAGE2)                   // 196608

__global__ __launch_bounds__(512, 1)
void gemm_glu(const __nv_bfloat16* __restrict__ Wh, const __nv_bfloat16* __restrict__ Wl,
              const __nv_bfloat16* __restrict__ Xh, const __nv_bfloat16* __restrict__ Xl,
              float* __restrict__ out, const float* __restrict__ bias,
              const float* __restrict__ Hprev)
{
    extern __shared__ char smem[];
    const uint32_t sb = smem_u32(smem);
    const int tid = threadIdx.x;
    const int wid = tid >> 5, lane = tid & 31;
    const int wm = wid >> 1, wn = wid & 1;    // 8(M) x 2(N)
    const int n0 = blockIdx.x * 128;
    const int m0 = blockIdx.y * 128;          // 128 out rows per CTA
    const int lr = lane & 7, lg = lane >> 3;

    float acc[2][8][4];
#pragma unroll
    for (int i = 0; i < 2; ++i)
#pragma unroll
        for (int j = 0; j < 8; ++j)
#pragma unroll
            for (int q = 0; q < 4; ++q) acc[i][j][q] = 0.f;

    auto load_chunk = [&](int kc, int st) {
        const uint32_t base = sb + st * STAGE2;
        const size_t gk = (size_t)kc * KC;
#pragma unroll
        for (int i = 0; i < 4; ++i) {
            int lin = i * 512 + tid;
            int row = lin >> 3, seg = lin & 7;   // row 0..255
            uint32_t soff = row * 128 + (((seg ^ (row & 7))) << 4);
            int wrow = ((row >> 4) & 1) * HD + m0 + ((row >> 5) << 4) + (row & 15);
            const size_t wgo = (size_t)wrow * HD + gk + seg * 8;
            cp_async16(base + soff, Wh + wgo);
            cp_async16(base + TILE_A2 + soff, Wl + wgo);
        }
#pragma unroll
        for (int i = 0; i < 2; ++i) {
            int lin = i * 512 + tid;
            int row = lin >> 3, seg = lin & 7;   // row 0..127
            uint32_t soff = row * 128 + (((seg ^ (row & 7))) << 4);
            const size_t xgo = (size_t)(n0 + row) * HD + gk + seg * 8;
            cp_async16(base + 2 * TILE_A2 + soff, Xh + xgo);
            cp_async16(base + 2 * TILE_A2 + TILE_B2 + soff, Xl + xgo);
        }
        CP_COMMIT();
    };

    load_chunk(0, 0);

    const int NCH = HD / KC;  // 8
    for (int c = 0; c < NCH; ++c) {
        if (c + 1 < NCH) {
            load_chunk(c + 1, (c + 1) & 1);
            CP_WAIT(1);
        } else {
            CP_WAIT(0);
        }
        __syncthreads();

        const uint32_t stg = sb + (c & 1) * STAGE2;
#pragma unroll
        for (int ks = 0; ks < 4; ++ks) {
            uint32_t a[2][2][4];   // [half][mi]
#pragma unroll
            for (int mi = 0; mi < 2; ++mi) {
                int arow = wm * 32 + mi * 16 + lr + (lg & 1) * 8;
                int aseg = ks * 2 + (lg >> 1);
                uint32_t off = arow * 128 + ((aseg ^ (arow & 7)) << 4);
                ldmx4(a[0][mi], stg + off);
                ldmx4(a[1][mi], stg + TILE_A2 + off);
            }
#pragma unroll
            for (int gh = 0; gh < 2; ++gh) {
                uint32_t b[2][2][4];   // [half][gg]
#pragma unroll
                for (int gg = 0; gg < 2; ++gg) {
                    int g = gh * 2 + gg;
                    int brow = wn * 64 + g * 16 + lr + (lg >> 1) * 8;
                    int bseg = ks * 2 + (lg & 1);
                    uint32_t off = brow * 128 + ((bseg ^ (brow & 7)) << 4);
                    ldmx4(b[0][gg], stg + 2 * TILE_A2 + off);
                    ldmx4(b[1][gg], stg + 2 * TILE_A2 + TILE_B2 + off);
                }
#pragma unroll
                for (int mi = 0; mi < 2; ++mi)
#pragma unroll
                    for (int jj = 0; jj < 4; ++jj) {
                        const int j = gh * 4 + jj;
                        const int gg = jj >> 1, p = (jj & 1) * 2;
                        uint32_t bh[2] = {b[0][gg][p], b[0][gg][p + 1]};
                        uint32_t bl[2] = {b[1][gg][p], b[1][gg][p + 1]};
                        mma16816(acc[mi][j], a[0][mi], bh);  // ah*bh
                        mma16816(acc[mi][j], a[0][mi], bl);  // ah*bl
                        mma16816(acc[mi][j], a[1][mi], bh);  // al*bh
                    }
            }
        }
        __syncthreads();
    }

    // epilogue: acc[0]=z1 rows m, acc[1]=z2 rows m
    {
        const int m = m0 + wm * 16 + (lane >> 2);
        const int m8 = m + 8;
        const float b10 = bias[m],      b18 = bias[m8];
        const float b20 = bias[HD + m], b28 = bias[HD + m8];
#pragma unroll
        for (int j = 0; j < 8; ++j) {
            const int n = n0 + wn * 64 + j * 8 + (lane & 3) * 2;
            const int bb = n >> 11;
            const int t = n & (LL - 1);
            float z10 = acc[0][j][0] + b10, z11 = acc[0][j][1] + b10;
            float z12 = acc[0][j][2] + b18, z13 = acc[0][j][3] + b18;
            float z20 = acc[1][j][0] + b20, z21 = acc[1][j][1] + b20;
            float z22 = acc[1][j][2] + b28, z23 = acc[1][j][3] + b28;
            const float2 p0 = *reinterpret_cast<const float2*>(
                Hprev + ((size_t)bb * HD + m) * LL + t);
            const float2 p1 = *reinterpret_cast<const float2*>(
                Hprev + ((size_t)bb * HD + m8) * LL + t);
            float2 v0, v1;
            v0.x = z10 / (1.f + expf(-z20)) + p0.x;
            v0.y = z11 / (1.f + expf(-z21)) + p0.y;
            v1.x = z12 / (1.f + expf(-z22)) + p1.x;
            v1.y = z13 / (1.f + expf(-z23)) + p1.y;
            *reinterpret_cast<float2*>(out + ((size_t)bb * HD + m) * LL + t) = v0;
            *reinterpret_cast<float2*>(out + ((size_t)bb * HD + m8) * LL + t) = v1;
        }
    }
}

// ---------------- single-pass LayerNorm ----------------
template <int WRT>
__global__ __launch_bounds__(256)
void ln_kernel(const float* __restrict__ V, float* __restrict__ Hn,
               __nv_bfloat16* __restrict__ dhi, __nv_bfloat16* __restrict__ dlo,
               const float* __restrict__ gamma, const float* __restrict__ beta)
{
    __shared__ float ssum[8][32];
    __shared__ float ssq[8][32];
    __shared__ __nv_bfloat16 hs[32][72];
    __shared__ __nv_bfloat16 ls[32][72];
    const int b = blockIdx.y;
    const int tx = threadIdx.x & 31;
    const int ty = threadIdx.x >> 5;
    const size_t t = (size_t)blockIdx.x * 32 + tx;
    const float* Vb = V + (size_t)b * HD * LL + t;
    float* Hb = Hn + (size_t)b * HD * LL + t;

    float vals[64];
    float s = 0.f, s2 = 0.f;
#pragma unroll
    for (int k = 0; k < 64; ++k) {
        const int c = k * 8 + ty;
        float v = Vb[(size_t)c * LL];
        vals[k] = v;
        s += v;
        s2 = fmaf(v, v, s2);
    }
    ssum[ty][tx] = s;
    ssq[ty][tx] = s2;
    __syncthreads();
    float st = 0.f, st2 = 0.f;
#pragma unroll
    for (int i = 0; i < 8; ++i) {
        st += ssum[i][tx];
        st2 += ssq[i][tx];
    }
    const float mu = st * (1.f / HD);
    const float var = st2 * (1.f / HD) - mu * mu;
    const float rstd = rsqrtf(var + 1e-5f);

    if (WRT == 0) {
#pragma unroll
        for (int k = 0; k < 64; ++k) {
            const int c = k * 8 + ty;
            Hb[(size_t)c * LL] = (vals[k] - mu) * rstd * gamma[c] + beta[c];
        }
    } else {
        const int tt = (int)(threadIdx.x >> 3), seg = (int)(threadIdx.x & 7);
        const size_t trow = ((size_t)b * LL + (size_t)blockIdx.x * 32 + tt) * HD;
#pragma unroll
        for (int kc = 0; kc < 8; ++kc) {
#pragma unroll
            for (int i = 0; i < 8; ++i) {
                const int k = kc * 8 + i;
                const int c = k * 8 + ty;
                float v = (vals[k] - mu) * rstd * gamma[c] + beta[c];
                __nv_bfloat16 h = __float2bfloat16(v);
                hs[tx][i * 8 + ty] = h;
                ls[tx][i * 8 + ty] = __float2bfloat16(v - __bfloat162float(h));
            }
            __syncthreads();
            *reinterpret_cast<uint4*>(dhi + trow + kc * 64 + seg * 8) =
                *reinterpret_cast<const uint4*>(&hs[tt][seg * 8]);
            *reinterpret_cast<uint4*>(dlo + trow + kc * 64 + seg * 8) =
                *reinterpret_cast<const uint4*>(&ls[tt][seg * 8]);
            __syncthreads();
        }
    }
}

// ---------------- SSM scan: 4 lanes/channel, 8 states/lane -> bf16 hi/lo T --
__global__ __launch_bounds__(256)
void ssm_scan_fused(const float* __restrict__ hbuf,
                    __nv_bfloat16* __restrict__ dhi,
                    __nv_bfloat16* __restrict__ dlo,
                    const float* __restrict__ wre, const float* __restrict__ wim,
                    const float* __restrict__ ccre, const float* __restrict__ ccim,
                    const float* __restrict__ Dv)
{
    __shared__ float tile[32][72];
    const int tid = threadIdx.x;
    const int q = tid & 3;
    const int g = tid >> 2;
    const int grp0 = blockIdx.x * 64;
    const int grp = grp0 + g;
    const int b = grp >> 9;
    const int hh = grp & (HD - 1);
    const int h0 = grp0 & (HD - 1);
    const float* hrow = hbuf + (size_t)grp * LL;

    const int pbase = hh * NN + q * 8;
    float wr[8], wi[8], cr[8], ci[8];
    {
        float4 a0 = *reinterpret_cast<const float4*>(&wre[pbase]);
        float4 a1 = *reinterpret_cast<const float4*>(&wre[pbase + 4]);
        wr[0]=a0.x; wr[1]=a0.y; wr[2]=a0.z; wr[3]=a0.w;
        wr[4]=a1.x; wr[5]=a1.y; wr[6]=a1.z; wr[7]=a1.w;
        float4 b0 = *reinterpret_cast<const float4*>(&wim[pbase]);
        float4 b1 = *reinterpret_cast<const float4*>(&wim[pbase + 4]);
        wi[0]=b0.x; wi[1]=b0.y; wi[2]=b0.z; wi[3]=b0.w;
        wi[4]=b1.x; wi[5]=b1.y; wi[6]=b1.z; wi[7]=b1.w;
        float4 c0 = *reinterpret_cast<const float4*>(&ccre[pbase]);
        float4 c1 = *reinterpret_cast<const float4*>(&ccre[pbase + 4]);
        cr[0]=c0.x; cr[1]=c0.y; cr[2]=c0.z; cr[3]=c0.w;
        cr[4]=c1.x; cr[5]=c1.y; cr[6]=c1.z; cr[7]=c1.w;
        float4 d0 = *reinterpret_cast<const float4*>(&ccim[pbase]);
        float4 d1 = *reinterpret_cast<const float4*>(&ccim[pbase + 4]);
        ci[0]=d0.x; ci[1]=d0.y; ci[2]=d0.z; ci[3]=d0.w;
        ci[4]=d1.x; ci[5]=d1.y; ci[6]=d1.z; ci[7]=d1.w;
    }
    const float Dh = Dv[hh];

    float sr[8], si[8];
#pragma unroll
    for (int k = 0; k < 8; ++k) { sr[k] = 0.f; si[k] = 0.f; }

    const int tt = tid >> 3, seg = tid & 7;

    for (int t0 = 0; t0 < LL; t0 += 32) {
#pragma unroll
        for (int sub = 0; sub < 8; ++sub) {
            const int tb = t0 + sub * 4;
            const float4 ua = *reinterpret_cast<const float4*>(hrow + tb);
            const float uu[4] = {ua.x, ua.y, ua.z, ua.w};
            float umine = 0.f, ykeep = 0.f;
#pragma unroll
            for (int j = 0; j < 4; ++j) {
                const float u = uu[j];
#pragma unroll
                for (int k = 0; k < 8; ++k) {
                    float nr = fmaf(wr[k], sr[k], u);
                    nr = fmaf(-wi[k], si[k], nr);
                    float ni = wr[k] * si[k];
                    ni = fmaf(wi[k], sr[k], ni);
                    sr[k] = nr;
                    si[k] = ni;
                }
                float acc = 0.f;
#pragma unroll
                for (int k = 0; k < 8; ++k) {
                    acc = fmaf(cr[k], sr[k], acc);
                    acc = fmaf(-ci[k], si[k], acc);
                }
                acc += __shfl_xor_sync(0xffffffffu, acc, 1);
                acc += __shfl_xor_sync(0xffffffffu, acc, 2);
                if (j == q) { umine = u; ykeep = acc; }
            }
            float yv = fmaf(Dh, umine, 2.f * ykeep);
            float gv = 0.5f * yv * (1.f + erff(yv * 0.70710678118654752f));
            tile[sub * 4 + q][g] = gv;
        }
        __syncthreads();
        {
            const int t = t0 + tt;
            __nv_bfloat16 hi8[8], lo8[8];
#pragma unroll
            for (int i = 0; i < 8; ++i) {
                float v = tile[tt][seg * 8 + i];
                hi8[i] = __float2bfloat16(v);
                lo8[i] = __float2bfloat16(v - __bfloat162float(hi8[i]));
            }
            const size_t o = ((size_t)b * LL + t) * HD + h0 + seg * 8;
            *reinterpret_cast<uint4*>(dhi + o) = *reinterpret_cast<uint4*>(hi8);
            *reinterpret_cast<uint4*>(dlo + o) = *reinterpret_cast<uint4*>(lo8);
        }
        __syncthreads();
    }
}

// ---------------- launch ----------------
extern "C" void kernel_launch(void* const* d_in, const int* in_sizes, int n_in,
                              void* d_out, int out_size)
{
    const float* x = (const float*)d_in[0];
    const float* W_enc = (const float*)d_in[1];
    const float* W_dec = (const float*)d_in[2];
    const float* log_dt = (const float*)d_in[3];
    const float* log_A_real = (const float*)d_in[4];
    const float* A_imag = (const float*)d_in[5];
    const float* C_re = (const float*)d_in[6];
    const float* C_im = (const float*)d_in[7];
    const float* Dv = (const float*)d_in[8];
    const float* W_out = (const float*)d_in[9];
    const float* b_out = (const float*)d_in[10];
    const float* ln_g = (const float*)d_in[11];
    const float* ln_b = (const float*)d_in[12];
    float* out = (float*)d_out;

    float *pH, *pV, *pwre, *pwim, *pcre, *pcim;
    __nv_bfloat16 *pBth, *pBtl, *pWh, *pWl;
    cudaGetSymbolAddress((void**)&pH, g_H);
    cudaGetSymbolAddress((void**)&pV, g_V);
    cudaGetSymbolAddress((void**)&pwre, g_wre);
    cudaGetSymbolAddress((void**)&pwim, g_wim);
    cudaGetSymbolAddress((void**)&pcre, g_cre);
    cudaGetSymbolAddress((void**)&pcim, g_cim);
    cudaGetSymbolAddress((void**)&pBth, g_Bth);
    cudaGetSymbolAddress((void**)&pBtl, g_Btl);
    cudaGetSymbolAddress((void**)&pWh, g_Wh);
    cudaGetSymbolAddress((void**)&pWl, g_Wl);

    cudaFuncSetAttribute(gemm_relu, cudaFuncAttributeMaxDynamicSharedMemorySize, SMEM0);
    cudaFuncSetAttribute(gemm_glu, cudaFuncAttributeMaxDynamicSharedMemorySize, SMEM2);

    precompute_kernel<<<(NL * HD * NN + 255) / 256, 256>>>(log_dt, log_A_real,
                                                           A_imag, C_re, C_im);
    split_w_all<<<(W_ELEMS + 255) / 256, 256>>>(W_enc, W_out, W_dec, pWh, pWl);

    const dim3 tgrid(LL / 32, HD / 32, BQ);

    // encoder: H = relu(W_enc @ quant(x))
    transpose_split_kernel<true><<<tgrid, 256>>>(x, pBth, pBtl);
    gemm_relu<<<dim3(NTOT / 128, HD / 128), 256, SMEM0>>>(
        pWh + W_ENC_OFF, pWl + W_ENC_OFF, pBth, pBtl, pH, HD);

    for (int l = 0; l < NL; ++l) {
        const int po = l * HD * NN;
        // scan(H) + gelu -> transposed bf16 hi/lo
        ssm_scan_fused<<<(BQ * HD) / 64, 256>>>(
            pH, pBth, pBtl, pwre + po, pwim + po, pcre + po, pcim + po,
            Dv + l * HD);
        // fused GLU + residual: V = glu(z) + H  (128 out rows per CTA)
        gemm_glu<<<dim3(NTOT / 128, HD / 128), 512, SMEM2>>>(
            pWh + W_OUT_OFF + (size_t)l * 2 * HD * HD,
            pWl + W_OUT_OFF + (size_t)l * 2 * HD * HD,
            pBth, pBtl, pV, b_out + l * 2 * HD, pH);
        // H = LN(V); last layer writes decoder operands directly
        if (l < NL - 1)
            ln_kernel<0><<<dim3(LL / 32, BQ), 256>>>(pV, pH, nullptr, nullptr,
                                                     ln_g + l * HD, ln_b + l * HD);
        else
            ln_kernel<1><<<dim3(LL / 32, BQ), 256>>>(pV, nullptr, pBth, pBtl,
                                                     ln_g + l * HD, ln_b + l * HD);
    }

    // decoder: out = relu(W_dec @ LN(V3))
    gemm_relu<<<dim3(NTOT / 128, HD / 128), 256, SMEM0>>>(
        pWh + W_DEC_OFF, pWl + W_DEC_OFF, pBth, pBtl, out, HD);
}

// round 17
// speedup vs baseline: 1.2058x; 1.0389x over previous
#include <cuda_runtime.h>
#include <cuda_fp16.h>
#include <stdint.h>
#include <math.h>

#define BQ 16
#define HD 512
#define LL 2048
#define NL 4
#define NN 32
#define NTOT (BQ * LL)  // 32768 total columns

// ---------------- scratch (static __device__, no allocs) ----------------
__device__ float g_H[(size_t)BQ * HD * LL];          // normalized stream Hn
__device__ float g_V[(size_t)BQ * HD * LL];          // pre-norm V scratch
__device__ __half g_X[(size_t)NTOT * HD];            // activations (n,k) fp16
#define W_ENC_OFF 0
#define W_OUT_OFF (HD * HD)
#define W_DEC_OFF (HD * HD + NL * 2 * HD * HD)
#define W_ELEMS (2 * HD * HD + NL * 2 * HD * HD)
__device__ __half g_Wh[W_ELEMS];
__device__ __half g_Wl[W_ELEMS];
__device__ float g_wre[NL * HD * NN];
__device__ float g_wim[NL * HD * NN];
__device__ float g_cre[NL * HD * NN];
__device__ float g_cim[NL * HD * NN];

// ---------------- helpers ----------------
__device__ __forceinline__ uint32_t smem_u32(const void* p)
{
    uint32_t a;
    asm("{ .reg .u64 t; cvta.to.shared.u64 t, %1; cvt.u32.u64 %0, t; }"
        : "=r"(a) : "l"(p));
    return a;
}

__device__ __forceinline__ void cp_async16(uint32_t dst, const void* src)
{
    asm volatile("cp.async.cg.shared.global [%0], [%1], 16;" :: "r"(dst), "l"(src));
}
#define CP_COMMIT() asm volatile("cp.async.commit_group;" ::: "memory")
#define CP_WAIT(n)  asm volatile("cp.async.wait_group %0;" :: "n"(n) : "memory")

__device__ __forceinline__ void ldmx4(uint32_t* r, uint32_t addr)
{
    asm volatile("ldmatrix.sync.aligned.m8n8.x4.shared.b16 {%0,%1,%2,%3}, [%4];"
                 : "=r"(r[0]), "=r"(r[1]), "=r"(r[2]), "=r"(r[3]) : "r"(addr));
}

__device__ __forceinline__ void mma16816(float* c, const uint32_t* a,
                                         const uint32_t* b)
{
    asm volatile(
        "mma.sync.aligned.m16n8k16.row.col.f32.f16.f16.f32 "
        "{%0,%1,%2,%3}, {%4,%5,%6,%7}, {%8,%9}, {%0,%1,%2,%3};"
        : "+f"(c[0]), "+f"(c[1]), "+f"(c[2]), "+f"(c[3])
        : "r"(a[0]), "r"(a[1]), "r"(a[2]), "r"(a[3]), "r"(b[0]), "r"(b[1]));
}

// ---------------- parameter precompute ----------------
__global__ __launch_bounds__(256)
void precompute_kernel(const float* __restrict__ log_dt,
                       const float* __restrict__ log_A_real,
                       const float* __restrict__ A_imag,
                       const float* __restrict__ C_re,
                       const float* __restrict__ C_im)
{
    int idx = blockIdx.x * 256 + threadIdx.x;
    if (idx >= NL * HD * NN) return;
    int h = (idx >> 5) & (HD - 1);
    int l = idx >> 14;
    float dt = expf(log_dt[l * HD + h]);
    float a = -expf(log_A_real[idx]);
    float b = A_imag[idx];
    float xr = dt * a, xi = dt * b;
    float er = expf(xr);
    float c = cosf(xi), s = sinf(xi);
    g_wre[idx] = er * c;
    g_wim[idx] = er * s;
    float sh = sinf(0.5f * xi);
    float Ere = expm1f(xr) * c - 2.f * sh * sh;
    float Eim = er * s;
    float den = a * a + b * b;
    float Fre = (Ere * a + Eim * b) / den;
    float Fim = (Eim * a - Ere * b) / den;
    float cr = C_re[idx], ci = C_im[idx];
    g_cre[idx] = cr * Fre - ci * Fim;
    g_cim[idx] = cr * Fim + ci * Fre;
}

// ---------------- weight split fp32 -> fp16 hi/lo ----------------
__global__ __launch_bounds__(256)
void split_w_all(const float* __restrict__ W_enc, const float* __restrict__ W_out,
                 const float* __restrict__ W_dec,
                 __half* __restrict__ hi, __half* __restrict__ lo)
{
    int i = blockIdx.x * 256 + threadIdx.x;
    if (i >= W_ELEMS) return;
    float v;
    if (i < W_OUT_OFF) v = W_enc[i];
    else if (i < W_DEC_OFF) v = W_out[i - W_OUT_OFF];
    else v = W_dec[i - W_DEC_OFF];
    __half h = __float2half(v);
    hi[i] = h;
    lo[i] = __float2half(v - __half2float(h));
}

// ---------------- transpose (+opt quant) -> fp16 ----------
template <bool QUANT>
__global__ __launch_bounds__(256)
void transpose_half_kernel(const float* __restrict__ src,
                           __half* __restrict__ dst)
{
    __shared__ float tile[32][33];
    const int b = blockIdx.z;
    const int c0 = blockIdx.y * 32;
    const int t0 = blockIdx.x * 32;
    const int tx = threadIdx.x & 31, ty = threadIdx.x >> 5;
#pragma unroll
    for (int i = 0; i < 32; i += 8) {
        float v = src[((size_t)b * HD + c0 + ty + i) * LL + t0 + tx];
        if (QUANT) v = rintf(v * 64.f) * 0.015625f;
        tile[ty + i][tx] = v;
    }
    __syncthreads();
#pragma unroll
    for (int i = 0; i < 32; i += 8) {
        int t = t0 + ty + i;
        int c = c0 + tx;
        size_t o = ((size_t)b * LL + t) * HD + c;
        dst[o] = __float2half(tile[tx][ty + i]);
    }
}

#define KC 64
#define TILE_BYTES 16384            // 128 * 64 * 2B

// ============ EPI0 GEMM: relu, 256 thr, tile 128x128, 3-stage, 2-term =======
#define STAGE0 (3 * TILE_BYTES)     // 49152: Ah, Al, X
#define SMEM0 (3 * STAGE0)          // 147456

__global__ __launch_bounds__(256, 1)
void gemm_relu(const __half* __restrict__ Wh, const __half* __restrict__ Wl,
               const __half* __restrict__ X,
               float* __restrict__ out, int M)
{
    extern __shared__ char smem[];
    const uint32_t sb = smem_u32(smem);
    const int tid = threadIdx.x;
    const int wid = tid >> 5, lane = tid & 31;
    const int wm = wid >> 1, wn = wid & 1;
    const int n0 = blockIdx.x * 128;
    const int m0 = blockIdx.y * 128;
    const int lr = lane & 7, lg = lane >> 3;

    float acc[2][8][4];
#pragma unroll
    for (int i = 0; i < 2; ++i)
#pragma unroll
        for (int j = 0; j < 8; ++j)
#pragma unroll
            for (int q = 0; q < 4; ++q) acc[i][j][q] = 0.f;

    auto load_chunk = [&](int kc, int st) {
        const uint32_t base = sb + st * STAGE0;
        const size_t gk = (size_t)kc * KC;
#pragma unroll
        for (int i = 0; i < 4; ++i) {
            int lin = i * 256 + tid;
            int row = lin >> 3, seg = lin & 7;
            uint32_t soff = row * 128 + (((seg ^ (row & 7))) << 4);
            const size_t wgo = (size_t)(m0 + row) * HD + gk + seg * 8;
            const size_t xgo = (size_t)(n0 + row) * HD + gk + seg * 8;
            cp_async16(base + soff, Wh + wgo);
            cp_async16(base + TILE_BYTES + soff, Wl + wgo);
            cp_async16(base + 2 * TILE_BYTES + soff, X + xgo);
        }
        CP_COMMIT();
    };

    load_chunk(0, 0);
    load_chunk(1, 1);

    const int NCH = HD / KC;  // 8
    for (int c = 0; c < NCH; ++c) {
        if (c < NCH - 1) { CP_WAIT(1); } else { CP_WAIT(0); }
        __syncthreads();
        if (c + 2 < NCH) load_chunk(c + 2, (c + 2) % 3);

        const uint32_t stg = sb + (c % 3) * STAGE0;
#pragma unroll
        for (int ks = 0; ks < 4; ++ks) {
            uint32_t a[2][2][4];
            uint32_t b[4][4];
#pragma unroll
            for (int mi = 0; mi < 2; ++mi) {
                int arow = wm * 32 + mi * 16 + lr + (lg & 1) * 8;
                int aseg = ks * 2 + (lg >> 1);
                uint32_t off = arow * 128 + ((aseg ^ (arow & 7)) << 4);
                ldmx4(a[0][mi], stg + off);
                ldmx4(a[1][mi], stg + TILE_BYTES + off);
            }
#pragma unroll
            for (int g = 0; g < 4; ++g) {
                int brow = wn * 64 + g * 16 + lr + (lg >> 1) * 8;
                int bseg = ks * 2 + (lg & 1);
                uint32_t off = brow * 128 + ((bseg ^ (brow & 7)) << 4);
                ldmx4(b[g], stg + 2 * TILE_BYTES + off);
            }
#pragma unroll
            for (int mi = 0; mi < 2; ++mi)
#pragma unroll
                for (int j = 0; j < 8; ++j) {
                    const int g = j >> 1, p = (j & 1) * 2;
                    uint32_t bh[2] = {b[g][p], b[g][p + 1]};
                    mma16816(acc[mi][j], a[0][mi], bh);   // wh*x
                    mma16816(acc[mi][j], a[1][mi], bh);   // wl*x
                }
        }
    }

#pragma unroll
    for (int mi = 0; mi < 2; ++mi) {
        const int mrow0 = m0 + wm * 32 + mi * 16 + (lane >> 2);
#pragma unroll
        for (int j = 0; j < 8; ++j) {
            const int n = n0 + wn * 64 + j * 8 + (lane & 3) * 2;
            const int bb = n >> 11;
            const int t = n & (LL - 1);
            float2 v0, v1;
            v0.x = fmaxf(acc[mi][j][0], 0.f);
            v0.y = fmaxf(acc[mi][j][1], 0.f);
            v1.x = fmaxf(acc[mi][j][2], 0.f);
            v1.y = fmaxf(acc[mi][j][3], 0.f);
            *reinterpret_cast<float2*>(out + ((size_t)bb * M + mrow0) * LL + t) = v0;
            *reinterpret_cast<float2*>(out + ((size_t)bb * M + mrow0 + 8) * LL + t) = v1;
        }
    }
}

// ==== EPI2 GEMM: GLU+residual, 512 thr, A 256x64 (z1/z2) 2 planes, B 1 plane
#define TILE_A2 32768               // 256 * 64 * 2B
#define STAGE2 (2 * TILE_A2 + TILE_BYTES)    // 81920
#define SMEM2 (2 * STAGE2)                   // 163840

__global__ __launch_bounds__(512, 1)
void gemm_glu(const __half* __restrict__ Wh, const __half* __restrict__ Wl,
              const __half* __restrict__ X,
              float* __restrict__ out, const float* __restrict__ bias,
              const float* __restrict__ Hprev)
{
    extern __shared__ char smem[];
    const uint32_t sb = smem_u32(smem);
    const int tid = threadIdx.x;
    const int wid = tid >> 5, lane = tid & 31;
    const int wm = wid >> 1, wn = wid & 1;    // 8(M) x 2(N)
    const int n0 = blockIdx.x * 128;
    const int m0 = blockIdx.y * 128;          // 128 out rows per CTA
    const int lr = lane & 7, lg = lane >> 3;

    float acc[2][8][4];
#pragma unroll
    for (int i = 0; i < 2; ++i)
#pragma unroll
        for (int j = 0; j < 8; ++j)
#pragma unroll
            for (int q = 0; q < 4; ++q) acc[i][j][q] = 0.f;

    auto load_chunk = [&](int kc, int st) {
        const uint32_t base = sb + st * STAGE2;
        const size_t gk = (size_t)kc * KC;
#pragma unroll
        for (int i = 0; i < 4; ++i) {
            int lin = i * 512 + tid;
            int row = lin >> 3, seg = lin & 7;   // row 0..255
            uint32_t soff = row * 128 + (((seg ^ (row & 7))) << 4);
            int wrow = ((row >> 4) & 1) * HD + m0 + ((row >> 5) << 4) + (row & 15);
            const size_t wgo = (size_t)wrow * HD + gk + seg * 8;
            cp_async16(base + soff, Wh + wgo);
            cp_async16(base + TILE_A2 + soff, Wl + wgo);
        }
#pragma unroll
        for (int i = 0; i < 2; ++i) {
            int lin = i * 512 + tid;
            int row = lin >> 3, seg = lin & 7;   // row 0..127
            uint32_t soff = row * 128 + (((seg ^ (row & 7))) << 4);
            const size_t xgo = (size_t)(n0 + row) * HD + gk + seg * 8;
            cp_async16(base + 2 * TILE_A2 + soff, X + xgo);
        }
        CP_COMMIT();
    };

    load_chunk(0, 0);

    const int NCH = HD / KC;  // 8
    for (int c = 0; c < NCH; ++c) {
        if (c + 1 < NCH) {
            load_chunk(c + 1, (c + 1) & 1);
            CP_WAIT(1);
        } else {
            CP_WAIT(0);
        }
        __syncthreads();

        const uint32_t stg = sb + (c & 1) * STAGE2;
#pragma unroll
        for (int ks = 0; ks < 4; ++ks) {
            uint32_t a[2][2][4];   // [plane][mi]
            uint32_t b[4][4];
#pragma unroll
            for (int mi = 0; mi < 2; ++mi) {
                int arow = wm * 32 + mi * 16 + lr + (lg & 1) * 8;
                int aseg = ks * 2 + (lg >> 1);
                uint32_t off = arow * 128 + ((aseg ^ (arow & 7)) << 4);
                ldmx4(a[0][mi], stg + off);
                ldmx4(a[1][mi], stg + TILE_A2 + off);
            }
#pragma unroll
            for (int g = 0; g < 4; ++g) {
                int brow = wn * 64 + g * 16 + lr + (lg >> 1) * 8;
                int bseg = ks * 2 + (lg & 1);
                uint32_t off = brow * 128 + ((bseg ^ (brow & 7)) << 4);
                ldmx4(b[g], stg + 2 * TILE_A2 + off);
            }
#pragma unroll
            for (int mi = 0; mi < 2; ++mi)
#pragma unroll
                for (int j = 0; j < 8; ++j) {
                    const int g = j >> 1, p = (j & 1) * 2;
                    uint32_t bh[2] = {b[g][p], b[g][p + 1]};
                    mma16816(acc[mi][j], a[0][mi], bh);   // wh*x
                    mma16816(acc[mi][j], a[1][mi], bh);   // wl*x
                }
        }
        __syncthreads();
    }

    // epilogue: acc[0]=z1 rows m, acc[1]=z2 rows m
    {
        const int m = m0 + wm * 16 + (lane >> 2);
        const int m8 = m + 8;
        const float b10 = bias[m],      b18 = bias[m8];
        const float b20 = bias[HD + m], b28 = bias[HD + m8];
#pragma unroll
        for (int j = 0; j < 8; ++j) {
            const int n = n0 + wn * 64 + j * 8 + (lane & 3) * 2;
            const int bb = n >> 11;
            const int t = n & (LL - 1);
            float z10 = acc[0][j][0] + b10, z11 = acc[0][j][1] + b10;
            float z12 = acc[0][j][2] + b18, z13 = acc[0][j][3] + b18;
            float z20 = acc[1][j][0] + b20, z21 = acc[1][j][1] + b20;
            float z22 = acc[1][j][2] + b28, z23 = acc[1][j][3] + b28;
            const float2 p0 = *reinterpret_cast<const float2*>(
                Hprev + ((size_t)bb * HD + m) * LL + t);
            const float2 p1 = *reinterpret_cast<const float2*>(
                Hprev + ((size_t)bb * HD + m8) * LL + t);
            float2 v0, v1;
            v0.x = z10 / (1.f + expf(-z20)) + p0.x;
            v0.y = z11 / (1.f + expf(-z21)) + p0.y;
            v1.x = z12 / (1.f + expf(-z22)) + p1.x;
            v1.y = z13 / (1.f + expf(-z23)) + p1.y;
            *reinterpret_cast<float2*>(out + ((size_t)bb * HD + m) * LL + t) = v0;
            *reinterpret_cast<float2*>(out + ((size_t)bb * HD + m8) * LL + t) = v1;
        }
    }
}

// ---------------- single-pass LayerNorm ----------------
// WRT==0: Hn = LN(V) fp32; WRT==1: LN(V) -> transposed fp16 (decoder operand)
template <int WRT>
__global__ __launch_bounds__(256)
void ln_kernel(const float* __restrict__ V, float* __restrict__ Hn,
               __half* __restrict__ dst,
               const float* __restrict__ gamma, const float* __restrict__ beta)
{
    __shared__ float ssum[8][32];
    __shared__ float ssq[8][32];
    __shared__ __half hs[32][72];
    const int b = blockIdx.y;
    const int tx = threadIdx.x & 31;
    const int ty = threadIdx.x >> 5;
    const size_t t = (size_t)blockIdx.x * 32 + tx;
    const float* Vb = V + (size_t)b * HD * LL + t;
    float* Hb = Hn + (size_t)b * HD * LL + t;

    float vals[64];
    float s = 0.f, s2 = 0.f;
#pragma unroll
    for (int k = 0; k < 64; ++k) {
        const int c = k * 8 + ty;
        float v = Vb[(size_t)c * LL];
        vals[k] = v;
        s += v;
        s2 = fmaf(v, v, s2);
    }
    ssum[ty][tx] = s;
    ssq[ty][tx] = s2;
    __syncthreads();
    float st = 0.f, st2 = 0.f;
#pragma unroll
    for (int i = 0; i < 8; ++i) {
        st += ssum[i][tx];
        st2 += ssq[i][tx];
    }
    const float mu = st * (1.f / HD);
    const float var = st2 * (1.f / HD) - mu * mu;
    const float rstd = rsqrtf(var + 1e-5f);

    if (WRT == 0) {
#pragma unroll
        for (int k = 0; k < 64; ++k) {
            const int c = k * 8 + ty;
            Hb[(size_t)c * LL] = (vals[k] - mu) * rstd * gamma[c] + beta[c];
        }
    } else {
        const int tt = (int)(threadIdx.x >> 3), seg = (int)(threadIdx.x & 7);
        const size_t trow = ((size_t)b * LL + (size_t)blockIdx.x * 32 + tt) * HD;
#pragma unroll
        for (int kc = 0; kc < 8; ++kc) {
#pragma unroll
            for (int i = 0; i < 8; ++i) {
                const int k = kc * 8 + i;
                const int c = k * 8 + ty;
                float v = (vals[k] - mu) * rstd * gamma[c] + beta[c];
                hs[tx][i * 8 + ty] = __float2half(v);
            }
            __syncthreads();
            *reinterpret_cast<uint4*>(dst + trow + kc * 64 + seg * 8) =
                *reinterpret_cast<const uint4*>(&hs[tt][seg * 8]);
            __syncthreads();
        }
    }
}

// ---------------- SSM scan: 4 lanes/channel, 8 states/lane -> fp16 T --------
__global__ __launch_bounds__(256)
void ssm_scan_fused(const float* __restrict__ hbuf,
                    __half* __restrict__ dst,
                    const float* __restrict__ wre, const float* __restrict__ wim,
                    const float* __restrict__ ccre, const float* __restrict__ ccim,
                    const float* __restrict__ Dv)
{
    __shared__ float tile[32][72];
    const int tid = threadIdx.x;
    const int q = tid & 3;
    const int g = tid >> 2;
    const int grp0 = blockIdx.x * 64;
    const int grp = grp0 + g;
    const int b = grp >> 9;
    const int hh = grp & (HD - 1);
    const int h0 = grp0 & (HD - 1);
    const float* hrow = hbuf + (size_t)grp * LL;

    const int pbase = hh * NN + q * 8;
    float wr[8], wi[8], cr[8], ci[8];
    {
        float4 a0 = *reinterpret_cast<const float4*>(&wre[pbase]);
        float4 a1 = *reinterpret_cast<const float4*>(&wre[pbase + 4]);
        wr[0]=a0.x; wr[1]=a0.y; wr[2]=a0.z; wr[3]=a0.w;
        wr[4]=a1.x; wr[5]=a1.y; wr[6]=a1.z; wr[7]=a1.w;
        float4 b0 = *reinterpret_cast<const float4*>(&wim[pbase]);
        float4 b1 = *reinterpret_cast<const float4*>(&wim[pbase + 4]);
        wi[0]=b0.x; wi[1]=b0.y; wi[2]=b0.z; wi[3]=b0.w;
        wi[4]=b1.x; wi[5]=b1.y; wi[6]=b1.z; wi[7]=b1.w;
        float4 c0 = *reinterpret_cast<const float4*>(&ccre[pbase]);
        float4 c1 = *reinterpret_cast<const float4*>(&ccre[pbase + 4]);
        cr[0]=c0.x; cr[1]=c0.y; cr[2]=c0.z; cr[3]=c0.w;
        cr[4]=c1.x; cr[5]=c1.y; cr[6]=c1.z; cr[7]=c1.w;
        float4 d0 = *reinterpret_cast<const float4*>(&ccim[pbase]);
        float4 d1 = *reinterpret_cast<const float4*>(&ccim[pbase + 4]);
        ci[0]=d0.x; ci[1]=d0.y; ci[2]=d0.z; ci[3]=d0.w;
        ci[4]=d1.x; ci[5]=d1.y; ci[6]=d1.z; ci[7]=d1.w;
    }
    const float Dh = Dv[hh];

    float sr[8], si[8];
#pragma unroll
    for (int k = 0; k < 8; ++k) { sr[k] = 0.f; si[k] = 0.f; }

    const int tt = tid >> 3, seg = tid & 7;

    for (int t0 = 0; t0 < LL; t0 += 32) {
#pragma unroll
        for (int sub = 0; sub < 8; ++sub) {
            const int tb = t0 + sub * 4;
            const float4 ua = *reinterpret_cast<const float4*>(hrow + tb);
            const float uu[4] = {ua.x, ua.y, ua.z, ua.w};
            float umine = 0.f, ykeep = 0.f;
#pragma unroll
            for (int j = 0; j < 4; ++j) {
                const float u = uu[j];
#pragma unroll
                for (int k = 0; k < 8; ++k) {
                    float nr = fmaf(wr[k], sr[k], u);
                    nr = fmaf(-wi[k], si[k], nr);
                    float ni = wr[k] * si[k];
                    ni = fmaf(wi[k], sr[k], ni);
                    sr[k] = nr;
                    si[k] = ni;
                }
                float acc = 0.f;
#pragma unroll
                for (int k = 0; k < 8; ++k) {
                    acc = fmaf(cr[k], sr[k], acc);
                    acc = fmaf(-ci[k], si[k], acc);
                }
                acc += __shfl_xor_sync(0xffffffffu, acc, 1);
                acc += __shfl_xor_sync(0xffffffffu, acc, 2);
                if (j == q) { umine = u; ykeep = acc; }
            }
            float yv = fmaf(Dh, umine, 2.f * ykeep);
            float gv = 0.5f * yv * (1.f + erff(yv * 0.70710678118654752f));
            tile[sub * 4 + q][g] = gv;
        }
        __syncthreads();
        {
            const int t = t0 + tt;
            __half h8[8];
#pragma unroll
            for (int i = 0; i < 8; ++i)
                h8[i] = __float2half(tile[tt][seg * 8 + i]);
            const size_t o = ((size_t)b * LL + t) * HD + h0 + seg * 8;
            *reinterpret_cast<uint4*>(dst + o) = *reinterpret_cast<uint4*>(h8);
        }
        __syncthreads();
    }
}

// ---------------- launch ----------------
extern "C" void kernel_launch(void* const* d_in, const int* in_sizes, int n_in,
                              void* d_out, int out_size)
{
    const float* x = (const float*)d_in[0];
    const float* W_enc = (const float*)d_in[1];
    const float* W_dec = (const float*)d_in[2];
    const float* log_dt = (const float*)d_in[3];
    const float* log_A_real = (const float*)d_in[4];
    const float* A_imag = (const float*)d_in[5];
    const float* C_re = (const float*)d_in[6];
    const float* C_im = (const float*)d_in[7];
    const float* Dv = (const float*)d_in[8];
    const float* W_out = (const float*)d_in[9];
    const float* b_out = (const float*)d_in[10];
    const float* ln_g = (const float*)d_in[11];
    const float* ln_b = (const float*)d_in[12];
    float* out = (float*)d_out;

    float *pH, *pV, *pwre, *pwim, *pcre, *pcim;
    __half *pX, *pWh, *pWl;
    cudaGetSymbolAddress((void**)&pH, g_H);
    cudaGetSymbolAddress((void**)&pV, g_V);
    cudaGetSymbolAddress((void**)&pwre, g_wre);
    cudaGetSymbolAddress((void**)&pwim, g_wim);
    cudaGetSymbolAddress((void**)&pcre, g_cre);
    cudaGetSymbolAddress((void**)&pcim, g_cim);
    cudaGetSymbolAddress((void**)&pX, g_X);
    cudaGetSymbolAddress((void**)&pWh, g_Wh);
    cudaGetSymbolAddress((void**)&pWl, g_Wl);

    cudaFuncSetAttribute(gemm_relu, cudaFuncAttributeMaxDynamicSharedMemorySize, SMEM0);
    cudaFuncSetAttribute(gemm_glu, cudaFuncAttributeMaxDynamicSharedMemorySize, SMEM2);

    precompute_kernel<<<(NL * HD * NN + 255) / 256, 256>>>(log_dt, log_A_real,
                                                           A_imag, C_re, C_im);
    split_w_all<<<(W_ELEMS + 255) / 256, 256>>>(W_enc, W_out, W_dec, pWh, pWl);

    const dim3 tgrid(LL / 32, HD / 32, BQ);

    // encoder: H = relu(W_enc @ quant(x))  (quantized x is exact in fp16)
    transpose_half_kernel<true><<<tgrid, 256>>>(x, pX);
    gemm_relu<<<dim3(NTOT / 128, HD / 128), 256, SMEM0>>>(
        pWh + W_ENC_OFF, pWl + W_ENC_OFF, pX, pH, HD);

    for (int l = 0; l < NL; ++l) {
        const int po = l * HD * NN;
        // scan(H) + gelu -> transposed fp16
        ssm_scan_fused<<<(BQ * HD) / 64, 256>>>(
            pH, pX, pwre + po, pwim + po, pcre + po, pcim + po, Dv + l * HD);
        // fused GLU + residual: V = glu(z) + H  (128 out rows per CTA)
        gemm_glu<<<dim3(NTOT / 128, HD / 128), 512, SMEM2>>>(
            pWh + W_OUT_OFF + (size_t)l * 2 * HD * HD,
            pWl + W_OUT_OFF + (size_t)l * 2 * HD * HD,
            pX, pV, b_out + l * 2 * HD, pH);
        // H = LN(V); last layer writes decoder operand directly
        if (l < NL - 1)
            ln_kernel<0><<<dim3(LL / 32, BQ), 256>>>(pV, pH, nullptr,
                                                     ln_g + l * HD, ln_b + l * HD);
        else
            ln_kernel<1><<<dim3(LL / 32, BQ), 256>>>(pV, nullptr, pX,
                                                     ln_g + l * HD, ln_b + l * HD);
    }

    // decoder: out = relu(W_dec @ LN(V3))
    gemm_relu<<<dim3(NTOT / 128, HD / 128), 256, SMEM0>>>(
        pWh + W_DEC_OFF, pWl + W_DEC_OFF, pX, out, HD);
}